// round 2
// baseline (speedup 1.0000x reference)
#include <cuda_runtime.h>
#include <string.h>

#define B_ 16
#define N_ 2048
#define F_ 2048
#define E_ 128
#define K_ 10
#define R_ 2

// ---------------- device scratch (no allocations allowed) ----------------
__device__ float g_h[R_][2][B_][E_];       // hop vectors h1,h2 per rule
__device__ float g_esq[B_][N_];            // entity squared norms
__device__ float g_cbias[R_][B_][F_];      // log kr_f - 0.5*||fy_f||^2  (-inf masked)
__device__ float g_s0[B_];                 // scores_0 (linear)
__device__ float g_L[R_][B_][N_];          // log sp scores
__device__ int   g_zidx[R_][B_][K_];
__device__ float g_zlog[R_][B_][K_];
__device__ float g_s2log[R_][B_][K_];

__device__ __forceinline__ float warp_sum(float v) {
#pragma unroll
    for (int o = 16; o > 0; o >>= 1) v += __shfl_xor_sync(0xffffffffu, v, o);
    return v;
}
__device__ __forceinline__ float dot4(float4 a, float4 b) {
    return a.x * b.x + a.y * b.y + a.z * b.z + a.w * b.w;
}
__device__ __forceinline__ float2 unpack2(unsigned long long u) {
    float2 v;
    asm("mov.b64 {%0, %1}, %2;" : "=f"(v.x), "=f"(v.y) : "l"(u));
    return v;
}

// ---------------- hop vectors: h[r][h][b] = rel[b] @ W[r,h] + b[r,h] -----
__global__ void k_hop(const float* __restrict__ rel, const float* __restrict__ W,
                      const float* __restrict__ hb) {
    int b = blockIdx.x, h = blockIdx.y, r = blockIdx.z, e = threadIdx.x;
    const float* w = W + (size_t)((r * 2 + h) * E_) * E_ + e;
    const float* rb = rel + b * E_;
    float s = hb[(r * 2 + h) * E_ + e];
#pragma unroll 8
    for (int i = 0; i < E_; i++) s += rb[i] * w[(size_t)i * E_];
    g_h[r][h][b][e] = s;
}

// ---------------- entity squared norms (warp per row) --------------------
__global__ void k_esq(const float* __restrict__ ent) {
    int gw = (blockIdx.x * blockDim.x + threadIdx.x) >> 5;
    int lane = threadIdx.x & 31;
    if (gw >= B_ * N_) return;
    float4 v = ((const float4*)(ent + (size_t)gw * E_))[lane];
    float s = warp_sum(dot4(v, v));
    if (lane == 0) ((float*)g_esq)[gw] = s;
}

// ---------------- per-fact log(kr) biases for both rules -----------------
__global__ void k_cbias(const float* __restrict__ arg1, const float* __restrict__ fr,
                        const float* __restrict__ fa1, const float* __restrict__ fa2,
                        const int* __restrict__ nbf) {
    int gw = (blockIdx.x * 256 + threadIdx.x) >> 5;
    int lane = threadIdx.x & 31;
    if (gw >= B_ * F_) return;
    int b = gw >> 11, f = gw & (F_ - 1);
    size_t off = ((size_t)b * F_ + f) * E_ + lane * 4;
    float4 vr = *(const float4*)(fr + off);
    float4 v1 = *(const float4*)(fa1 + off);
    float4 v2 = *(const float4*)(fa2 + off);
    float4 h0 = *(const float4*)(&g_h[0][0][b][lane * 4]);
    float4 h1 = *(const float4*)(&g_h[1][0][b][lane * 4]);
    float4 a1 = *(const float4*)(arg1 + b * E_ + lane * 4);
    float common = dot4(vr, vr) + dot4(v1, v1) + dot4(v2, v2) + dot4(a1, a1);
    // rule0: -0.5*(d2(h0,fr)+d2(arg1,fa1)) - 0.5*||fa2||^2
    float p0 = common + dot4(h0, h0) - 2.f * (dot4(h0, vr) + dot4(a1, v1));
    // rule1: -0.5*(d2(h1,fr)+d2(arg1,fa2)) - 0.5*||fa1||^2
    float p1 = common + dot4(h1, h1) - 2.f * (dot4(h1, vr) + dot4(a1, v2));
    p0 = warp_sum(p0);
    p1 = warp_sum(p1);
    if (lane == 0) {
        bool valid = f < nbf[b];
        g_cbias[0][b][f] = valid ? -0.5f * p0 : -3e30f;
        g_cbias[1][b][f] = valid ? -0.5f * p1 : -3e30f;
    }
}

// ---------------- scores_0: max over valid facts of triple kernel --------
__global__ void k_s0(const float* __restrict__ rel, const float* __restrict__ arg1,
                     const float* __restrict__ arg2, const float* __restrict__ fr,
                     const float* __restrict__ fa1, const float* __restrict__ fa2,
                     const int* __restrict__ nbf) {
    int b = blockIdx.x;
    int w = threadIdx.x >> 5, lane = threadIdx.x & 31;
    float4 qr = *(const float4*)(rel + b * E_ + lane * 4);
    float4 q1 = *(const float4*)(arg1 + b * E_ + lane * 4);
    float4 q2 = *(const float4*)(arg2 + b * E_ + lane * 4);
    float sqq = warp_sum(dot4(qr, qr) + dot4(q1, q1) + dot4(q2, q2));
    int nf = nbf[b];
    float m = -3e30f;
    for (int f = w; f < nf; f += 8) {
        size_t off = ((size_t)b * F_ + f) * E_ + lane * 4;
        float4 vr = *(const float4*)(fr + off);
        float4 v1 = *(const float4*)(fa1 + off);
        float4 v2 = *(const float4*)(fa2 + off);
        float p = dot4(vr, vr) - 2.f * dot4(qr, vr) + dot4(v1, v1) - 2.f * dot4(q1, v1) +
                  dot4(v2, v2) - 2.f * dot4(q2, v2);
        p = warp_sum(p);
        m = fmaxf(m, -0.5f * (sqq + p));
    }
    __shared__ float sm[8];
    if (lane == 0) sm[w] = m;
    __syncthreads();
    if (threadIdx.x == 0) {
        float mm = -3e30f;
        for (int i = 0; i < 8; i++) mm = fmaxf(mm, sm[i]);
        g_s0[b] = expf(mm);
    }
}

// ---------------- heavy: L[b,n] = max_f (ent_n . fy_f + cbias_f) ---------
// block tile 128n x 128f, thread tile 8x8 via packed f32x2 FMA (FFMA2).
// As: entity tile [e][n] stride 132 (resident), Bs: fact k-chunks [16][128] x2.
#define AS_STRIDE 132
#define SMEM_FLOATS (128 * AS_STRIDE + 2 * 16 * 128 + 128 * 17)

__global__ __launch_bounds__(256, 2) void k_maxgemm(const float* __restrict__ ent,
                                                    const float* __restrict__ fa1,
                                                    const float* __restrict__ fa2,
                                                    const int* __restrict__ nbe) {
    extern __shared__ float smem[];
    float* As = smem;                       // [128][132]
    float* Bs = smem + 128 * AS_STRIDE;     // [2][16][128]
    float* Red = Bs + 2 * 16 * 128;         // [128][17]

    int nt = blockIdx.x, b = blockIdx.y, r = blockIdx.z;
    const float* fy = (r == 0 ? fa2 : fa1) + (size_t)b * F_ * E_;
    const float* eb = ent + ((size_t)b * N_ + nt * 128) * E_;
    const float* cb = &g_cbias[r][b][0];
    int tid = threadIdx.x, tx = tid & 15, ty = tid >> 4;

    // fill entity tile As[e][n] (one-time; transposed store)
    for (int it = 0; it < 64; ++it) {
        int u = tid + it * 256;
        int n = u >> 7, e = u & 127;
        As[e * AS_STRIDE + n] = eb[(size_t)n * E_ + e];
    }

    auto fillB = [&](int bufsel, int ft, int kc) {
        float* dst = Bs + bufsel * (16 * 128);
#pragma unroll
        for (int it = 0; it < 2; ++it) {
            int u = tid + it * 256;
            int f = u >> 2, e4 = u & 3;
            float4 v = *(const float4*)(fy + (size_t)(ft * 128 + f) * E_ + kc * 16 + e4 * 4);
            dst[(e4 * 4 + 0) * 128 + f] = v.x;
            dst[(e4 * 4 + 1) * 128 + f] = v.y;
            dst[(e4 * 4 + 2) * 128 + f] = v.z;
            dst[(e4 * 4 + 3) * 128 + f] = v.w;
        }
    };
    fillB(0, 0, 0);

    unsigned long long acc[4][8];
    float rmax[8];
#pragma unroll
    for (int i = 0; i < 8; i++) rmax[i] = -3e30f;

    int cur = 0;
    for (int ft = 0; ft < 16; ++ft) {
#pragma unroll
        for (int p = 0; p < 4; p++)
#pragma unroll
            for (int j = 0; j < 8; j++) acc[p][j] = 0ull;

        for (int kc = 0; kc < 8; ++kc) {
            __syncthreads();  // prev buffer fill visible; prev compute done
            int nxt = ft * 8 + kc + 1;
            if (nxt < 128) fillB(cur ^ 1, nxt >> 3, nxt & 7);

            const float* Abase = As + kc * 16 * AS_STRIDE + ty * 8;
            const float* Bbase = Bs + cur * (16 * 128) + tx;
#pragma unroll
            for (int k = 0; k < 16; k++) {
                ulonglong2 av0 = *(const ulonglong2*)(Abase + k * AS_STRIDE);
                ulonglong2 av1 = *(const ulonglong2*)(Abase + k * AS_STRIDE + 4);
                unsigned long long a2[4] = {av0.x, av0.y, av1.x, av1.y};
                unsigned long long b2[8];
#pragma unroll
                for (int j = 0; j < 8; j++) {
                    float bv = Bbase[k * 128 + 16 * j];
                    asm("mov.b64 %0, {%1, %1};" : "=l"(b2[j]) : "f"(bv));
                }
#pragma unroll
                for (int p = 0; p < 4; p++)
#pragma unroll
                    for (int j = 0; j < 8; j++)
                        asm("fma.rn.f32x2 %0, %1, %2, %0;"
                            : "+l"(acc[p][j])
                            : "l"(a2[p]), "l"(b2[j]));
            }
            cur ^= 1;
        }
        // epilogue for this fact tile: add cbias, fold into running row-max
#pragma unroll
        for (int j = 0; j < 8; j++) {
            float cj = __ldg(cb + ft * 128 + tx + 16 * j);
#pragma unroll
            for (int p = 0; p < 4; p++) {
                float2 v = unpack2(acc[p][j]);
                rmax[2 * p] = fmaxf(rmax[2 * p], v.x + cj);
                rmax[2 * p + 1] = fmaxf(rmax[2 * p + 1], v.y + cj);
            }
        }
    }
    // cross-tx reduction of row maxima
    __syncthreads();
#pragma unroll
    for (int i = 0; i < 8; i++) Red[(ty * 8 + i) * 17 + tx] = rmax[i];
    __syncthreads();
    if (tid < 128) {
        float m = -3e30f;
#pragma unroll
        for (int t = 0; t < 16; t++) m = fmaxf(m, Red[tid * 17 + t]);
        int gn = nt * 128 + tid;
        float Lv = m - 0.5f * g_esq[b][gn];
        if (gn >= nbe[b]) Lv = -3e30f;
        g_L[r][b][gn] = Lv;
    }
}

// ---------------- top-K over N per (r,b) ----------------------------------
__global__ void k_topk() {
    int b = blockIdx.x, r = blockIdx.y, tid = threadIdx.x;
    __shared__ float Ls[N_];
    __shared__ float sv[256];
    __shared__ int si[256];
    for (int i = tid; i < N_; i += 256) Ls[i] = g_L[r][b][i];
    __syncthreads();
    for (int kk = 0; kk < K_; kk++) {
        float bv = -3.5e30f;
        int bi = 0;
        for (int i = tid; i < N_; i += 256) {
            float v = Ls[i];
            if (v > bv) { bv = v; bi = i; }
        }
        sv[tid] = bv;
        si[tid] = bi;
        __syncthreads();
        for (int s = 128; s > 0; s >>= 1) {
            if (tid < s) {
                float v = sv[tid + s];
                int j = si[tid + s];
                if (v > sv[tid] || (v == sv[tid] && j < si[tid])) { sv[tid] = v; si[tid] = j; }
            }
            __syncthreads();
        }
        if (tid == 0) {
            g_zidx[r][b][kk] = si[0];
            g_zlog[r][b][kk] = sv[0];
            Ls[si[0]] = -3.5e30f;
        }
        __syncthreads();
    }
}

// ---------------- final-hop rescoring of K beam candidates ----------------
__global__ void k_s2(const float* __restrict__ ent, const float* __restrict__ arg2,
                     const float* __restrict__ fr, const float* __restrict__ fa1,
                     const float* __restrict__ fa2, const int* __restrict__ nbf) {
    int k = blockIdx.x, b = blockIdx.y, r = blockIdx.z;
    int lane = threadIdx.x & 31, w = threadIdx.x >> 5;
    int zi = g_zidx[r][b][k];
    const float* zv = ent + ((size_t)b * N_ + zi) * E_;
    const float* av = arg2 + b * E_;
    const float* x1 = (r == 0) ? zv : av;  // matched against fact_arg1
    const float* x2 = (r == 0) ? av : zv;  // matched against fact_arg2
    float4 qh = *(const float4*)(&g_h[r][1][b][lane * 4]);
    float4 q1 = *(const float4*)(x1 + lane * 4);
    float4 q2 = *(const float4*)(x2 + lane * 4);
    float sqq = warp_sum(dot4(qh, qh) + dot4(q1, q1) + dot4(q2, q2));
    int nf = nbf[b];
    float m = -3e30f;
    for (int f = w; f < nf; f += 8) {
        size_t off = ((size_t)b * F_ + f) * E_ + lane * 4;
        float4 vr = *(const float4*)(fr + off);
        float4 v1 = *(const float4*)(fa1 + off);
        float4 v2 = *(const float4*)(fa2 + off);
        float p = dot4(vr, vr) - 2.f * dot4(qh, vr) + dot4(v1, v1) - 2.f * dot4(q1, v1) +
                  dot4(v2, v2) - 2.f * dot4(q2, v2);
        p = warp_sum(p);
        m = fmaxf(m, -0.5f * (sqq + p));
    }
    __shared__ float sm[8];
    if (lane == 0) sm[w] = m;
    __syncthreads();
    if (threadIdx.x == 0) {
        float mm = -3e30f;
        for (int i = 0; i < 8; i++) mm = fmaxf(mm, sm[i]);
        g_s2log[r][b][k] = mm;
    }
}

// ---------------- final combine -------------------------------------------
__global__ void k_final(float* __restrict__ out) {
    int b = threadIdx.x;
    if (b >= B_) return;
    float res = g_s0[b];
#pragma unroll
    for (int r = 0; r < R_; r++)
#pragma unroll
        for (int k = 0; k < K_; k++)
            res = fmaxf(res, expf(fminf(g_s2log[r][b][k], g_zlog[r][b][k])));
    out[b] = res;
}

// ---------------- launch ---------------------------------------------------
extern "C" void kernel_launch(void* const* d_in, const int* in_sizes, int n_in,
                              void* d_out, int out_size) {
    (void)in_sizes; (void)n_in; (void)out_size;
    const float* rel = (const float*)d_in[0];
    const float* arg1 = (const float*)d_in[1];
    const float* arg2 = (const float*)d_in[2];
    const float* fr = (const float*)d_in[3];
    const float* fa1 = (const float*)d_in[4];
    const float* fa2 = (const float*)d_in[5];
    const float* ent = (const float*)d_in[6];
    const float* W = (const float*)d_in[7];
    const float* hb = (const float*)d_in[8];
    const int* nbf = (const int*)d_in[9];
    const int* nbe = (const int*)d_in[10];
    float* out = (float*)d_out;

    cudaFuncSetAttribute(k_maxgemm, cudaFuncAttributeMaxDynamicSharedMemorySize,
                         SMEM_FLOATS * 4);

    k_hop<<<dim3(B_, 2, R_), E_>>>(rel, W, hb);
    k_esq<<<(B_ * N_) / 8, 256>>>(ent);
    k_cbias<<<(B_ * F_) / 8, 256>>>(arg1, fr, fa1, fa2, nbf);
    k_s0<<<B_, 256>>>(rel, arg1, arg2, fr, fa1, fa2, nbf);
    k_maxgemm<<<dim3(N_ / 128, B_, R_), 256, SMEM_FLOATS * 4>>>(ent, fa1, fa2, nbe);
    k_topk<<<dim3(B_, R_), 256>>>();
    k_s2<<<dim3(K_, B_, R_), 256>>>(ent, arg2, fr, fa1, fa2, nbf);
    k_final<<<1, 32>>>(out);
}

// round 4
// speedup vs baseline: 2.4545x; 2.4545x over previous
#include <cuda_runtime.h>
#include <cuda_bf16.h>
#include <cstdint>

#define B_ 16
#define N_ 2048
#define F_ 2048
#define E_ 128
#define K_ 10
#define R_ 2
#define ZSPLIT 8

// ---------------- device scratch (static, no runtime allocation) ----------
__device__ float g_h[R_][2][B_][E_];        // hop vectors (h1,h2) per rule
__device__ float g_esq[B_][N_];             // entity squared norms
__device__ float g_cbias[R_][B_][F_];       // hop-1 fact bias
__device__ float g_cb2[R_][B_][F_];         // hop-2 fact bias
__device__ unsigned g_s0key[B_];            // scores_0 ordered-int atomic max
__device__ float g_L[R_][B_][N_];           // hop-1 log scores over entities
__device__ int   g_zidx[R_][B_][K_];
__device__ float g_zlog[R_][B_][K_];
__device__ float g_s2part[R_][B_][ZSPLIT][K_];

// bf16 hi/lo split planes
__device__ __nv_bfloat16 g_ehi[B_ * N_ * E_];
__device__ __nv_bfloat16 g_elo[B_ * N_ * E_];
__device__ __nv_bfloat16 g_f1hi[B_ * F_ * E_];
__device__ __nv_bfloat16 g_f1lo[B_ * F_ * E_];
__device__ __nv_bfloat16 g_f2hi[B_ * F_ * E_];
__device__ __nv_bfloat16 g_f2lo[B_ * F_ * E_];

// ---------------- helpers ---------------------------------------------------
__device__ __forceinline__ float warp_sum(float v) {
#pragma unroll
    for (int o = 16; o > 0; o >>= 1) v += __shfl_xor_sync(0xffffffffu, v, o);
    return v;
}
__device__ __forceinline__ float dot4(float4 a, float4 b) {
    return a.x * b.x + a.y * b.y + a.z * b.z + a.w * b.w;
}
__device__ __forceinline__ unsigned fenc(float v) {
    unsigned u = __float_as_uint(v);
    return (u & 0x80000000u) ? ~u : (u | 0x80000000u);
}
__device__ __forceinline__ float fdec(unsigned k) {
    return (k & 0x80000000u) ? __uint_as_float(k ^ 0x80000000u) : __uint_as_float(~k);
}
__device__ __forceinline__ uint32_t smem_u32(const void* p) {
    uint32_t a;
    asm("{ .reg .u64 t; cvta.to.shared.u64 t, %1; cvt.u32.u64 %0, t; }" : "=r"(a) : "l"(p));
    return a;
}

// ---------------- portable tensor-core / async-copy PTX ----------------------
__device__ __forceinline__ void cp16(uint32_t s, const void* g) {
    asm volatile("cp.async.cg.shared.global [%0], [%1], 16;" :: "r"(s), "l"(g));
}
__device__ __forceinline__ void cpcommit() { asm volatile("cp.async.commit_group;"); }
template <int NN>
__device__ __forceinline__ void cpwait() {
    asm volatile("cp.async.wait_group %0;" :: "n"(NN));
}
__device__ __forceinline__ void ldsm4(uint32_t& r0, uint32_t& r1, uint32_t& r2, uint32_t& r3,
                                      uint32_t a) {
    asm volatile("ldmatrix.sync.aligned.m8n8.x4.shared.b16 {%0,%1,%2,%3}, [%4];"
                 : "=r"(r0), "=r"(r1), "=r"(r2), "=r"(r3) : "r"(a));
}
__device__ __forceinline__ void mma16816(float* c, const uint32_t* a, const uint32_t* b) {
    asm volatile(
        "mma.sync.aligned.m16n8k16.row.col.f32.bf16.bf16.f32 "
        "{%0,%1,%2,%3},{%4,%5,%6,%7},{%8,%9},{%0,%1,%2,%3};"
        : "+f"(c[0]), "+f"(c[1]), "+f"(c[2]), "+f"(c[3])
        : "r"(a[0]), "r"(a[1]), "r"(a[2]), "r"(a[3]), "r"(b[0]), "r"(b[1]));
}
// swizzled tile offset: 128 rows x 128 bf16 (256B rows, 16-byte chunks, XOR swizzle)
__device__ __forceinline__ uint32_t swz(int row, int chunk) {
    return (uint32_t)row * 256u + (uint32_t)((chunk ^ (row & 7)) * 16);
}

// ---------------- bf16 hi/lo split ------------------------------------------
__global__ void k_split(const float* __restrict__ ent, const float* __restrict__ fa1,
                        const float* __restrict__ fa2) {
    int z = blockIdx.y;
    size_t i = ((size_t)blockIdx.x * 256 + threadIdx.x) * 4;
    const float* src = (z == 0) ? ent : (z == 1) ? fa1 : fa2;
    __nv_bfloat16* hi = (z == 0) ? g_ehi : (z == 1) ? g_f1hi : g_f2hi;
    __nv_bfloat16* lo = (z == 0) ? g_elo : (z == 1) ? g_f1lo : g_f2lo;
    float4 v = *(const float4*)(src + i);
    __nv_bfloat16 h0 = __float2bfloat16(v.x), h1 = __float2bfloat16(v.y);
    __nv_bfloat16 h2 = __float2bfloat16(v.z), h3 = __float2bfloat16(v.w);
    __nv_bfloat16 l0 = __float2bfloat16(v.x - __bfloat162float(h0));
    __nv_bfloat16 l1 = __float2bfloat16(v.y - __bfloat162float(h1));
    __nv_bfloat16 l2 = __float2bfloat16(v.z - __bfloat162float(h2));
    __nv_bfloat16 l3 = __float2bfloat16(v.w - __bfloat162float(h3));
    __nv_bfloat162 hh0 = __halves2bfloat162(h0, h1), hh1 = __halves2bfloat162(h2, h3);
    __nv_bfloat162 ll0 = __halves2bfloat162(l0, l1), ll1 = __halves2bfloat162(l2, l3);
    uint2 uh = {*(unsigned*)&hh0, *(unsigned*)&hh1};
    uint2 ul = {*(unsigned*)&ll0, *(unsigned*)&ll1};
    *(uint2*)(hi + i) = uh;
    *(uint2*)(lo + i) = ul;
}

// ---------------- hop vectors + s0key init ----------------------------------
__global__ void k_hop(const float* __restrict__ rel, const float* __restrict__ W,
                      const float* __restrict__ hb) {
    int b = blockIdx.x, h = blockIdx.y, r = blockIdx.z, e = threadIdx.x;
    if (e == 0 && h == 0 && r == 0) g_s0key[b] = fenc(-3e30f);
    const float* w = W + (size_t)((r * 2 + h) * E_) * E_ + e;
    const float* rb = rel + b * E_;
    float s = hb[(r * 2 + h) * E_ + e];
#pragma unroll 8
    for (int i = 0; i < E_; i++) s += rb[i] * w[(size_t)i * E_];
    g_h[r][h][b][e] = s;
}

// ---------------- entity squared norms --------------------------------------
__global__ void k_esq(const float* __restrict__ ent) {
    int gw = (blockIdx.x * blockDim.x + threadIdx.x) >> 5;
    int lane = threadIdx.x & 31;
    if (gw >= B_ * N_) return;
    float4 v = ((const float4*)(ent + (size_t)gw * E_))[lane];
    float s = warp_sum(dot4(v, v));
    if (lane == 0) ((float*)g_esq)[gw] = s;
}

// ---------------- per-fact biases (hop1, hop2) + fused scores_0 --------------
__global__ void k_cbias(const float* __restrict__ rel, const float* __restrict__ arg1,
                        const float* __restrict__ arg2, const float* __restrict__ fr,
                        const float* __restrict__ fa1, const float* __restrict__ fa2,
                        const int* __restrict__ nbf) {
    int gw = (blockIdx.x * 256 + threadIdx.x) >> 5;
    int lane = threadIdx.x & 31;
    if (gw >= B_ * F_) return;
    int b = gw >> 11, f = gw & (F_ - 1);
    size_t off = ((size_t)b * F_ + f) * E_ + lane * 4;
    float4 vr = *(const float4*)(fr + off);
    float4 v1 = *(const float4*)(fa1 + off);
    float4 v2 = *(const float4*)(fa2 + off);
    float4 h00 = *(const float4*)(&g_h[0][0][b][lane * 4]);
    float4 h10 = *(const float4*)(&g_h[1][0][b][lane * 4]);
    float4 h01 = *(const float4*)(&g_h[0][1][b][lane * 4]);
    float4 h11 = *(const float4*)(&g_h[1][1][b][lane * 4]);
    float4 qr = *(const float4*)(rel + b * E_ + lane * 4);
    float4 a1 = *(const float4*)(arg1 + b * E_ + lane * 4);
    float4 a2 = *(const float4*)(arg2 + b * E_ + lane * 4);
    float nsum = dot4(vr, vr) + dot4(v1, v1) + dot4(v2, v2);
    float a1s = dot4(a1, a1), a2s = dot4(a2, a2);
    float p0 = nsum + dot4(h00, h00) + a1s - 2.f * (dot4(h00, vr) + dot4(a1, v1));
    float p1 = nsum + dot4(h10, h10) + a1s - 2.f * (dot4(h10, vr) + dot4(a1, v2));
    float q0 = nsum + dot4(h01, h01) + a2s - 2.f * (dot4(h01, vr) + dot4(a2, v2));
    float q1 = nsum + dot4(h11, h11) + a2s - 2.f * (dot4(h11, vr) + dot4(a2, v1));
    float s = nsum + dot4(qr, qr) + a1s + a2s -
              2.f * (dot4(qr, vr) + dot4(a1, v1) + dot4(a2, v2));
    p0 = warp_sum(p0);
    p1 = warp_sum(p1);
    q0 = warp_sum(q0);
    q1 = warp_sum(q1);
    s = warp_sum(s);
    if (lane == 0) {
        bool valid = f < nbf[b];
        g_cbias[0][b][f] = valid ? -0.5f * p0 : -3e30f;
        g_cbias[1][b][f] = valid ? -0.5f * p1 : -3e30f;
        g_cb2[0][b][f] = valid ? -0.5f * q0 : -3e30f;
        g_cb2[1][b][f] = valid ? -0.5f * q1 : -3e30f;
        if (valid) atomicMax(&g_s0key[b], fenc(-0.5f * s));
    }
}

// ---------------- heavy max-plus GEMM via mma.sync (bf16 hi/lo split) --------
#define OFF_AHI 0
#define OFF_ALO 32768
#define OFF_B0 65536
#define SMEM_MG 196608

__global__ __launch_bounds__(256, 1) void k_maxgemm(const int* __restrict__ nbe) {
    extern __shared__ char smem[];
    uint32_t sb = smem_u32(smem);
    const int tid = threadIdx.x, lane = tid & 31, wid = tid >> 5;
    const int wm = (wid & 1) * 64, wn = (wid >> 1) * 32;
    const int nt = blockIdx.x, b = blockIdx.y, r = blockIdx.z;

    const __nv_bfloat16* ehi = g_ehi + ((size_t)b * N_ + nt * 128) * E_;
    const __nv_bfloat16* elo = g_elo + ((size_t)b * N_ + nt * 128) * E_;
    const __nv_bfloat16* fhi = ((r == 0) ? g_f2hi : g_f1hi) + (size_t)b * F_ * E_;
    const __nv_bfloat16* flo = ((r == 0) ? g_f2lo : g_f1lo) + (size_t)b * F_ * E_;
    const float* cb = &g_cbias[r][b][0];

    // resident entity tile (hi + lo), swizzled
#pragma unroll
    for (int it = 0; it < 8; ++it) {
        int i = tid + it * 256;
        int row = i >> 4, ch = i & 15;
        uint32_t o = swz(row, ch);
        *(uint4*)(smem + OFF_AHI + o) = *(const uint4*)(ehi + (size_t)row * E_ + ch * 8);
        *(uint4*)(smem + OFF_ALO + o) = *(const uint4*)(elo + (size_t)row * E_ + ch * 8);
    }

    auto issueB = [&](int ft, int buf) {
        uint32_t base = sb + OFF_B0 + buf * 65536;
        const __nv_bfloat16* sh = fhi + (size_t)ft * 128 * E_;
        const __nv_bfloat16* sl = flo + (size_t)ft * 128 * E_;
#pragma unroll
        for (int it = 0; it < 8; ++it) {
            int i = tid + it * 256;
            int row = i >> 4, ch = i & 15;
            uint32_t o = swz(row, ch);
            cp16(base + o, sh + (size_t)row * E_ + ch * 8);
            cp16(base + 32768 + o, sl + (size_t)row * E_ + ch * 8);
        }
    };
    issueB(0, 0);
    cpcommit();

    float rmax[8];
#pragma unroll
    for (int i = 0; i < 8; i++) rmax[i] = -3e30f;

    for (int ft = 0; ft < 16; ++ft) {
        __syncthreads();  // all warps done with the buffer we are about to overwrite
        if (ft + 1 < 16) {
            issueB(ft + 1, (ft + 1) & 1);
            cpcommit();
            cpwait<1>();
        } else {
            cpwait<0>();
        }
        __syncthreads();

        float acc[4][4][4];
#pragma unroll
        for (int i = 0; i < 4; i++)
#pragma unroll
            for (int j = 0; j < 4; j++)
#pragma unroll
                for (int q = 0; q < 4; q++) acc[i][j][q] = 0.f;

        uint32_t bbase = sb + OFF_B0 + (ft & 1) * 65536;
#pragma unroll
        for (int ks = 0; ks < 8; ++ks) {
            int kc = ks * 2 + (lane >> 4);
            uint32_t ah[4][4], al[4][4];
#pragma unroll
            for (int i = 0; i < 4; i++) {
                int row = wm + i * 16 + (lane & 15);
                uint32_t o = swz(row, kc);
                ldsm4(ah[i][0], ah[i][1], ah[i][2], ah[i][3], sb + OFF_AHI + o);
                ldsm4(al[i][0], al[i][1], al[i][2], al[i][3], sb + OFF_ALO + o);
            }
            uint32_t bh[4][2], bl[4][2];
#pragma unroll
            for (int p = 0; p < 2; p++) {
                int row = wn + p * 16 + (lane & 15);
                uint32_t o = swz(row, kc);
                uint32_t r0, r1, r2, r3;
                ldsm4(r0, r1, r2, r3, bbase + o);
                bh[2 * p][0] = r0; bh[2 * p][1] = r2;
                bh[2 * p + 1][0] = r1; bh[2 * p + 1][1] = r3;
                ldsm4(r0, r1, r2, r3, bbase + 32768 + o);
                bl[2 * p][0] = r0; bl[2 * p][1] = r2;
                bl[2 * p + 1][0] = r1; bl[2 * p + 1][1] = r3;
            }
#pragma unroll
            for (int i = 0; i < 4; i++)
#pragma unroll
                for (int j = 0; j < 4; j++) {
                    mma16816(acc[i][j], ah[i], bh[j]);
                    mma16816(acc[i][j], ah[i], bl[j]);
                    mma16816(acc[i][j], al[i], bh[j]);
                }
        }
        // epilogue: add cbias, fold running row-max
#pragma unroll
        for (int j = 0; j < 4; j++) {
            int col = ft * 128 + wn + j * 8 + 2 * (lane & 3);
            float c0 = __ldg(cb + col), c1 = __ldg(cb + col + 1);
#pragma unroll
            for (int i = 0; i < 4; i++) {
                rmax[2 * i] = fmaxf(rmax[2 * i], fmaxf(acc[i][j][0] + c0, acc[i][j][1] + c1));
                rmax[2 * i + 1] = fmaxf(rmax[2 * i + 1],
                                        fmaxf(acc[i][j][2] + c0, acc[i][j][3] + c1));
            }
        }
    }

    // cross-thread row-max reduction (reuse smem)
    __syncthreads();
    float* Red = (float*)smem;
#pragma unroll
    for (int i = 0; i < 4; i++)
#pragma unroll
        for (int h = 0; h < 2; h++) {
            int row = wm + i * 16 + h * 8 + (lane >> 2);
            Red[row * 16 + (wid >> 1) * 4 + (lane & 3)] = rmax[2 * i + h];
        }
    __syncthreads();
    if (tid < 128) {
        float m = -3e30f;
#pragma unroll
        for (int t = 0; t < 16; t++) m = fmaxf(m, Red[tid * 16 + t]);
        int gn = nt * 128 + tid;
        float Lv = m - 0.5f * g_esq[b][gn];
        if (gn >= nbe[b]) Lv = -3e30f;
        g_L[r][b][gn] = Lv;
    }
}

// ---------------- top-K over N per (r,b) -------------------------------------
__global__ void k_topk() {
    int b = blockIdx.x, r = blockIdx.y, tid = threadIdx.x;
    __shared__ float Ls[N_];
    __shared__ float sv[256];
    __shared__ int si[256];
    for (int i = tid; i < N_; i += 256) Ls[i] = g_L[r][b][i];
    __syncthreads();
    for (int kk = 0; kk < K_; kk++) {
        float bv = -3.5e30f;
        int bi = 0;
        for (int i = tid; i < N_; i += 256) {
            float v = Ls[i];
            if (v > bv) { bv = v; bi = i; }
        }
        sv[tid] = bv;
        si[tid] = bi;
        __syncthreads();
        for (int s = 128; s > 0; s >>= 1) {
            if (tid < s) {
                float v = sv[tid + s];
                int j = si[tid + s];
                if (v > sv[tid] || (v == sv[tid] && j < si[tid])) { sv[tid] = v; si[tid] = j; }
            }
            __syncthreads();
        }
        if (tid == 0) {
            g_zidx[r][b][kk] = si[0];
            g_zlog[r][b][kk] = sv[0];
            Ls[si[0]] = -3.5e30f;
        }
        __syncthreads();
    }
}

// ---------------- hop-2 rescoring: max-plus over facts (split 8-way) ---------
__global__ void k_s2(const float* __restrict__ ent, const float* __restrict__ fa1,
                     const float* __restrict__ fa2) {
    int b = blockIdx.x, r = blockIdx.y, z = blockIdx.z, tid = threadIdx.x;
    __shared__ float zs[K_][E_];
    __shared__ float red[K_][257];
    for (int i = tid; i < K_ * E_; i += 256) {
        int k = i >> 7, e = i & 127;
        zs[k][e] = ent[((size_t)b * N_ + g_zidx[r][b][k]) * E_ + e];
    }
    __syncthreads();
    const float* fy = ((r == 0) ? fa1 : fa2) + (size_t)b * F_ * E_;
    int f = z * 256 + tid;
    float c = g_cb2[r][b][f];
    const float4* row = (const float4*)(fy + (size_t)f * E_);
    float d[K_];
#pragma unroll
    for (int k = 0; k < K_; k++) d[k] = 0.f;
#pragma unroll 4
    for (int e4 = 0; e4 < 32; e4++) {
        float4 v = row[e4];
#pragma unroll
        for (int k = 0; k < K_; k++) {
            float4 zz = ((const float4*)zs[k])[e4];
            d[k] += v.x * zz.x + v.y * zz.y + v.z * zz.z + v.w * zz.w;
        }
    }
#pragma unroll
    for (int k = 0; k < K_; k++) red[k][tid] = d[k] + c;
    __syncthreads();
    if (tid < K_) {
        float m = -3e30f;
        for (int j = 0; j < 256; j++) m = fmaxf(m, red[tid][j]);
        g_s2part[r][b][z][tid] = m;
    }
}

// ---------------- final combine ----------------------------------------------
__global__ void k_final(float* __restrict__ out) {
    int b = threadIdx.x;
    if (b >= B_) return;
    float res = expf(fdec(g_s0key[b]));
#pragma unroll
    for (int r = 0; r < R_; r++)
#pragma unroll
        for (int k = 0; k < K_; k++) {
            float m = -3e30f;
            for (int z = 0; z < ZSPLIT; z++) m = fmaxf(m, g_s2part[r][b][z][k]);
            float s2 = m - 0.5f * g_esq[b][g_zidx[r][b][k]];
            res = fmaxf(res, expf(fminf(s2, g_zlog[r][b][k])));
        }
    out[b] = res;
}

// ---------------- launch -------------------------------------------------------
extern "C" void kernel_launch(void* const* d_in, const int* in_sizes, int n_in,
                              void* d_out, int out_size) {
    (void)in_sizes; (void)n_in; (void)out_size;
    const float* rel = (const float*)d_in[0];
    const float* arg1 = (const float*)d_in[1];
    const float* arg2 = (const float*)d_in[2];
    const float* fr = (const float*)d_in[3];
    const float* fa1 = (const float*)d_in[4];
    const float* fa2 = (const float*)d_in[5];
    const float* ent = (const float*)d_in[6];
    const float* W = (const float*)d_in[7];
    const float* hb = (const float*)d_in[8];
    const int* nbf = (const int*)d_in[9];
    const int* nbe = (const int*)d_in[10];
    float* out = (float*)d_out;

    cudaFuncSetAttribute(k_maxgemm, cudaFuncAttributeMaxDynamicSharedMemorySize, SMEM_MG);

    k_split<<<dim3((B_ * N_ * E_) / 1024, 3), 256>>>(ent, fa1, fa2);
    k_hop<<<dim3(B_, 2, R_), E_>>>(rel, W, hb);
    k_esq<<<(B_ * N_) / 8, 256>>>(ent);
    k_cbias<<<(B_ * F_) / 8, 256>>>(rel, arg1, arg2, fr, fa1, fa2, nbf);
    k_maxgemm<<<dim3(N_ / 128, B_, R_), 256, SMEM_MG>>>(nbe);
    k_topk<<<dim3(B_, R_), 256>>>();
    k_s2<<<dim3(B_, R_, ZSPLIT), 256>>>(ent, fa1, fa2);
    k_final<<<1, 32>>>(out);
}

// round 5
// speedup vs baseline: 2.7278x; 1.1114x over previous
#include <cuda_runtime.h>
#include <cuda_bf16.h>
#include <cstdint>

#define B_ 16
#define N_ 2048
#define F_ 2048
#define E_ 128
#define K_ 10
#define R_ 2
#define ZSPLIT 8

// ---------------- device scratch (static, no runtime allocation) ----------
__device__ float g_h[R_][2][B_][E_];        // hop vectors (h1,h2) per rule
__device__ float g_esq[B_][N_];             // entity squared norms
__device__ float g_cbias[R_][B_][F_];       // hop-1 fact bias
__device__ float g_cb2[R_][B_][F_];         // hop-2 fact bias
__device__ unsigned g_s0key[B_];            // scores_0 ordered-int atomic max
__device__ unsigned g_Lkey[R_][B_][N_];     // hop-1 log scores (ordered-uint)
__device__ int   g_zidx[R_][B_][K_];
__device__ float g_zlog[R_][B_][K_];
__device__ float g_s2part[R_][B_][ZSPLIT][K_];

// bf16 hi/lo split planes
__device__ __nv_bfloat16 g_ehi[B_ * N_ * E_];
__device__ __nv_bfloat16 g_elo[B_ * N_ * E_];
__device__ __nv_bfloat16 g_f1hi[B_ * F_ * E_];
__device__ __nv_bfloat16 g_f1lo[B_ * F_ * E_];
__device__ __nv_bfloat16 g_f2hi[B_ * F_ * E_];
__device__ __nv_bfloat16 g_f2lo[B_ * F_ * E_];

// ---------------- helpers ---------------------------------------------------
__device__ __forceinline__ float warp_sum(float v) {
#pragma unroll
    for (int o = 16; o > 0; o >>= 1) v += __shfl_xor_sync(0xffffffffu, v, o);
    return v;
}
__device__ __forceinline__ float hsum16(float v) {
#pragma unroll
    for (int o = 8; o > 0; o >>= 1) v += __shfl_xor_sync(0xffffffffu, v, o);
    return v;
}
__device__ __forceinline__ float dot4(float4 a, float4 b) {
    return a.x * b.x + a.y * b.y + a.z * b.z + a.w * b.w;
}
__device__ __forceinline__ unsigned fenc(float v) {
    unsigned u = __float_as_uint(v);
    return (u & 0x80000000u) ? ~u : (u | 0x80000000u);
}
__device__ __forceinline__ float fdec(unsigned k) {
    return (k & 0x80000000u) ? __uint_as_float(k ^ 0x80000000u) : __uint_as_float(~k);
}
__device__ __forceinline__ uint32_t smem_u32(const void* p) {
    uint32_t a;
    asm("{ .reg .u64 t; cvta.to.shared.u64 t, %1; cvt.u32.u64 %0, t; }" : "=r"(a) : "l"(p));
    return a;
}

// ---------------- portable tensor-core / async-copy PTX ----------------------
__device__ __forceinline__ void cp16(uint32_t s, const void* g) {
    asm volatile("cp.async.cg.shared.global [%0], [%1], 16;" :: "r"(s), "l"(g));
}
__device__ __forceinline__ void cpcommit() { asm volatile("cp.async.commit_group;"); }
template <int NN>
__device__ __forceinline__ void cpwait() {
    asm volatile("cp.async.wait_group %0;" :: "n"(NN));
}
__device__ __forceinline__ void ldsm4(uint32_t& r0, uint32_t& r1, uint32_t& r2, uint32_t& r3,
                                      uint32_t a) {
    asm volatile("ldmatrix.sync.aligned.m8n8.x4.shared.b16 {%0,%1,%2,%3}, [%4];"
                 : "=r"(r0), "=r"(r1), "=r"(r2), "=r"(r3) : "r"(a));
}
__device__ __forceinline__ void mma16816(float* c, const uint32_t* a, const uint32_t* b) {
    asm volatile(
        "mma.sync.aligned.m16n8k16.row.col.f32.bf16.bf16.f32 "
        "{%0,%1,%2,%3},{%4,%5,%6,%7},{%8,%9},{%0,%1,%2,%3};"
        : "+f"(c[0]), "+f"(c[1]), "+f"(c[2]), "+f"(c[3])
        : "r"(a[0]), "r"(a[1]), "r"(a[2]), "r"(a[3]), "r"(b[0]), "r"(b[1]));
}
// swizzled tile offset: 128 rows x 128 bf16 (256B rows, 16-byte chunks, XOR swizzle)
__device__ __forceinline__ uint32_t swz(int row, int chunk) {
    return (uint32_t)row * 256u + (uint32_t)((chunk ^ (row & 7)) * 16);
}

// ------ bf16 hi/lo split + fused entity norms + g_Lkey init ------------------
__global__ void k_split(const float* __restrict__ ent, const float* __restrict__ fa1,
                        const float* __restrict__ fa2) {
    int z = blockIdx.y;
    int tid = threadIdx.x;
    size_t i = ((size_t)blockIdx.x * 256 + tid) * 4;
    const float* src = (z == 0) ? ent : (z == 1) ? fa1 : fa2;
    __nv_bfloat16* hi = (z == 0) ? g_ehi : (z == 1) ? g_f1hi : g_f2hi;
    __nv_bfloat16* lo = (z == 0) ? g_elo : (z == 1) ? g_f1lo : g_f2lo;
    float4 v = *(const float4*)(src + i);
    __nv_bfloat16 h0 = __float2bfloat16(v.x), h1 = __float2bfloat16(v.y);
    __nv_bfloat16 h2 = __float2bfloat16(v.z), h3 = __float2bfloat16(v.w);
    __nv_bfloat16 l0 = __float2bfloat16(v.x - __bfloat162float(h0));
    __nv_bfloat16 l1 = __float2bfloat16(v.y - __bfloat162float(h1));
    __nv_bfloat16 l2 = __float2bfloat16(v.z - __bfloat162float(h2));
    __nv_bfloat16 l3 = __float2bfloat16(v.w - __bfloat162float(h3));
    __nv_bfloat162 hh0 = __halves2bfloat162(h0, h1), hh1 = __halves2bfloat162(h2, h3);
    __nv_bfloat162 ll0 = __halves2bfloat162(l0, l1), ll1 = __halves2bfloat162(l2, l3);
    uint2 uh = {*(unsigned*)&hh0, *(unsigned*)&hh1};
    uint2 ul = {*(unsigned*)&ll0, *(unsigned*)&ll1};
    *(uint2*)(hi + i) = uh;
    *(uint2*)(lo + i) = ul;
    if (z == 0) {
        // one warp == one entity row (32 lanes * 4 floats = 128)
        float s = warp_sum(dot4(v, v));
        if ((tid & 31) == 0) {
            int gw = blockIdx.x * 8 + (tid >> 5);  // row over B*N
            ((float*)g_esq)[gw] = s;
            unsigned init = fenc(-3e30f);
            int b = gw >> 11, n = gw & (N_ - 1);
            g_Lkey[0][b][n] = init;
            g_Lkey[1][b][n] = init;
        }
    }
}

// ---------------- hop vectors + s0key init ----------------------------------
__global__ void k_hop(const float* __restrict__ rel, const float* __restrict__ W,
                      const float* __restrict__ hb) {
    int b = blockIdx.x, h = blockIdx.y, r = blockIdx.z, e = threadIdx.x;
    if (e == 0 && h == 0 && r == 0) g_s0key[b] = fenc(-3e30f);
    const float* w = W + (size_t)((r * 2 + h) * E_) * E_ + e;
    const float* rb = rel + b * E_;
    float s = hb[(r * 2 + h) * E_ + e];
#pragma unroll 8
    for (int i = 0; i < E_; i++) s += rb[i] * w[(size_t)i * E_];
    g_h[r][h][b][e] = s;
}

// -------- per-fact biases (hop1, hop2) + fused scores_0; 2 facts/warp --------
__global__ void k_cbias(const float* __restrict__ rel, const float* __restrict__ arg1,
                        const float* __restrict__ arg2, const float* __restrict__ fr,
                        const float* __restrict__ fa1, const float* __restrict__ fa2,
                        const int* __restrict__ nbf) {
    int tid = threadIdx.x, lane = tid & 31, hl = lane & 15;
    int fi = ((blockIdx.x * 256 + tid) >> 5) * 2 + (lane >> 4);
    int b = fi >> 11, f = fi & (F_ - 1);
    size_t off = ((size_t)b * F_ + f) * E_ + hl * 8;
    const float4* PR = (const float4*)(fr + off);
    const float4* P1 = (const float4*)(fa1 + off);
    const float4* P2 = (const float4*)(fa2 + off);
    float4 vr0 = PR[0], vr1 = PR[1];
    float4 v10 = P1[0], v11 = P1[1];
    float4 v20 = P2[0], v21 = P2[1];
    const float4* Q;
#define LD2(dst0, dst1, base) Q = (const float4*)(base); float4 dst0 = Q[0], dst1 = Q[1];
    LD2(h00a, h00b, &g_h[0][0][b][hl * 8]);
    LD2(h10a, h10b, &g_h[1][0][b][hl * 8]);
    LD2(h01a, h01b, &g_h[0][1][b][hl * 8]);
    LD2(h11a, h11b, &g_h[1][1][b][hl * 8]);
    LD2(qra, qrb, rel + b * E_ + hl * 8);
    LD2(a1a, a1b, arg1 + b * E_ + hl * 8);
    LD2(a2a, a2b, arg2 + b * E_ + hl * 8);
#undef LD2
    float nsum = dot4(vr0, vr0) + dot4(vr1, vr1) + dot4(v10, v10) + dot4(v11, v11) +
                 dot4(v20, v20) + dot4(v21, v21);
    float a1s = dot4(a1a, a1a) + dot4(a1b, a1b);
    float a2s = dot4(a2a, a2a) + dot4(a2b, a2b);
    float p0 = nsum + dot4(h00a, h00a) + dot4(h00b, h00b) + a1s -
               2.f * (dot4(h00a, vr0) + dot4(h00b, vr1) + dot4(a1a, v10) + dot4(a1b, v11));
    float p1 = nsum + dot4(h10a, h10a) + dot4(h10b, h10b) + a1s -
               2.f * (dot4(h10a, vr0) + dot4(h10b, vr1) + dot4(a1a, v20) + dot4(a1b, v21));
    float q0 = nsum + dot4(h01a, h01a) + dot4(h01b, h01b) + a2s -
               2.f * (dot4(h01a, vr0) + dot4(h01b, vr1) + dot4(a2a, v20) + dot4(a2b, v21));
    float q1 = nsum + dot4(h11a, h11a) + dot4(h11b, h11b) + a2s -
               2.f * (dot4(h11a, vr0) + dot4(h11b, vr1) + dot4(a2a, v10) + dot4(a2b, v11));
    float s = nsum + dot4(qra, qra) + dot4(qrb, qrb) + a1s + a2s -
              2.f * (dot4(qra, vr0) + dot4(qrb, vr1) + dot4(a1a, v10) + dot4(a1b, v11) +
                     dot4(a2a, v20) + dot4(a2b, v21));
    p0 = hsum16(p0);
    p1 = hsum16(p1);
    q0 = hsum16(q0);
    q1 = hsum16(q1);
    s = hsum16(s);
    if (hl == 0) {
        bool valid = f < nbf[b];
        g_cbias[0][b][f] = valid ? -0.5f * p0 : -3e30f;
        g_cbias[1][b][f] = valid ? -0.5f * p1 : -3e30f;
        g_cb2[0][b][f] = valid ? -0.5f * q0 : -3e30f;
        g_cb2[1][b][f] = valid ? -0.5f * q1 : -3e30f;
        if (valid) atomicMax(&g_s0key[b], fenc(-0.5f * s));
    }
}

// ---------------- heavy max-plus GEMM via mma.sync (bf16 hi/lo split) --------
// grid (nt=16, b=16, r*2+fhalf=4): each CTA covers 8 fact tiles (half the range)
#define OFF_AHI 0
#define OFF_ALO 32768
#define OFF_B0 65536
#define SMEM_MG 196608

__global__ __launch_bounds__(256, 1) void k_maxgemm(const int* __restrict__ nbe) {
    extern __shared__ char smem[];
    uint32_t sb = smem_u32(smem);
    const int tid = threadIdx.x, lane = tid & 31, wid = tid >> 5;
    const int wm = (wid & 1) * 64, wn = (wid >> 1) * 32;
    const int nt = blockIdx.x, b = blockIdx.y;
    const int r = blockIdx.z >> 1, fh = blockIdx.z & 1;

    const __nv_bfloat16* ehi = g_ehi + ((size_t)b * N_ + nt * 128) * E_;
    const __nv_bfloat16* elo = g_elo + ((size_t)b * N_ + nt * 128) * E_;
    const __nv_bfloat16* fhi = ((r == 0) ? g_f2hi : g_f1hi) + (size_t)b * F_ * E_;
    const __nv_bfloat16* flo = ((r == 0) ? g_f2lo : g_f1lo) + (size_t)b * F_ * E_;
    const float* cb = &g_cbias[r][b][0];

    // resident entity tile (hi + lo), swizzled
#pragma unroll
    for (int it = 0; it < 8; ++it) {
        int i = tid + it * 256;
        int row = i >> 4, ch = i & 15;
        uint32_t o = swz(row, ch);
        *(uint4*)(smem + OFF_AHI + o) = *(const uint4*)(ehi + (size_t)row * E_ + ch * 8);
        *(uint4*)(smem + OFF_ALO + o) = *(const uint4*)(elo + (size_t)row * E_ + ch * 8);
    }

    auto issueB = [&](int ft, int buf) {
        uint32_t base = sb + OFF_B0 + buf * 65536;
        const __nv_bfloat16* sh = fhi + (size_t)ft * 128 * E_;
        const __nv_bfloat16* sl = flo + (size_t)ft * 128 * E_;
#pragma unroll
        for (int it = 0; it < 8; ++it) {
            int i = tid + it * 256;
            int row = i >> 4, ch = i & 15;
            uint32_t o = swz(row, ch);
            cp16(base + o, sh + (size_t)row * E_ + ch * 8);
            cp16(base + 32768 + o, sl + (size_t)row * E_ + ch * 8);
        }
    };
    issueB(fh * 8, 0);
    cpcommit();

    float rmax[8];
#pragma unroll
    for (int i = 0; i < 8; i++) rmax[i] = -3e30f;

    for (int t = 0; t < 8; ++t) {
        int ft = fh * 8 + t;
        cpwait<0>();
        __syncthreads();  // buffer t&1 ready AND everyone done with it from t-2
        if (t + 1 < 8) {
            issueB(ft + 1, (t + 1) & 1);
            cpcommit();
        }

        float acc[4][4][4];
#pragma unroll
        for (int i = 0; i < 4; i++)
#pragma unroll
            for (int j = 0; j < 4; j++)
#pragma unroll
                for (int q = 0; q < 4; q++) acc[i][j][q] = 0.f;

        uint32_t bbase = sb + OFF_B0 + (t & 1) * 65536;
#pragma unroll
        for (int ks = 0; ks < 8; ++ks) {
            int kc = ks * 2 + (lane >> 4);
            uint32_t ah[4][4], al[4][4];
#pragma unroll
            for (int i = 0; i < 4; i++) {
                int row = wm + i * 16 + (lane & 15);
                uint32_t o = swz(row, kc);
                ldsm4(ah[i][0], ah[i][1], ah[i][2], ah[i][3], sb + OFF_AHI + o);
                ldsm4(al[i][0], al[i][1], al[i][2], al[i][3], sb + OFF_ALO + o);
            }
            uint32_t bh[4][2], bl[4][2];
#pragma unroll
            for (int p = 0; p < 2; p++) {
                int row = wn + p * 16 + (lane & 15);
                uint32_t o = swz(row, kc);
                uint32_t r0, r1, r2, r3;
                ldsm4(r0, r1, r2, r3, bbase + o);
                bh[2 * p][0] = r0; bh[2 * p][1] = r2;
                bh[2 * p + 1][0] = r1; bh[2 * p + 1][1] = r3;
                ldsm4(r0, r1, r2, r3, bbase + 32768 + o);
                bl[2 * p][0] = r0; bl[2 * p][1] = r2;
                bl[2 * p + 1][0] = r1; bl[2 * p + 1][1] = r3;
            }
#pragma unroll
            for (int i = 0; i < 4; i++)
#pragma unroll
                for (int j = 0; j < 4; j++) {
                    mma16816(acc[i][j], ah[i], bh[j]);
                    mma16816(acc[i][j], ah[i], bl[j]);
                    mma16816(acc[i][j], al[i], bh[j]);
                }
        }
        __syncthreads();  // all warps done reading buffer t&1 before t+1 overwrites... (t+1 uses other buf; this sync orders t+2's issue)
        // epilogue: add cbias, fold running row-max
#pragma unroll
        for (int j = 0; j < 4; j++) {
            int col = ft * 128 + wn + j * 8 + 2 * (lane & 3);
            float c0 = __ldg(cb + col), c1 = __ldg(cb + col + 1);
#pragma unroll
            for (int i = 0; i < 4; i++) {
                rmax[2 * i] = fmaxf(rmax[2 * i], fmaxf(acc[i][j][0] + c0, acc[i][j][1] + c1));
                rmax[2 * i + 1] = fmaxf(rmax[2 * i + 1],
                                        fmaxf(acc[i][j][2] + c0, acc[i][j][3] + c1));
            }
        }
    }

    // cross-thread row-max reduction (reuse smem)
    __syncthreads();
    float* Red = (float*)smem;
#pragma unroll
    for (int i = 0; i < 4; i++)
#pragma unroll
        for (int h = 0; h < 2; h++) {
            int row = wm + i * 16 + h * 8 + (lane >> 2);
            Red[row * 16 + (wid >> 1) * 4 + (lane & 3)] = rmax[2 * i + h];
        }
    __syncthreads();
    if (tid < 128) {
        float m = -3e30f;
#pragma unroll
        for (int t = 0; t < 16; t++) m = fmaxf(m, Red[tid * 16 + t]);
        int gn = nt * 128 + tid;
        float Lv = m - 0.5f * g_esq[b][gn];
        if (gn < nbe[b]) atomicMax(&g_Lkey[r][b][gn], fenc(Lv));
    }
}

// ---------------- top-K over N per (r,b): shuffle-based -----------------------
__global__ void k_topk() {
    int b = blockIdx.x, r = blockIdx.y, tid = threadIdx.x;
    int lane = tid & 31, wid = tid >> 5;
    float v[8];
#pragma unroll
    for (int j = 0; j < 8; j++) v[j] = fdec(g_Lkey[r][b][tid + 256 * j]);
    __shared__ float swv[8];
    __shared__ int swi[8];
    __shared__ int schosen;
    for (int kk = 0; kk < K_; kk++) {
        float bv = -3.4e38f;
        int bi = 0;
#pragma unroll
        for (int j = 0; j < 8; j++)
            if (v[j] > bv) { bv = v[j]; bi = tid + 256 * j; }
#pragma unroll
        for (int o = 16; o > 0; o >>= 1) {
            float ov = __shfl_xor_sync(0xffffffffu, bv, o);
            int oi = __shfl_xor_sync(0xffffffffu, bi, o);
            if (ov > bv || (ov == bv && oi < bi)) { bv = ov; bi = oi; }
        }
        if (lane == 0) { swv[wid] = bv; swi[wid] = bi; }
        __syncthreads();
        if (wid == 0) {
            float bv2 = (lane < 8) ? swv[lane] : -3.4e38f;
            int bi2 = (lane < 8) ? swi[lane] : 0;
#pragma unroll
            for (int o = 4; o > 0; o >>= 1) {
                float ov = __shfl_xor_sync(0xffffffffu, bv2, o);
                int oi = __shfl_xor_sync(0xffffffffu, bi2, o);
                if (ov > bv2 || (ov == bv2 && oi < bi2)) { bv2 = ov; bi2 = oi; }
            }
            if (lane == 0) {
                g_zidx[r][b][kk] = bi2;
                g_zlog[r][b][kk] = bv2;
                schosen = bi2;
            }
        }
        __syncthreads();
        int ch = schosen;
        if ((ch & 255) == tid) v[ch >> 8] = -3.4e38f;
        __syncthreads();
    }
}

// ---------------- hop-2 rescoring: max-plus over facts (split 8-way) ---------
__global__ void k_s2(const float* __restrict__ ent, const float* __restrict__ fa1,
                     const float* __restrict__ fa2) {
    int b = blockIdx.x, r = blockIdx.y, z = blockIdx.z, tid = threadIdx.x;
    int lane = tid & 31, wid = tid >> 5;
    __shared__ float zs[K_][E_];
    __shared__ float red[K_][257];
    for (int i = tid; i < K_ * E_; i += 256) {
        int k = i >> 7, e = i & 127;
        zs[k][e] = ent[((size_t)b * N_ + g_zidx[r][b][k]) * E_ + e];
    }
    __syncthreads();
    const float* fy = ((r == 0) ? fa1 : fa2) + (size_t)b * F_ * E_;
    int f = z * 256 + tid;
    float c = g_cb2[r][b][f];
    const float4* row = (const float4*)(fy + (size_t)f * E_);
    float d[K_];
#pragma unroll
    for (int k = 0; k < K_; k++) d[k] = 0.f;
#pragma unroll 4
    for (int e4 = 0; e4 < 32; e4++) {
        float4 v = row[e4];
#pragma unroll
        for (int k = 0; k < K_; k++) {
            float4 zz = ((const float4*)zs[k])[e4];
            d[k] += v.x * zz.x + v.y * zz.y + v.z * zz.z + v.w * zz.w;
        }
    }
#pragma unroll
    for (int k = 0; k < K_; k++) red[k][tid] = d[k] + c;
    __syncthreads();
    for (int k = wid; k < K_; k += 8) {
        float m = -3e30f;
        for (int j = lane; j < 256; j += 32) m = fmaxf(m, red[k][j]);
#pragma unroll
        for (int o = 16; o > 0; o >>= 1) m = fmaxf(m, __shfl_xor_sync(0xffffffffu, m, o));
        if (lane == 0) g_s2part[r][b][z][k] = m;
    }
}

// ---------------- final combine ----------------------------------------------
__global__ void k_final(float* __restrict__ out) {
    int b = threadIdx.x;
    if (b >= B_) return;
    float res = expf(fdec(g_s0key[b]));
#pragma unroll
    for (int r = 0; r < R_; r++)
#pragma unroll
        for (int k = 0; k < K_; k++) {
            float m = -3e30f;
            for (int z = 0; z < ZSPLIT; z++) m = fmaxf(m, g_s2part[r][b][z][k]);
            float s2 = m - 0.5f * g_esq[b][g_zidx[r][b][k]];
            res = fmaxf(res, expf(fminf(s2, g_zlog[r][b][k])));
        }
    out[b] = res;
}

// ---------------- launch -------------------------------------------------------
extern "C" void kernel_launch(void* const* d_in, const int* in_sizes, int n_in,
                              void* d_out, int out_size) {
    (void)in_sizes; (void)n_in; (void)out_size;
    const float* rel = (const float*)d_in[0];
    const float* arg1 = (const float*)d_in[1];
    const float* arg2 = (const float*)d_in[2];
    const float* fr = (const float*)d_in[3];
    const float* fa1 = (const float*)d_in[4];
    const float* fa2 = (const float*)d_in[5];
    const float* ent = (const float*)d_in[6];
    const float* W = (const float*)d_in[7];
    const float* hb = (const float*)d_in[8];
    const int* nbf = (const int*)d_in[9];
    const int* nbe = (const int*)d_in[10];
    float* out = (float*)d_out;

    cudaFuncSetAttribute(k_maxgemm, cudaFuncAttributeMaxDynamicSharedMemorySize, SMEM_MG);

    k_split<<<dim3((B_ * N_ * E_) / 1024, 3), 256>>>(ent, fa1, fa2);
    k_hop<<<dim3(B_, 2, R_), E_>>>(rel, W, hb);
    k_cbias<<<(B_ * F_) / 16, 256>>>(rel, arg1, arg2, fr, fa1, fa2, nbf);
    k_maxgemm<<<dim3(N_ / 128, B_, 2 * R_), 256, SMEM_MG>>>(nbe);
    k_topk<<<dim3(B_, R_), 256>>>();
    k_s2<<<dim3(B_, R_, ZSPLIT), 256>>>(ent, fa1, fa2);
    k_final<<<1, 32>>>(out);
}

// round 6
// speedup vs baseline: 2.8632x; 1.0496x over previous
#include <cuda_runtime.h>
#include <cuda_bf16.h>
#include <cstdint>

#define B_ 16
#define N_ 2048
#define F_ 2048
#define E_ 128
#define K_ 10
#define R_ 2
#define ZSPLIT 8

// ---------------- device scratch (static, no runtime allocation) ----------
__device__ float g_h[R_][2][B_][E_];        // hop vectors (h1,h2) per rule
__device__ float g_esq[B_][N_];             // entity squared norms
__device__ float g_cbias[R_][B_][F_];       // hop-1 fact bias
__device__ float g_cb2[R_][B_][F_];         // hop-2 fact bias
__device__ unsigned g_s0key[B_];            // scores_0 ordered-int atomic max
__device__ unsigned g_Lkey[R_][B_][N_];     // hop-1 log scores (ordered-uint)
__device__ int   g_zidx[R_][B_][K_];
__device__ float g_zlog[R_][B_][K_];
__device__ float g_s2part[R_][B_][ZSPLIT][K_];

// bf16 hi/lo split planes
__device__ __nv_bfloat16 g_ehi[B_ * N_ * E_];
__device__ __nv_bfloat16 g_elo[B_ * N_ * E_];
__device__ __nv_bfloat16 g_f1hi[B_ * F_ * E_];
__device__ __nv_bfloat16 g_f1lo[B_ * F_ * E_];
__device__ __nv_bfloat16 g_f2hi[B_ * F_ * E_];
__device__ __nv_bfloat16 g_f2lo[B_ * F_ * E_];

// ---------------- helpers ---------------------------------------------------
__device__ __forceinline__ float warp_sum(float v) {
#pragma unroll
    for (int o = 16; o > 0; o >>= 1) v += __shfl_xor_sync(0xffffffffu, v, o);
    return v;
}
__device__ __forceinline__ float hsum16(float v) {
#pragma unroll
    for (int o = 8; o > 0; o >>= 1) v += __shfl_xor_sync(0xffffffffu, v, o);
    return v;
}
__device__ __forceinline__ float dot4(float4 a, float4 b) {
    return a.x * b.x + a.y * b.y + a.z * b.z + a.w * b.w;
}
__device__ __forceinline__ unsigned fenc(float v) {
    unsigned u = __float_as_uint(v);
    return (u & 0x80000000u) ? ~u : (u | 0x80000000u);
}
__device__ __forceinline__ float fdec(unsigned k) {
    return (k & 0x80000000u) ? __uint_as_float(k ^ 0x80000000u) : __uint_as_float(~k);
}
__device__ __forceinline__ uint32_t smem_u32(const void* p) {
    uint32_t a;
    asm("{ .reg .u64 t; cvta.to.shared.u64 t, %1; cvt.u32.u64 %0, t; }" : "=r"(a) : "l"(p));
    return a;
}

// ---------------- portable tensor-core / async-copy PTX ----------------------
__device__ __forceinline__ void cp16(uint32_t s, const void* g) {
    asm volatile("cp.async.cg.shared.global [%0], [%1], 16;" :: "r"(s), "l"(g));
}
__device__ __forceinline__ void cpcommit() { asm volatile("cp.async.commit_group;"); }
template <int NN>
__device__ __forceinline__ void cpwait() {
    asm volatile("cp.async.wait_group %0;" :: "n"(NN));
}
__device__ __forceinline__ void ldsm4(uint32_t& r0, uint32_t& r1, uint32_t& r2, uint32_t& r3,
                                      uint32_t a) {
    asm volatile("ldmatrix.sync.aligned.m8n8.x4.shared.b16 {%0,%1,%2,%3}, [%4];"
                 : "=r"(r0), "=r"(r1), "=r"(r2), "=r"(r3) : "r"(a));
}
__device__ __forceinline__ void mma16816(float* c, const uint32_t* a, const uint32_t* b) {
    asm volatile(
        "mma.sync.aligned.m16n8k16.row.col.f32.bf16.bf16.f32 "
        "{%0,%1,%2,%3},{%4,%5,%6,%7},{%8,%9},{%0,%1,%2,%3};"
        : "+f"(c[0]), "+f"(c[1]), "+f"(c[2]), "+f"(c[3])
        : "r"(a[0]), "r"(a[1]), "r"(a[2]), "r"(a[3]), "r"(b[0]), "r"(b[1]));
}
// swizzled tile offset: 128 rows x 128 bf16 (256B rows, 16-byte chunks, XOR swizzle)
__device__ __forceinline__ uint32_t swz(int row, int chunk) {
    return (uint32_t)row * 256u + (uint32_t)((chunk ^ (row & 7)) * 16);
}

// ------ bf16 hi/lo split + fused entity norms + g_Lkey init ------------------
__global__ void k_split(const float* __restrict__ ent, const float* __restrict__ fa1,
                        const float* __restrict__ fa2) {
    int z = blockIdx.y;
    int tid = threadIdx.x;
    size_t i = ((size_t)blockIdx.x * 256 + tid) * 4;
    const float* src = (z == 0) ? ent : (z == 1) ? fa1 : fa2;
    __nv_bfloat16* hi = (z == 0) ? g_ehi : (z == 1) ? g_f1hi : g_f2hi;
    __nv_bfloat16* lo = (z == 0) ? g_elo : (z == 1) ? g_f1lo : g_f2lo;
    float4 v = *(const float4*)(src + i);
    __nv_bfloat16 h0 = __float2bfloat16(v.x), h1 = __float2bfloat16(v.y);
    __nv_bfloat16 h2 = __float2bfloat16(v.z), h3 = __float2bfloat16(v.w);
    __nv_bfloat16 l0 = __float2bfloat16(v.x - __bfloat162float(h0));
    __nv_bfloat16 l1 = __float2bfloat16(v.y - __bfloat162float(h1));
    __nv_bfloat16 l2 = __float2bfloat16(v.z - __bfloat162float(h2));
    __nv_bfloat16 l3 = __float2bfloat16(v.w - __bfloat162float(h3));
    __nv_bfloat162 hh0 = __halves2bfloat162(h0, h1), hh1 = __halves2bfloat162(h2, h3);
    __nv_bfloat162 ll0 = __halves2bfloat162(l0, l1), ll1 = __halves2bfloat162(l2, l3);
    uint2 uh = {*(unsigned*)&hh0, *(unsigned*)&hh1};
    uint2 ul = {*(unsigned*)&ll0, *(unsigned*)&ll1};
    *(uint2*)(hi + i) = uh;
    *(uint2*)(lo + i) = ul;
    if (z == 0) {
        float s = warp_sum(dot4(v, v));
        if ((tid & 31) == 0) {
            int gw = blockIdx.x * 8 + (tid >> 5);
            ((float*)g_esq)[gw] = s;
            unsigned init = fenc(-3e30f);
            int b = gw >> 11, n = gw & (N_ - 1);
            g_Lkey[0][b][n] = init;
            g_Lkey[1][b][n] = init;
        }
    }
}

// ---------------- hop vectors + s0key init ----------------------------------
__global__ void k_hop(const float* __restrict__ rel, const float* __restrict__ W,
                      const float* __restrict__ hb) {
    int b = blockIdx.x, h = blockIdx.y, r = blockIdx.z, e = threadIdx.x;
    if (e == 0 && h == 0 && r == 0) g_s0key[b] = fenc(-3e30f);
    const float* w = W + (size_t)((r * 2 + h) * E_) * E_ + e;
    const float* rb = rel + b * E_;
    float s = hb[(r * 2 + h) * E_ + e];
#pragma unroll 8
    for (int i = 0; i < E_; i++) s += rb[i] * w[(size_t)i * E_];
    g_h[r][h][b][e] = s;
}

// -------- per-fact biases (hop1, hop2) + fused scores_0; 2 facts/warp --------
__global__ void k_cbias(const float* __restrict__ rel, const float* __restrict__ arg1,
                        const float* __restrict__ arg2, const float* __restrict__ fr,
                        const float* __restrict__ fa1, const float* __restrict__ fa2,
                        const int* __restrict__ nbf) {
    int tid = threadIdx.x, lane = tid & 31, hl = lane & 15;
    int fi = ((blockIdx.x * 256 + tid) >> 5) * 2 + (lane >> 4);
    int b = fi >> 11, f = fi & (F_ - 1);
    size_t off = ((size_t)b * F_ + f) * E_ + hl * 8;
    const float4* PR = (const float4*)(fr + off);
    const float4* P1 = (const float4*)(fa1 + off);
    const float4* P2 = (const float4*)(fa2 + off);
    float4 vr0 = PR[0], vr1 = PR[1];
    float4 v10 = P1[0], v11 = P1[1];
    float4 v20 = P2[0], v21 = P2[1];
    const float4* Q;
#define LD2(dst0, dst1, base) Q = (const float4*)(base); float4 dst0 = Q[0], dst1 = Q[1];
    LD2(h00a, h00b, &g_h[0][0][b][hl * 8]);
    LD2(h10a, h10b, &g_h[1][0][b][hl * 8]);
    LD2(h01a, h01b, &g_h[0][1][b][hl * 8]);
    LD2(h11a, h11b, &g_h[1][1][b][hl * 8]);
    LD2(qra, qrb, rel + b * E_ + hl * 8);
    LD2(a1a, a1b, arg1 + b * E_ + hl * 8);
    LD2(a2a, a2b, arg2 + b * E_ + hl * 8);
#undef LD2
    float nsum = dot4(vr0, vr0) + dot4(vr1, vr1) + dot4(v10, v10) + dot4(v11, v11) +
                 dot4(v20, v20) + dot4(v21, v21);
    float a1s = dot4(a1a, a1a) + dot4(a1b, a1b);
    float a2s = dot4(a2a, a2a) + dot4(a2b, a2b);
    float p0 = nsum + dot4(h00a, h00a) + dot4(h00b, h00b) + a1s -
               2.f * (dot4(h00a, vr0) + dot4(h00b, vr1) + dot4(a1a, v10) + dot4(a1b, v11));
    float p1 = nsum + dot4(h10a, h10a) + dot4(h10b, h10b) + a1s -
               2.f * (dot4(h10a, vr0) + dot4(h10b, vr1) + dot4(a1a, v20) + dot4(a1b, v21));
    float q0 = nsum + dot4(h01a, h01a) + dot4(h01b, h01b) + a2s -
               2.f * (dot4(h01a, vr0) + dot4(h01b, vr1) + dot4(a2a, v20) + dot4(a2b, v21));
    float q1 = nsum + dot4(h11a, h11a) + dot4(h11b, h11b) + a2s -
               2.f * (dot4(h11a, vr0) + dot4(h11b, vr1) + dot4(a2a, v10) + dot4(a2b, v11));
    float s = nsum + dot4(qra, qra) + dot4(qrb, qrb) + a1s + a2s -
              2.f * (dot4(qra, vr0) + dot4(qrb, vr1) + dot4(a1a, v10) + dot4(a1b, v11) +
                     dot4(a2a, v20) + dot4(a2b, v21));
    p0 = hsum16(p0);
    p1 = hsum16(p1);
    q0 = hsum16(q0);
    q1 = hsum16(q1);
    s = hsum16(s);
    if (hl == 0) {
        bool valid = f < nbf[b];
        g_cbias[0][b][f] = valid ? -0.5f * p0 : -3e30f;
        g_cbias[1][b][f] = valid ? -0.5f * p1 : -3e30f;
        g_cb2[0][b][f] = valid ? -0.5f * q0 : -3e30f;
        g_cb2[1][b][f] = valid ? -0.5f * q1 : -3e30f;
        if (valid) atomicMax(&g_s0key[b], fenc(-0.5f * s));
    }
}

// ---------------- heavy max-plus GEMM via mma.sync (bf16 hi/lo split) --------
// grid (nt=16, b=16, r*2+fhalf=4); 512 threads / 16 warps, warp tile 32x32
#define OFF_AHI 0
#define OFF_ALO 32768
#define OFF_B0 65536
#define SMEM_MG 196608

__global__ __launch_bounds__(512, 1) void k_maxgemm(const int* __restrict__ nbe) {
    extern __shared__ char smem[];
    uint32_t sb = smem_u32(smem);
    const int tid = threadIdx.x, lane = tid & 31, wid = tid >> 5;
    const int wm = (wid & 3) * 32, wn = (wid >> 2) * 32;
    const int nt = blockIdx.x, b = blockIdx.y;
    const int r = blockIdx.z >> 1, fh = blockIdx.z & 1;

    const __nv_bfloat16* ehi = g_ehi + ((size_t)b * N_ + nt * 128) * E_;
    const __nv_bfloat16* elo = g_elo + ((size_t)b * N_ + nt * 128) * E_;
    const __nv_bfloat16* fhi = ((r == 0) ? g_f2hi : g_f1hi) + (size_t)b * F_ * E_;
    const __nv_bfloat16* flo = ((r == 0) ? g_f2lo : g_f1lo) + (size_t)b * F_ * E_;
    const float* cb = &g_cbias[r][b][0];

    // resident entity tile (hi + lo), swizzled
#pragma unroll
    for (int it = 0; it < 4; ++it) {
        int i = tid + it * 512;
        int row = i >> 4, ch = i & 15;
        uint32_t o = swz(row, ch);
        *(uint4*)(smem + OFF_AHI + o) = *(const uint4*)(ehi + (size_t)row * E_ + ch * 8);
        *(uint4*)(smem + OFF_ALO + o) = *(const uint4*)(elo + (size_t)row * E_ + ch * 8);
    }

    auto issueB = [&](int ft, int buf) {
        uint32_t base = sb + OFF_B0 + buf * 65536;
        const __nv_bfloat16* sh = fhi + (size_t)ft * 128 * E_;
        const __nv_bfloat16* sl = flo + (size_t)ft * 128 * E_;
#pragma unroll
        for (int it = 0; it < 4; ++it) {
            int i = tid + it * 512;
            int row = i >> 4, ch = i & 15;
            uint32_t o = swz(row, ch);
            cp16(base + o, sh + (size_t)row * E_ + ch * 8);
            cp16(base + 32768 + o, sl + (size_t)row * E_ + ch * 8);
        }
    };
    issueB(fh * 8, 0);
    cpcommit();

    float rmax[4];
#pragma unroll
    for (int i = 0; i < 4; i++) rmax[i] = -3e30f;

    for (int t = 0; t < 8; ++t) {
        int ft = fh * 8 + t;
        cpwait<0>();
        __syncthreads();  // buffer t&1 ready; all warps done with buffer (t+1)&1 (read at t-1)
        if (t + 1 < 8) {
            issueB(ft + 1, (t + 1) & 1);
            cpcommit();
        }

        float acc[2][4][4];
#pragma unroll
        for (int i = 0; i < 2; i++)
#pragma unroll
            for (int j = 0; j < 4; j++)
#pragma unroll
                for (int q = 0; q < 4; q++) acc[i][j][q] = 0.f;

        uint32_t bbase = sb + OFF_B0 + (t & 1) * 65536;
#pragma unroll
        for (int ks = 0; ks < 8; ++ks) {
            int kc = ks * 2 + (lane >> 4);
            uint32_t ah[2][4], al[2][4];
#pragma unroll
            for (int i = 0; i < 2; i++) {
                int row = wm + i * 16 + (lane & 15);
                uint32_t o = swz(row, kc);
                ldsm4(ah[i][0], ah[i][1], ah[i][2], ah[i][3], sb + OFF_AHI + o);
                ldsm4(al[i][0], al[i][1], al[i][2], al[i][3], sb + OFF_ALO + o);
            }
            uint32_t bh[4][2], bl[4][2];
#pragma unroll
            for (int p = 0; p < 2; p++) {
                int row = wn + p * 16 + (lane & 15);
                uint32_t o = swz(row, kc);
                uint32_t r0, r1, r2, r3;
                ldsm4(r0, r1, r2, r3, bbase + o);
                bh[2 * p][0] = r0; bh[2 * p][1] = r2;
                bh[2 * p + 1][0] = r1; bh[2 * p + 1][1] = r3;
                ldsm4(r0, r1, r2, r3, bbase + 32768 + o);
                bl[2 * p][0] = r0; bl[2 * p][1] = r2;
                bl[2 * p + 1][0] = r1; bl[2 * p + 1][1] = r3;
            }
#pragma unroll
            for (int i = 0; i < 2; i++)
#pragma unroll
                for (int j = 0; j < 4; j++) {
                    mma16816(acc[i][j], ah[i], bh[j]);
                    mma16816(acc[i][j], ah[i], bl[j]);
                    mma16816(acc[i][j], al[i], bh[j]);
                }
        }
        // epilogue: add cbias, fold running row-max (no extra barrier needed)
#pragma unroll
        for (int j = 0; j < 4; j++) {
            int col = ft * 128 + wn + j * 8 + 2 * (lane & 3);
            float c0 = __ldg(cb + col), c1 = __ldg(cb + col + 1);
#pragma unroll
            for (int i = 0; i < 2; i++) {
                rmax[2 * i] = fmaxf(rmax[2 * i], fmaxf(acc[i][j][0] + c0, acc[i][j][1] + c1));
                rmax[2 * i + 1] = fmaxf(rmax[2 * i + 1],
                                        fmaxf(acc[i][j][2] + c0, acc[i][j][3] + c1));
            }
        }
    }

    // cross-thread row-max reduction (reuse smem)
    __syncthreads();
    float* Red = (float*)smem;
#pragma unroll
    for (int i = 0; i < 2; i++)
#pragma unroll
        for (int h = 0; h < 2; h++) {
            int row = wm + i * 16 + h * 8 + (lane >> 2);
            Red[row * 16 + (wid >> 2) * 4 + (lane & 3)] = rmax[2 * i + h];
        }
    __syncthreads();
    if (tid < 128) {
        float m = -3e30f;
#pragma unroll
        for (int t = 0; t < 16; t++) m = fmaxf(m, Red[tid * 16 + t]);
        int gn = nt * 128 + tid;
        float Lv = m - 0.5f * g_esq[b][gn];
        if (gn < nbe[b]) atomicMax(&g_Lkey[r][b][gn], fenc(Lv));
    }
}

// ---------------- top-K over N per (r,b): shuffle-based -----------------------
__global__ void k_topk() {
    int b = blockIdx.x, r = blockIdx.y, tid = threadIdx.x;
    int lane = tid & 31, wid = tid >> 5;
    float v[8];
#pragma unroll
    for (int j = 0; j < 8; j++) v[j] = fdec(g_Lkey[r][b][tid + 256 * j]);
    __shared__ float swv[8];
    __shared__ int swi[8];
    __shared__ int schosen;
    for (int kk = 0; kk < K_; kk++) {
        float bv = -3.4e38f;
        int bi = 0;
#pragma unroll
        for (int j = 0; j < 8; j++)
            if (v[j] > bv) { bv = v[j]; bi = tid + 256 * j; }
#pragma unroll
        for (int o = 16; o > 0; o >>= 1) {
            float ov = __shfl_xor_sync(0xffffffffu, bv, o);
            int oi = __shfl_xor_sync(0xffffffffu, bi, o);
            if (ov > bv || (ov == bv && oi < bi)) { bv = ov; bi = oi; }
        }
        if (lane == 0) { swv[wid] = bv; swi[wid] = bi; }
        __syncthreads();
        if (wid == 0) {
            float bv2 = (lane < 8) ? swv[lane] : -3.4e38f;
            int bi2 = (lane < 8) ? swi[lane] : 0;
#pragma unroll
            for (int o = 4; o > 0; o >>= 1) {
                float ov = __shfl_xor_sync(0xffffffffu, bv2, o);
                int oi = __shfl_xor_sync(0xffffffffu, bi2, o);
                if (ov > bv2 || (ov == bv2 && oi < bi2)) { bv2 = ov; bi2 = oi; }
            }
            if (lane == 0) {
                g_zidx[r][b][kk] = bi2;
                g_zlog[r][b][kk] = bv2;
                schosen = bi2;
            }
        }
        __syncthreads();
        int ch = schosen;
        if ((ch & 255) == tid) v[ch >> 8] = -3.4e38f;
        __syncthreads();
    }
}

// ---------------- hop-2 rescoring: max-plus over facts (split 8-way) ---------
__global__ void k_s2(const float* __restrict__ ent, const float* __restrict__ fa1,
                     const float* __restrict__ fa2) {
    int b = blockIdx.x, r = blockIdx.y, z = blockIdx.z, tid = threadIdx.x;
    int lane = tid & 31, wid = tid >> 5;
    __shared__ float zs[K_][E_];
    __shared__ float red[K_][257];
    for (int i = tid; i < K_ * E_; i += 256) {
        int k = i >> 7, e = i & 127;
        zs[k][e] = ent[((size_t)b * N_ + g_zidx[r][b][k]) * E_ + e];
    }
    __syncthreads();
    const float* fy = ((r == 0) ? fa1 : fa2) + (size_t)b * F_ * E_;
    int f = z * 256 + tid;
    float c = g_cb2[r][b][f];
    const float4* row = (const float4*)(fy + (size_t)f * E_);
    float d[K_];
#pragma unroll
    for (int k = 0; k < K_; k++) d[k] = 0.f;
#pragma unroll 4
    for (int e4 = 0; e4 < 32; e4++) {
        float4 v = row[e4];
#pragma unroll
        for (int k = 0; k < K_; k++) {
            float4 zz = ((const float4*)zs[k])[e4];
            d[k] += v.x * zz.x + v.y * zz.y + v.z * zz.z + v.w * zz.w;
        }
    }
#pragma unroll
    for (int k = 0; k < K_; k++) red[k][tid] = d[k] + c;
    __syncthreads();
    for (int k = wid; k < K_; k += 8) {
        float m = -3e30f;
        for (int j = lane; j < 256; j += 32) m = fmaxf(m, red[k][j]);
#pragma unroll
        for (int o = 16; o > 0; o >>= 1) m = fmaxf(m, __shfl_xor_sync(0xffffffffu, m, o));
        if (lane == 0) g_s2part[r][b][z][k] = m;
    }
}

// ---------------- final combine ----------------------------------------------
__global__ void k_final(float* __restrict__ out) {
    int b = threadIdx.x;
    if (b >= B_) return;
    float res = expf(fdec(g_s0key[b]));
#pragma unroll
    for (int r = 0; r < R_; r++)
#pragma unroll
        for (int k = 0; k < K_; k++) {
            float m = -3e30f;
            for (int z = 0; z < ZSPLIT; z++) m = fmaxf(m, g_s2part[r][b][z][k]);
            float s2 = m - 0.5f * g_esq[b][g_zidx[r][b][k]];
            res = fmaxf(res, expf(fminf(s2, g_zlog[r][b][k])));
        }
    out[b] = res;
}

// ---------------- launch -------------------------------------------------------
extern "C" void kernel_launch(void* const* d_in, const int* in_sizes, int n_in,
                              void* d_out, int out_size) {
    (void)in_sizes; (void)n_in; (void)out_size;
    const float* rel = (const float*)d_in[0];
    const float* arg1 = (const float*)d_in[1];
    const float* arg2 = (const float*)d_in[2];
    const float* fr = (const float*)d_in[3];
    const float* fa1 = (const float*)d_in[4];
    const float* fa2 = (const float*)d_in[5];
    const float* ent = (const float*)d_in[6];
    const float* W = (const float*)d_in[7];
    const float* hb = (const float*)d_in[8];
    const int* nbf = (const int*)d_in[9];
    const int* nbe = (const int*)d_in[10];
    float* out = (float*)d_out;

    cudaFuncSetAttribute(k_maxgemm, cudaFuncAttributeMaxDynamicSharedMemorySize, SMEM_MG);

    k_split<<<dim3((B_ * N_ * E_) / 1024, 3), 256>>>(ent, fa1, fa2);
    k_hop<<<dim3(B_, 2, R_), E_>>>(rel, W, hb);
    k_cbias<<<(B_ * F_) / 16, 256>>>(rel, arg1, arg2, fr, fa1, fa2, nbf);
    k_maxgemm<<<dim3(N_ / 128, B_, 2 * R_), 512, SMEM_MG>>>(nbe);
    k_topk<<<dim3(B_, R_), 256>>>();
    k_s2<<<dim3(B_, R_, ZSPLIT), 256>>>(ent, fa1, fa2);
    k_final<<<1, 32>>>(out);
}

// round 7
// speedup vs baseline: 3.6195x; 1.2641x over previous
#include <cuda_runtime.h>
#include <cuda_fp16.h>
#include <cstdint>

#define B_ 16
#define N_ 2048
#define F_ 2048
#define E_ 128
#define K_ 10
#define R_ 2
#define ZSPLIT 8

// ---------------- device scratch (static, no runtime allocation) ----------
__device__ float g_h[R_][2][B_][E_];        // hop vectors (h1,h2) per rule
__device__ float g_esq[B_][N_];             // entity squared norms
__device__ float g_cbias[R_][B_][F_];       // hop-1 fact bias
__device__ float g_cb2[R_][B_][F_];         // hop-2 fact bias
__device__ unsigned g_s0key[B_];            // scores_0 ordered-int atomic max
__device__ unsigned g_Lkey[R_][B_][N_];     // hop-1 log scores (ordered-uint)
__device__ int   g_zidx[R_][B_][K_];
__device__ float g_zlog[R_][B_][K_];
__device__ float g_s2part[R_][B_][ZSPLIT][K_];

// fp16 planes: entities split hi/lo, facts truncated hi only
__device__ __half g_ehi[B_ * N_ * E_];
__device__ __half g_elo[B_ * N_ * E_];
__device__ __half g_f1hi[B_ * F_ * E_];
__device__ __half g_f2hi[B_ * F_ * E_];

// ---------------- helpers ---------------------------------------------------
__device__ __forceinline__ float warp_sum(float v) {
#pragma unroll
    for (int o = 16; o > 0; o >>= 1) v += __shfl_xor_sync(0xffffffffu, v, o);
    return v;
}
__device__ __forceinline__ float hsum16(float v) {
#pragma unroll
    for (int o = 8; o > 0; o >>= 1) v += __shfl_xor_sync(0xffffffffu, v, o);
    return v;
}
__device__ __forceinline__ float dot4(float4 a, float4 b) {
    return a.x * b.x + a.y * b.y + a.z * b.z + a.w * b.w;
}
__device__ __forceinline__ unsigned fenc(float v) {
    unsigned u = __float_as_uint(v);
    return (u & 0x80000000u) ? ~u : (u | 0x80000000u);
}
__device__ __forceinline__ float fdec(unsigned k) {
    return (k & 0x80000000u) ? __uint_as_float(k ^ 0x80000000u) : __uint_as_float(~k);
}
__device__ __forceinline__ uint32_t smem_u32(const void* p) {
    uint32_t a;
    asm("{ .reg .u64 t; cvta.to.shared.u64 t, %1; cvt.u32.u64 %0, t; }" : "=r"(a) : "l"(p));
    return a;
}
__device__ __forceinline__ unsigned pack_half2(float a, float b) {
    __half2 h = __halves2half2(__float2half_rn(a), __float2half_rn(b));
    return *(unsigned*)&h;
}

// ---------------- portable tensor-core / async-copy PTX ----------------------
__device__ __forceinline__ void cp16(uint32_t s, const void* g) {
    asm volatile("cp.async.cg.shared.global [%0], [%1], 16;" :: "r"(s), "l"(g));
}
__device__ __forceinline__ void cpcommit() { asm volatile("cp.async.commit_group;"); }
template <int NN>
__device__ __forceinline__ void cpwait() {
    asm volatile("cp.async.wait_group %0;" :: "n"(NN));
}
__device__ __forceinline__ void ldsm4(uint32_t& r0, uint32_t& r1, uint32_t& r2, uint32_t& r3,
                                      uint32_t a) {
    asm volatile("ldmatrix.sync.aligned.m8n8.x4.shared.b16 {%0,%1,%2,%3}, [%4];"
                 : "=r"(r0), "=r"(r1), "=r"(r2), "=r"(r3) : "r"(a));
}
__device__ __forceinline__ void mma16816(float* c, const uint32_t* a, const uint32_t* b) {
    asm volatile(
        "mma.sync.aligned.m16n8k16.row.col.f32.f16.f16.f32 "
        "{%0,%1,%2,%3},{%4,%5,%6,%7},{%8,%9},{%0,%1,%2,%3};"
        : "+f"(c[0]), "+f"(c[1]), "+f"(c[2]), "+f"(c[3])
        : "r"(a[0]), "r"(a[1]), "r"(a[2]), "r"(a[3]), "r"(b[0]), "r"(b[1]));
}
// swizzled tile offset: 128 rows x 128 fp16 (256B rows, 16-byte chunks, XOR swizzle)
__device__ __forceinline__ uint32_t swz(int row, int chunk) {
    return (uint32_t)row * 256u + (uint32_t)((chunk ^ (row & 7)) * 16);
}

// ------ entity fp16 hi/lo split + fused entity norms + g_Lkey init ----------
__global__ void k_split(const float* __restrict__ ent) {
    int tid = threadIdx.x;
    size_t i = ((size_t)blockIdx.x * 256 + tid) * 4;
    float4 v = *(const float4*)(ent + i);
    float h0 = __half2float(__float2half_rn(v.x));
    float h1 = __half2float(__float2half_rn(v.y));
    float h2 = __half2float(__float2half_rn(v.z));
    float h3 = __half2float(__float2half_rn(v.w));
    uint2 uh = {pack_half2(v.x, v.y), pack_half2(v.z, v.w)};
    uint2 ul = {pack_half2(v.x - h0, v.y - h1), pack_half2(v.z - h2, v.w - h3)};
    *(uint2*)(g_ehi + i) = uh;
    *(uint2*)(g_elo + i) = ul;
    float s = warp_sum(dot4(v, v));
    if ((tid & 31) == 0) {
        int gw = blockIdx.x * 8 + (tid >> 5);
        ((float*)g_esq)[gw] = s;
        unsigned init = fenc(-3e30f);
        int b = gw >> 11, n = gw & (N_ - 1);
        g_Lkey[0][b][n] = init;
        g_Lkey[1][b][n] = init;
    }
}

// ---------------- hop vectors + s0key init ----------------------------------
__global__ void k_hop(const float* __restrict__ rel, const float* __restrict__ W,
                      const float* __restrict__ hb) {
    int b = blockIdx.x, h = blockIdx.y, r = blockIdx.z, e = threadIdx.x;
    if (e == 0 && h == 0 && r == 0) g_s0key[b] = fenc(-3e30f);
    const float* w = W + (size_t)((r * 2 + h) * E_) * E_ + e;
    const float* rb = rel + b * E_;
    float s = hb[(r * 2 + h) * E_ + e];
#pragma unroll 8
    for (int i = 0; i < E_; i++) s += rb[i] * w[(size_t)i * E_];
    g_h[r][h][b][e] = s;
}

// -- per-fact biases + fused scores_0 + fused fp16 fact conversion; 2 facts/warp
__global__ void k_cbias(const float* __restrict__ rel, const float* __restrict__ arg1,
                        const float* __restrict__ arg2, const float* __restrict__ fr,
                        const float* __restrict__ fa1, const float* __restrict__ fa2,
                        const int* __restrict__ nbf) {
    int tid = threadIdx.x, lane = tid & 31, hl = lane & 15;
    int fi = ((blockIdx.x * 256 + tid) >> 5) * 2 + (lane >> 4);
    int b = fi >> 11, f = fi & (F_ - 1);
    size_t off = ((size_t)b * F_ + f) * E_ + hl * 8;
    const float4* PR = (const float4*)(fr + off);
    const float4* P1 = (const float4*)(fa1 + off);
    const float4* P2 = (const float4*)(fa2 + off);
    float4 vr0 = PR[0], vr1 = PR[1];
    float4 v10 = P1[0], v11 = P1[1];
    float4 v20 = P2[0], v21 = P2[1];
    // fused fp16 conversion of fact args (truncated hi planes)
    uint4 c1 = {pack_half2(v10.x, v10.y), pack_half2(v10.z, v10.w),
                pack_half2(v11.x, v11.y), pack_half2(v11.z, v11.w)};
    uint4 c2 = {pack_half2(v20.x, v20.y), pack_half2(v20.z, v20.w),
                pack_half2(v21.x, v21.y), pack_half2(v21.z, v21.w)};
    *(uint4*)(g_f1hi + off) = c1;
    *(uint4*)(g_f2hi + off) = c2;
    const float4* Q;
#define LD2(dst0, dst1, base) Q = (const float4*)(base); float4 dst0 = Q[0], dst1 = Q[1];
    LD2(h00a, h00b, &g_h[0][0][b][hl * 8]);
    LD2(h10a, h10b, &g_h[1][0][b][hl * 8]);
    LD2(h01a, h01b, &g_h[0][1][b][hl * 8]);
    LD2(h11a, h11b, &g_h[1][1][b][hl * 8]);
    LD2(qra, qrb, rel + b * E_ + hl * 8);
    LD2(a1a, a1b, arg1 + b * E_ + hl * 8);
    LD2(a2a, a2b, arg2 + b * E_ + hl * 8);
#undef LD2
    float nsum = dot4(vr0, vr0) + dot4(vr1, vr1) + dot4(v10, v10) + dot4(v11, v11) +
                 dot4(v20, v20) + dot4(v21, v21);
    float a1s = dot4(a1a, a1a) + dot4(a1b, a1b);
    float a2s = dot4(a2a, a2a) + dot4(a2b, a2b);
    float p0 = nsum + dot4(h00a, h00a) + dot4(h00b, h00b) + a1s -
               2.f * (dot4(h00a, vr0) + dot4(h00b, vr1) + dot4(a1a, v10) + dot4(a1b, v11));
    float p1 = nsum + dot4(h10a, h10a) + dot4(h10b, h10b) + a1s -
               2.f * (dot4(h10a, vr0) + dot4(h10b, vr1) + dot4(a1a, v20) + dot4(a1b, v21));
    float q0 = nsum + dot4(h01a, h01a) + dot4(h01b, h01b) + a2s -
               2.f * (dot4(h01a, vr0) + dot4(h01b, vr1) + dot4(a2a, v20) + dot4(a2b, v21));
    float q1 = nsum + dot4(h11a, h11a) + dot4(h11b, h11b) + a2s -
               2.f * (dot4(h11a, vr0) + dot4(h11b, vr1) + dot4(a2a, v10) + dot4(a2b, v11));
    float s = nsum + dot4(qra, qra) + dot4(qrb, qrb) + a1s + a2s -
              2.f * (dot4(qra, vr0) + dot4(qrb, vr1) + dot4(a1a, v10) + dot4(a1b, v11) +
                     dot4(a2a, v20) + dot4(a2b, v21));
    p0 = hsum16(p0);
    p1 = hsum16(p1);
    q0 = hsum16(q0);
    q1 = hsum16(q1);
    s = hsum16(s);
    if (hl == 0) {
        bool valid = f < nbf[b];
        g_cbias[0][b][f] = valid ? -0.5f * p0 : -3e30f;
        g_cbias[1][b][f] = valid ? -0.5f * p1 : -3e30f;
        g_cb2[0][b][f] = valid ? -0.5f * q0 : -3e30f;
        g_cb2[1][b][f] = valid ? -0.5f * q1 : -3e30f;
        if (valid) atomicMax(&g_s0key[b], fenc(-0.5f * s));
    }
}

// ------- heavy max-plus GEMM via mma.sync (fp16, split-A / truncated-B) -------
// grid (nt=16, b=16, r*2+fhalf=4); 512 threads / 16 warps, warp tile 32x32
#define OFF_AHI 0
#define OFF_ALO 32768
#define OFF_B0 65536
#define SMEM_MG 131072

__global__ __launch_bounds__(512, 1) void k_maxgemm(const int* __restrict__ nbe) {
    extern __shared__ char smem[];
    uint32_t sb = smem_u32(smem);
    const int tid = threadIdx.x, lane = tid & 31, wid = tid >> 5;
    const int wm = (wid & 3) * 32, wn = (wid >> 2) * 32;
    const int nt = blockIdx.x, b = blockIdx.y;
    const int r = blockIdx.z >> 1, fh = blockIdx.z & 1;

    const __half* ehi = g_ehi + ((size_t)b * N_ + nt * 128) * E_;
    const __half* elo = g_elo + ((size_t)b * N_ + nt * 128) * E_;
    const __half* fhi = ((r == 0) ? g_f2hi : g_f1hi) + (size_t)b * F_ * E_;
    const float* cb = &g_cbias[r][b][0];

    // resident entity tile (hi + lo), swizzled
#pragma unroll
    for (int it = 0; it < 4; ++it) {
        int i = tid + it * 512;
        int row = i >> 4, ch = i & 15;
        uint32_t o = swz(row, ch);
        *(uint4*)(smem + OFF_AHI + o) = *(const uint4*)(ehi + (size_t)row * E_ + ch * 8);
        *(uint4*)(smem + OFF_ALO + o) = *(const uint4*)(elo + (size_t)row * E_ + ch * 8);
    }

    auto issueB = [&](int ft, int buf) {
        uint32_t base = sb + OFF_B0 + buf * 32768;
        const __half* sh = fhi + (size_t)ft * 128 * E_;
#pragma unroll
        for (int it = 0; it < 4; ++it) {
            int i = tid + it * 512;
            int row = i >> 4, ch = i & 15;
            cp16(base + swz(row, ch), sh + (size_t)row * E_ + ch * 8);
        }
    };
    issueB(fh * 8, 0);
    cpcommit();

    float rmax[4];
#pragma unroll
    for (int i = 0; i < 4; i++) rmax[i] = -3e30f;

    for (int t = 0; t < 8; ++t) {
        int ft = fh * 8 + t;
        cpwait<0>();
        __syncthreads();  // buffer t&1 ready; all warps done with the other buffer
        if (t + 1 < 8) {
            issueB(ft + 1, (t + 1) & 1);
            cpcommit();
        }

        float acc[2][4][4];
#pragma unroll
        for (int i = 0; i < 2; i++)
#pragma unroll
            for (int j = 0; j < 4; j++)
#pragma unroll
                for (int q = 0; q < 4; q++) acc[i][j][q] = 0.f;

        uint32_t bbase = sb + OFF_B0 + (t & 1) * 32768;
#pragma unroll
        for (int ks = 0; ks < 8; ++ks) {
            int kc = ks * 2 + (lane >> 4);
            uint32_t ah[2][4], al[2][4];
#pragma unroll
            for (int i = 0; i < 2; i++) {
                int row = wm + i * 16 + (lane & 15);
                uint32_t o = swz(row, kc);
                ldsm4(ah[i][0], ah[i][1], ah[i][2], ah[i][3], sb + OFF_AHI + o);
                ldsm4(al[i][0], al[i][1], al[i][2], al[i][3], sb + OFF_ALO + o);
            }
            uint32_t bh[4][2];
#pragma unroll
            for (int p = 0; p < 2; p++) {
                int row = wn + p * 16 + (lane & 15);
                uint32_t r0, r1, r2, r3;
                ldsm4(r0, r1, r2, r3, bbase + swz(row, kc));
                bh[2 * p][0] = r0; bh[2 * p][1] = r2;
                bh[2 * p + 1][0] = r1; bh[2 * p + 1][1] = r3;
            }
#pragma unroll
            for (int i = 0; i < 2; i++)
#pragma unroll
                for (int j = 0; j < 4; j++) {
                    mma16816(acc[i][j], ah[i], bh[j]);
                    mma16816(acc[i][j], al[i], bh[j]);
                }
        }
        // epilogue: add cbias, fold running row-max
#pragma unroll
        for (int j = 0; j < 4; j++) {
            int col = ft * 128 + wn + j * 8 + 2 * (lane & 3);
            float c0 = __ldg(cb + col), c1 = __ldg(cb + col + 1);
#pragma unroll
            for (int i = 0; i < 2; i++) {
                rmax[2 * i] = fmaxf(rmax[2 * i], fmaxf(acc[i][j][0] + c0, acc[i][j][1] + c1));
                rmax[2 * i + 1] = fmaxf(rmax[2 * i + 1],
                                        fmaxf(acc[i][j][2] + c0, acc[i][j][3] + c1));
            }
        }
    }

    // cross-thread row-max reduction (reuse smem)
    __syncthreads();
    float* Red = (float*)smem;
#pragma unroll
    for (int i = 0; i < 2; i++)
#pragma unroll
        for (int h = 0; h < 2; h++) {
            int row = wm + i * 16 + h * 8 + (lane >> 2);
            Red[row * 16 + (wid >> 2) * 4 + (lane & 3)] = rmax[2 * i + h];
        }
    __syncthreads();
    if (tid < 128) {
        float m = -3e30f;
#pragma unroll
        for (int t = 0; t < 16; t++) m = fmaxf(m, Red[tid * 16 + t]);
        int gn = nt * 128 + tid;
        float Lv = m - 0.5f * g_esq[b][gn];
        if (gn < nbe[b]) atomicMax(&g_Lkey[r][b][gn], fenc(Lv));
    }
}

// ---------------- top-K over N per (r,b): shuffle-based -----------------------
__global__ void k_topk() {
    int b = blockIdx.x, r = blockIdx.y, tid = threadIdx.x;
    int lane = tid & 31, wid = tid >> 5;
    float v[8];
#pragma unroll
    for (int j = 0; j < 8; j++) v[j] = fdec(g_Lkey[r][b][tid + 256 * j]);
    __shared__ float swv[8];
    __shared__ int swi[8];
    __shared__ int schosen;
    for (int kk = 0; kk < K_; kk++) {
        float bv = -3.4e38f;
        int bi = 0;
#pragma unroll
        for (int j = 0; j < 8; j++)
            if (v[j] > bv) { bv = v[j]; bi = tid + 256 * j; }
#pragma unroll
        for (int o = 16; o > 0; o >>= 1) {
            float ov = __shfl_xor_sync(0xffffffffu, bv, o);
            int oi = __shfl_xor_sync(0xffffffffu, bi, o);
            if (ov > bv || (ov == bv && oi < bi)) { bv = ov; bi = oi; }
        }
        if (lane == 0) { swv[wid] = bv; swi[wid] = bi; }
        __syncthreads();
        if (wid == 0) {
            float bv2 = (lane < 8) ? swv[lane] : -3.4e38f;
            int bi2 = (lane < 8) ? swi[lane] : 0;
#pragma unroll
            for (int o = 4; o > 0; o >>= 1) {
                float ov = __shfl_xor_sync(0xffffffffu, bv2, o);
                int oi = __shfl_xor_sync(0xffffffffu, bi2, o);
                if (ov > bv2 || (ov == bv2 && oi < bi2)) { bv2 = ov; bi2 = oi; }
            }
            if (lane == 0) {
                g_zidx[r][b][kk] = bi2;
                g_zlog[r][b][kk] = bv2;
                schosen = bi2;
            }
        }
        __syncthreads();
        int ch = schosen;
        if ((ch & 255) == tid) v[ch >> 8] = -3.4e38f;
        __syncthreads();
    }
}

// ---------------- hop-2 rescoring: max-plus over facts (split 8-way) ---------
__global__ void k_s2(const float* __restrict__ ent, const float* __restrict__ fa1,
                     const float* __restrict__ fa2) {
    int b = blockIdx.x, r = blockIdx.y, z = blockIdx.z, tid = threadIdx.x;
    int lane = tid & 31, wid = tid >> 5;
    __shared__ float zs[K_][E_];
    __shared__ float red[K_][257];
    for (int i = tid; i < K_ * E_; i += 256) {
        int k = i >> 7, e = i & 127;
        zs[k][e] = ent[((size_t)b * N_ + g_zidx[r][b][k]) * E_ + e];
    }
    __syncthreads();
    const float* fy = ((r == 0) ? fa1 : fa2) + (size_t)b * F_ * E_;
    int f = z * 256 + tid;
    float c = g_cb2[r][b][f];
    const float4* row = (const float4*)(fy + (size_t)f * E_);
    float d[K_];
#pragma unroll
    for (int k = 0; k < K_; k++) d[k] = 0.f;
#pragma unroll 4
    for (int e4 = 0; e4 < 32; e4++) {
        float4 v = row[e4];
#pragma unroll
        for (int k = 0; k < K_; k++) {
            float4 zz = ((const float4*)zs[k])[e4];
            d[k] += v.x * zz.x + v.y * zz.y + v.z * zz.z + v.w * zz.w;
        }
    }
#pragma unroll
    for (int k = 0; k < K_; k++) red[k][tid] = d[k] + c;
    __syncthreads();
    for (int k = wid; k < K_; k += 8) {
        float m = -3e30f;
        for (int j = lane; j < 256; j += 32) m = fmaxf(m, red[k][j]);
#pragma unroll
        for (int o = 16; o > 0; o >>= 1) m = fmaxf(m, __shfl_xor_sync(0xffffffffu, m, o));
        if (lane == 0) g_s2part[r][b][z][k] = m;
    }
}

// ---------------- final combine ----------------------------------------------
__global__ void k_final(float* __restrict__ out) {
    int b = threadIdx.x;
    if (b >= B_) return;
    float res = expf(fdec(g_s0key[b]));
#pragma unroll
    for (int r = 0; r < R_; r++)
#pragma unroll
        for (int k = 0; k < K_; k++) {
            float m = -3e30f;
            for (int z = 0; z < ZSPLIT; z++) m = fmaxf(m, g_s2part[r][b][z][k]);
            float s2 = m - 0.5f * g_esq[b][g_zidx[r][b][k]];
            res = fmaxf(res, expf(fminf(s2, g_zlog[r][b][k])));
        }
    out[b] = res;
}

// ---------------- launch -------------------------------------------------------
extern "C" void kernel_launch(void* const* d_in, const int* in_sizes, int n_in,
                              void* d_out, int out_size) {
    (void)in_sizes; (void)n_in; (void)out_size;
    const float* rel = (const float*)d_in[0];
    const float* arg1 = (const float*)d_in[1];
    const float* arg2 = (const float*)d_in[2];
    const float* fr = (const float*)d_in[3];
    const float* fa1 = (const float*)d_in[4];
    const float* fa2 = (const float*)d_in[5];
    const float* ent = (const float*)d_in[6];
    const float* W = (const float*)d_in[7];
    const float* hb = (const float*)d_in[8];
    const int* nbf = (const int*)d_in[9];
    const int* nbe = (const int*)d_in[10];
    float* out = (float*)d_out;

    cudaFuncSetAttribute(k_maxgemm, cudaFuncAttributeMaxDynamicSharedMemorySize, SMEM_MG);

    k_split<<<(B_ * N_ * E_) / 1024, 256>>>(ent);
    k_hop<<<dim3(B_, 2, R_), E_>>>(rel, W, hb);
    k_cbias<<<(B_ * F_) / 16, 256>>>(rel, arg1, arg2, fr, fa1, fa2, nbf);
    k_maxgemm<<<dim3(N_ / 128, B_, 2 * R_), 512, SMEM_MG>>>(nbe);
    k_topk<<<dim3(B_, R_), 256>>>();
    k_s2<<<dim3(B_, R_, ZSPLIT), 256>>>(ent, fa1, fa2);
    k_final<<<1, 32>>>(out);
}

// round 8
// speedup vs baseline: 3.8511x; 1.0640x over previous
#include <cuda_runtime.h>
#include <cuda_fp16.h>
#include <cstdint>

#define B_ 16
#define N_ 2048
#define F_ 2048
#define E_ 128
#define K_ 10
#define R_ 2
#define ZSPLIT 8

// ---------------- device scratch (static, no runtime allocation) ----------
__device__ float g_h[R_][2][B_][E_];        // hop vectors (h1,h2) per rule
__device__ float g_esq[B_][N_];             // entity squared norms
__device__ float g_cbias[R_][B_][F_];       // hop-1 fact bias
__device__ float g_cb2[R_][B_][F_];         // hop-2 fact bias
__device__ unsigned g_s0key[B_];            // scores_0 ordered-int atomic max
__device__ unsigned g_Lkey[R_][B_][N_];     // hop-1 log scores (ordered-uint)
__device__ int   g_zidx[R_][B_][K_];
__device__ float g_zlog[R_][B_][K_];
__device__ float g_s2part[R_][B_][ZSPLIT][K_];

// fp16 planes: entities split hi/lo, facts truncated hi only
__device__ __half g_ehi[B_ * N_ * E_];
__device__ __half g_elo[B_ * N_ * E_];
__device__ __half g_f1hi[B_ * F_ * E_];
__device__ __half g_f2hi[B_ * F_ * E_];

// ---------------- helpers ---------------------------------------------------
__device__ __forceinline__ float warp_sum(float v) {
#pragma unroll
    for (int o = 16; o > 0; o >>= 1) v += __shfl_xor_sync(0xffffffffu, v, o);
    return v;
}
__device__ __forceinline__ float hsum16(float v) {
#pragma unroll
    for (int o = 8; o > 0; o >>= 1) v += __shfl_xor_sync(0xffffffffu, v, o);
    return v;
}
__device__ __forceinline__ float dot4(float4 a, float4 b) {
    return a.x * b.x + a.y * b.y + a.z * b.z + a.w * b.w;
}
__device__ __forceinline__ unsigned fenc(float v) {
    unsigned u = __float_as_uint(v);
    return (u & 0x80000000u) ? ~u : (u | 0x80000000u);
}
__device__ __forceinline__ float fdec(unsigned k) {
    return (k & 0x80000000u) ? __uint_as_float(k ^ 0x80000000u) : __uint_as_float(~k);
}
__device__ __forceinline__ uint32_t smem_u32(const void* p) {
    uint32_t a;
    asm("{ .reg .u64 t; cvta.to.shared.u64 t, %1; cvt.u32.u64 %0, t; }" : "=r"(a) : "l"(p));
    return a;
}
__device__ __forceinline__ unsigned pack_half2(float a, float b) {
    __half2 h = __halves2half2(__float2half_rn(a), __float2half_rn(b));
    return *(unsigned*)&h;
}

// ---------------- portable tensor-core / async-copy PTX ----------------------
__device__ __forceinline__ void cp16(uint32_t s, const void* g) {
    asm volatile("cp.async.cg.shared.global [%0], [%1], 16;" :: "r"(s), "l"(g));
}
__device__ __forceinline__ void cpcommit() { asm volatile("cp.async.commit_group;"); }
template <int NN>
__device__ __forceinline__ void cpwait() {
    asm volatile("cp.async.wait_group %0;" :: "n"(NN));
}
__device__ __forceinline__ void ldsm4(uint32_t& r0, uint32_t& r1, uint32_t& r2, uint32_t& r3,
                                      uint32_t a) {
    asm volatile("ldmatrix.sync.aligned.m8n8.x4.shared.b16 {%0,%1,%2,%3}, [%4];"
                 : "=r"(r0), "=r"(r1), "=r"(r2), "=r"(r3) : "r"(a));
}
__device__ __forceinline__ void mma16816(float* c, const uint32_t* a, const uint32_t* b) {
    asm volatile(
        "mma.sync.aligned.m16n8k16.row.col.f32.f16.f16.f32 "
        "{%0,%1,%2,%3},{%4,%5,%6,%7},{%8,%9},{%0,%1,%2,%3};"
        : "+f"(c[0]), "+f"(c[1]), "+f"(c[2]), "+f"(c[3])
        : "r"(a[0]), "r"(a[1]), "r"(a[2]), "r"(a[3]), "r"(b[0]), "r"(b[1]));
}
// swizzled tile offset: rows x 128 fp16 (256B rows, 16-byte chunks, XOR swizzle)
__device__ __forceinline__ uint32_t swz(int row, int chunk) {
    return (uint32_t)row * 256u + (uint32_t)((chunk ^ (row & 7)) * 16);
}

// ------ entity fp16 hi/lo split + fused entity norms + g_Lkey init ----------
__global__ void k_split(const float* __restrict__ ent) {
    int tid = threadIdx.x;
    size_t i = ((size_t)blockIdx.x * 256 + tid) * 4;
    float4 v = *(const float4*)(ent + i);
    float h0 = __half2float(__float2half_rn(v.x));
    float h1 = __half2float(__float2half_rn(v.y));
    float h2 = __half2float(__float2half_rn(v.z));
    float h3 = __half2float(__float2half_rn(v.w));
    uint2 uh = {pack_half2(v.x, v.y), pack_half2(v.z, v.w)};
    uint2 ul = {pack_half2(v.x - h0, v.y - h1), pack_half2(v.z - h2, v.w - h3)};
    *(uint2*)(g_ehi + i) = uh;
    *(uint2*)(g_elo + i) = ul;
    float s = warp_sum(dot4(v, v));
    if ((tid & 31) == 0) {
        int gw = blockIdx.x * 8 + (tid >> 5);
        ((float*)g_esq)[gw] = s;
        unsigned init = fenc(-3e30f);
        int b = gw >> 11, n = gw & (N_ - 1);
        g_Lkey[0][b][n] = init;
        g_Lkey[1][b][n] = init;
    }
}

// ---------------- hop vectors + s0key init ----------------------------------
__global__ void k_hop(const float* __restrict__ rel, const float* __restrict__ W,
                      const float* __restrict__ hb) {
    int b = blockIdx.x, h = blockIdx.y, r = blockIdx.z, e = threadIdx.x;
    if (e == 0 && h == 0 && r == 0) g_s0key[b] = fenc(-3e30f);
    const float* w = W + (size_t)((r * 2 + h) * E_) * E_ + e;
    const float* rb = rel + b * E_;
    float s = hb[(r * 2 + h) * E_ + e];
#pragma unroll 8
    for (int i = 0; i < E_; i++) s += rb[i] * w[(size_t)i * E_];
    g_h[r][h][b][e] = s;
}

// -- per-fact biases + fused scores_0 + fused fp16 fact conversion; 2 facts/warp
__global__ void k_cbias(const float* __restrict__ rel, const float* __restrict__ arg1,
                        const float* __restrict__ arg2, const float* __restrict__ fr,
                        const float* __restrict__ fa1, const float* __restrict__ fa2,
                        const int* __restrict__ nbf) {
    int tid = threadIdx.x, lane = tid & 31, hl = lane & 15;
    int fi = ((blockIdx.x * 256 + tid) >> 5) * 2 + (lane >> 4);
    int b = fi >> 11, f = fi & (F_ - 1);
    size_t off = ((size_t)b * F_ + f) * E_ + hl * 8;
    const float4* PR = (const float4*)(fr + off);
    const float4* P1 = (const float4*)(fa1 + off);
    const float4* P2 = (const float4*)(fa2 + off);
    float4 vr0 = PR[0], vr1 = PR[1];
    float4 v10 = P1[0], v11 = P1[1];
    float4 v20 = P2[0], v21 = P2[1];
    uint4 c1 = {pack_half2(v10.x, v10.y), pack_half2(v10.z, v10.w),
                pack_half2(v11.x, v11.y), pack_half2(v11.z, v11.w)};
    uint4 c2 = {pack_half2(v20.x, v20.y), pack_half2(v20.z, v20.w),
                pack_half2(v21.x, v21.y), pack_half2(v21.z, v21.w)};
    *(uint4*)(g_f1hi + off) = c1;
    *(uint4*)(g_f2hi + off) = c2;
    const float4* Q;
#define LD2(dst0, dst1, base) Q = (const float4*)(base); float4 dst0 = Q[0], dst1 = Q[1];
    LD2(h00a, h00b, &g_h[0][0][b][hl * 8]);
    LD2(h10a, h10b, &g_h[1][0][b][hl * 8]);
    LD2(h01a, h01b, &g_h[0][1][b][hl * 8]);
    LD2(h11a, h11b, &g_h[1][1][b][hl * 8]);
    LD2(qra, qrb, rel + b * E_ + hl * 8);
    LD2(a1a, a1b, arg1 + b * E_ + hl * 8);
    LD2(a2a, a2b, arg2 + b * E_ + hl * 8);
#undef LD2
    float nsum = dot4(vr0, vr0) + dot4(vr1, vr1) + dot4(v10, v10) + dot4(v11, v11) +
                 dot4(v20, v20) + dot4(v21, v21);
    float a1s = dot4(a1a, a1a) + dot4(a1b, a1b);
    float a2s = dot4(a2a, a2a) + dot4(a2b, a2b);
    float p0 = nsum + dot4(h00a, h00a) + dot4(h00b, h00b) + a1s -
               2.f * (dot4(h00a, vr0) + dot4(h00b, vr1) + dot4(a1a, v10) + dot4(a1b, v11));
    float p1 = nsum + dot4(h10a, h10a) + dot4(h10b, h10b) + a1s -
               2.f * (dot4(h10a, vr0) + dot4(h10b, vr1) + dot4(a1a, v20) + dot4(a1b, v21));
    float q0 = nsum + dot4(h01a, h01a) + dot4(h01b, h01b) + a2s -
               2.f * (dot4(h01a, vr0) + dot4(h01b, vr1) + dot4(a2a, v20) + dot4(a2b, v21));
    float q1 = nsum + dot4(h11a, h11a) + dot4(h11b, h11b) + a2s -
               2.f * (dot4(h11a, vr0) + dot4(h11b, vr1) + dot4(a2a, v10) + dot4(a2b, v11));
    float s = nsum + dot4(qra, qra) + dot4(qrb, qrb) + a1s + a2s -
              2.f * (dot4(qra, vr0) + dot4(qrb, vr1) + dot4(a1a, v10) + dot4(a1b, v11) +
                     dot4(a2a, v20) + dot4(a2b, v21));
    p0 = hsum16(p0);
    p1 = hsum16(p1);
    q0 = hsum16(q0);
    q1 = hsum16(q1);
    s = hsum16(s);
    if (hl == 0) {
        bool valid = f < nbf[b];
        g_cbias[0][b][f] = valid ? -0.5f * p0 : -3e30f;
        g_cbias[1][b][f] = valid ? -0.5f * p1 : -3e30f;
        g_cb2[0][b][f] = valid ? -0.5f * q0 : -3e30f;
        g_cb2[1][b][f] = valid ? -0.5f * q1 : -3e30f;
        if (valid) atomicMax(&g_s0key[b], fenc(-0.5f * s));
    }
}

// ------- heavy max-plus GEMM via mma.sync (fp16, split-A / truncated-B) -------
// grid (nt=32, b=16, r*2+fhalf=4); 256 threads / 8 warps, CTA tile 64x128,
// warp tile 32x32, smem 96KB -> 2 CTAs/SM
#define OFF_AHI 0
#define OFF_ALO 16384
#define OFF_B0 32768
#define SMEM_MG 98304

__global__ __launch_bounds__(256, 2) void k_maxgemm(const int* __restrict__ nbe) {
    extern __shared__ char smem[];
    uint32_t sb = smem_u32(smem);
    const int tid = threadIdx.x, lane = tid & 31, wid = tid >> 5;
    const int wm = (wid & 1) * 32, wn = (wid >> 1) * 32;
    const int nt = blockIdx.x, b = blockIdx.y;
    const int r = blockIdx.z >> 1, fh = blockIdx.z & 1;

    const __half* ehi = g_ehi + ((size_t)b * N_ + nt * 64) * E_;
    const __half* elo = g_elo + ((size_t)b * N_ + nt * 64) * E_;
    const __half* fhi = ((r == 0) ? g_f2hi : g_f1hi) + (size_t)b * F_ * E_;
    const float* cb = &g_cbias[r][b][0];

    // resident entity tile (64 rows, hi + lo), swizzled
#pragma unroll
    for (int it = 0; it < 4; ++it) {
        int i = tid + it * 256;
        int row = i >> 4, ch = i & 15;
        uint32_t o = swz(row, ch);
        *(uint4*)(smem + OFF_AHI + o) = *(const uint4*)(ehi + (size_t)row * E_ + ch * 8);
        *(uint4*)(smem + OFF_ALO + o) = *(const uint4*)(elo + (size_t)row * E_ + ch * 8);
    }

    auto issueB = [&](int ft, int buf) {
        uint32_t base = sb + OFF_B0 + buf * 32768;
        const __half* sh = fhi + (size_t)ft * 128 * E_;
#pragma unroll
        for (int it = 0; it < 8; ++it) {
            int i = tid + it * 256;
            int row = i >> 4, ch = i & 15;
            cp16(base + swz(row, ch), sh + (size_t)row * E_ + ch * 8);
        }
    };
    issueB(fh * 8, 0);
    cpcommit();

    float rmax[4];
#pragma unroll
    for (int i = 0; i < 4; i++) rmax[i] = -3e30f;

    for (int t = 0; t < 8; ++t) {
        int ft = fh * 8 + t;
        // prefetch this tile's cbias into registers (hides L2 latency under MMA)
        float creg[8];
#pragma unroll
        for (int j = 0; j < 4; j++) {
            int col = ft * 128 + wn + j * 8 + 2 * (lane & 3);
            creg[2 * j] = __ldg(cb + col);
            creg[2 * j + 1] = __ldg(cb + col + 1);
        }
        cpwait<0>();
        __syncthreads();  // buffer t&1 ready; all warps done with the other buffer
        if (t + 1 < 8) {
            issueB(ft + 1, (t + 1) & 1);
            cpcommit();
        }

        float acc[2][4][4];
#pragma unroll
        for (int i = 0; i < 2; i++)
#pragma unroll
            for (int j = 0; j < 4; j++)
#pragma unroll
                for (int q = 0; q < 4; q++) acc[i][j][q] = 0.f;

        uint32_t bbase = sb + OFF_B0 + (t & 1) * 32768;
#pragma unroll
        for (int ks = 0; ks < 8; ++ks) {
            int kc = ks * 2 + (lane >> 4);
            uint32_t ah[2][4], al[2][4];
#pragma unroll
            for (int i = 0; i < 2; i++) {
                int row = wm + i * 16 + (lane & 15);
                uint32_t o = swz(row, kc);
                ldsm4(ah[i][0], ah[i][1], ah[i][2], ah[i][3], sb + OFF_AHI + o);
                ldsm4(al[i][0], al[i][1], al[i][2], al[i][3], sb + OFF_ALO + o);
            }
            uint32_t bh[4][2];
#pragma unroll
            for (int p = 0; p < 2; p++) {
                int row = wn + p * 16 + (lane & 15);
                uint32_t r0, r1, r2, r3;
                ldsm4(r0, r1, r2, r3, bbase + swz(row, kc));
                bh[2 * p][0] = r0; bh[2 * p][1] = r2;
                bh[2 * p + 1][0] = r1; bh[2 * p + 1][1] = r3;
            }
#pragma unroll
            for (int i = 0; i < 2; i++)
#pragma unroll
                for (int j = 0; j < 4; j++) {
                    mma16816(acc[i][j], ah[i], bh[j]);
                    mma16816(acc[i][j], al[i], bh[j]);
                }
        }
        // epilogue: add cbias (registers), fold running row-max
#pragma unroll
        for (int j = 0; j < 4; j++) {
            float c0 = creg[2 * j], c1 = creg[2 * j + 1];
#pragma unroll
            for (int i = 0; i < 2; i++) {
                rmax[2 * i] = fmaxf(rmax[2 * i], fmaxf(acc[i][j][0] + c0, acc[i][j][1] + c1));
                rmax[2 * i + 1] = fmaxf(rmax[2 * i + 1],
                                        fmaxf(acc[i][j][2] + c0, acc[i][j][3] + c1));
            }
        }
    }

    // cross-thread row-max reduction (reuse smem)
    __syncthreads();
    float* Red = (float*)smem;
#pragma unroll
    for (int i = 0; i < 2; i++)
#pragma unroll
        for (int h = 0; h < 2; h++) {
            int row = wm + i * 16 + h * 8 + (lane >> 2);
            Red[row * 16 + (wid >> 1) * 4 + (lane & 3)] = rmax[2 * i + h];
        }
    __syncthreads();
    if (tid < 64) {
        float m = -3e30f;
#pragma unroll
        for (int t = 0; t < 16; t++) m = fmaxf(m, Red[tid * 16 + t]);
        int gn = nt * 64 + tid;
        float Lv = m - 0.5f * g_esq[b][gn];
        if (gn < nbe[b]) atomicMax(&g_Lkey[r][b][gn], fenc(Lv));
    }
}

// ---------------- top-K over N per (r,b): shuffle-based -----------------------
__global__ void k_topk() {
    int b = blockIdx.x, r = blockIdx.y, tid = threadIdx.x;
    int lane = tid & 31, wid = tid >> 5;
    float v[8];
#pragma unroll
    for (int j = 0; j < 8; j++) v[j] = fdec(g_Lkey[r][b][tid + 256 * j]);
    __shared__ float swv[8];
    __shared__ int swi[8];
    __shared__ int schosen;
    for (int kk = 0; kk < K_; kk++) {
        float bv = -3.4e38f;
        int bi = 0;
#pragma unroll
        for (int j = 0; j < 8; j++)
            if (v[j] > bv) { bv = v[j]; bi = tid + 256 * j; }
#pragma unroll
        for (int o = 16; o > 0; o >>= 1) {
            float ov = __shfl_xor_sync(0xffffffffu, bv, o);
            int oi = __shfl_xor_sync(0xffffffffu, bi, o);
            if (ov > bv || (ov == bv && oi < bi)) { bv = ov; bi = oi; }
        }
        if (lane == 0) { swv[wid] = bv; swi[wid] = bi; }
        __syncthreads();
        if (wid == 0) {
            float bv2 = (lane < 8) ? swv[lane] : -3.4e38f;
            int bi2 = (lane < 8) ? swi[lane] : 0;
#pragma unroll
            for (int o = 4; o > 0; o >>= 1) {
                float ov = __shfl_xor_sync(0xffffffffu, bv2, o);
                int oi = __shfl_xor_sync(0xffffffffu, bi2, o);
                if (ov > bv2 || (ov == bv2 && oi < bi2)) { bv2 = ov; bi2 = oi; }
            }
            if (lane == 0) {
                g_zidx[r][b][kk] = bi2;
                g_zlog[r][b][kk] = bv2;
                schosen = bi2;
            }
        }
        __syncthreads();
        int ch = schosen;
        if ((ch & 255) == tid) v[ch >> 8] = -3.4e38f;
        __syncthreads();
    }
}

// ---------------- hop-2 rescoring: max-plus over facts (split 8-way) ---------
__global__ void k_s2(const float* __restrict__ ent, const float* __restrict__ fa1,
                     const float* __restrict__ fa2) {
    int b = blockIdx.x, r = blockIdx.y, z = blockIdx.z, tid = threadIdx.x;
    int lane = tid & 31, wid = tid >> 5;
    __shared__ float zs[K_][E_];
    __shared__ float red[K_][257];
    for (int i = tid; i < K_ * E_; i += 256) {
        int k = i >> 7, e = i & 127;
        zs[k][e] = ent[((size_t)b * N_ + g_zidx[r][b][k]) * E_ + e];
    }
    __syncthreads();
    const float* fy = ((r == 0) ? fa1 : fa2) + (size_t)b * F_ * E_;
    int f = z * 256 + tid;
    float c = g_cb2[r][b][f];
    const float4* row = (const float4*)(fy + (size_t)f * E_);
    float d[K_];
#pragma unroll
    for (int k = 0; k < K_; k++) d[k] = 0.f;
#pragma unroll 4
    for (int e4 = 0; e4 < 32; e4++) {
        float4 v = row[e4];
#pragma unroll
        for (int k = 0; k < K_; k++) {
            float4 zz = ((const float4*)zs[k])[e4];
            d[k] += v.x * zz.x + v.y * zz.y + v.z * zz.z + v.w * zz.w;
        }
    }
#pragma unroll
    for (int k = 0; k < K_; k++) red[k][tid] = d[k] + c;
    __syncthreads();
    for (int k = wid; k < K_; k += 8) {
        float m = -3e30f;
        for (int j = lane; j < 256; j += 32) m = fmaxf(m, red[k][j]);
#pragma unroll
        for (int o = 16; o > 0; o >>= 1) m = fmaxf(m, __shfl_xor_sync(0xffffffffu, m, o));
        if (lane == 0) g_s2part[r][b][z][k] = m;
    }
}

// ---------------- final combine ----------------------------------------------
__global__ void k_final(float* __restrict__ out) {
    int b = threadIdx.x;
    if (b >= B_) return;
    float res = expf(fdec(g_s0key[b]));
#pragma unroll
    for (int r = 0; r < R_; r++)
#pragma unroll
        for (int k = 0; k < K_; k++) {
            float m = -3e30f;
            for (int z = 0; z < ZSPLIT; z++) m = fmaxf(m, g_s2part[r][b][z][k]);
            float s2 = m - 0.5f * g_esq[b][g_zidx[r][b][k]];
            res = fmaxf(res, expf(fminf(s2, g_zlog[r][b][k])));
        }
    out[b] = res;
}

// ---------------- launch -------------------------------------------------------
extern "C" void kernel_launch(void* const* d_in, const int* in_sizes, int n_in,
                              void* d_out, int out_size) {
    (void)in_sizes; (void)n_in; (void)out_size;
    const float* rel = (const float*)d_in[0];
    const float* arg1 = (const float*)d_in[1];
    const float* arg2 = (const float*)d_in[2];
    const float* fr = (const float*)d_in[3];
    const float* fa1 = (const float*)d_in[4];
    const float* fa2 = (const float*)d_in[5];
    const float* ent = (const float*)d_in[6];
    const float* W = (const float*)d_in[7];
    const float* hb = (const float*)d_in[8];
    const int* nbf = (const int*)d_in[9];
    const int* nbe = (const int*)d_in[10];
    float* out = (float*)d_out;

    cudaFuncSetAttribute(k_maxgemm, cudaFuncAttributeMaxDynamicSharedMemorySize, SMEM_MG);

    k_split<<<(B_ * N_ * E_) / 1024, 256>>>(ent);
    k_hop<<<dim3(B_, 2, R_), E_>>>(rel, W, hb);
    k_cbias<<<(B_ * F_) / 16, 256>>>(rel, arg1, arg2, fr, fa1, fa2, nbf);
    k_maxgemm<<<dim3(N_ / 64, B_, 2 * R_), 256, SMEM_MG>>>(nbe);
    k_topk<<<dim3(B_, R_), 256>>>();
    k_s2<<<dim3(B_, R_, ZSPLIT), 256>>>(ent, fa1, fa2);
    k_final<<<1, 32>>>(out);
}

// round 9
// speedup vs baseline: 5.4431x; 1.4134x over previous
#include <cuda_runtime.h>
#include <cuda_fp16.h>
#include <cstdint>

#define B_ 16
#define N_ 2048
#define F_ 2048
#define E_ 128
#define K_ 10
#define R_ 2
#define ZSPLIT 8

// ---------------- device scratch (static, no runtime allocation) ----------
__device__ float g_h[R_][2][B_][E_];        // hop vectors (h1,h2) per rule
__device__ float g_esq[B_][N_];             // entity squared norms
__device__ float g_cbias[R_][B_][F_];       // hop-1 fact bias
__device__ float g_cb2[R_][B_][F_];         // hop-2 fact bias
__device__ unsigned g_s0key[B_];            // scores_0 ordered-int atomic max
__device__ unsigned g_Lkey[R_][B_][N_];     // hop-1 log scores (ordered-uint)
__device__ int   g_zidx[R_][B_][K_];
__device__ float g_zlog[R_][B_][K_];
__device__ float g_s2part[R_][B_][ZSPLIT][K_];

// fp16 planes (truncated round-to-nearest)
__device__ __half g_ehi[B_ * N_ * E_];
__device__ __half g_f1hi[B_ * F_ * E_];
__device__ __half g_f2hi[B_ * F_ * E_];

// ---------------- helpers ---------------------------------------------------
__device__ __forceinline__ float warp_sum(float v) {
#pragma unroll
    for (int o = 16; o > 0; o >>= 1) v += __shfl_xor_sync(0xffffffffu, v, o);
    return v;
}
__device__ __forceinline__ float hsum16(float v) {
#pragma unroll
    for (int o = 8; o > 0; o >>= 1) v += __shfl_xor_sync(0xffffffffu, v, o);
    return v;
}
__device__ __forceinline__ float dot4(float4 a, float4 b) {
    return a.x * b.x + a.y * b.y + a.z * b.z + a.w * b.w;
}
__device__ __forceinline__ unsigned fenc(float v) {
    unsigned u = __float_as_uint(v);
    return (u & 0x80000000u) ? ~u : (u | 0x80000000u);
}
__device__ __forceinline__ float fdec(unsigned k) {
    return (k & 0x80000000u) ? __uint_as_float(k ^ 0x80000000u) : __uint_as_float(~k);
}
__device__ __forceinline__ uint32_t smem_u32(const void* p) {
    uint32_t a;
    asm("{ .reg .u64 t; cvta.to.shared.u64 t, %1; cvt.u32.u64 %0, t; }" : "=r"(a) : "l"(p));
    return a;
}
__device__ __forceinline__ unsigned pack_half2(float a, float b) {
    __half2 h = __halves2half2(__float2half_rn(a), __float2half_rn(b));
    return *(unsigned*)&h;
}

// ---------------- portable tensor-core / async-copy PTX ----------------------
__device__ __forceinline__ void cp16(uint32_t s, const void* g) {
    asm volatile("cp.async.cg.shared.global [%0], [%1], 16;" :: "r"(s), "l"(g));
}
__device__ __forceinline__ void cpcommit() { asm volatile("cp.async.commit_group;"); }
template <int NN>
__device__ __forceinline__ void cpwait() {
    asm volatile("cp.async.wait_group %0;" :: "n"(NN));
}
__device__ __forceinline__ void ldsm4(uint32_t& r0, uint32_t& r1, uint32_t& r2, uint32_t& r3,
                                      uint32_t a) {
    asm volatile("ldmatrix.sync.aligned.m8n8.x4.shared.b16 {%0,%1,%2,%3}, [%4];"
                 : "=r"(r0), "=r"(r1), "=r"(r2), "=r"(r3) : "r"(a));
}
__device__ __forceinline__ void mma16816(float* c, const uint32_t* a, const uint32_t* b) {
    asm volatile(
        "mma.sync.aligned.m16n8k16.row.col.f32.f16.f16.f32 "
        "{%0,%1,%2,%3},{%4,%5,%6,%7},{%8,%9},{%0,%1,%2,%3};"
        : "+f"(c[0]), "+f"(c[1]), "+f"(c[2]), "+f"(c[3])
        : "r"(a[0]), "r"(a[1]), "r"(a[2]), "r"(a[3]), "r"(b[0]), "r"(b[1]));
}
// swizzled tile offset: rows x 128 fp16 (256B rows, 16-byte chunks, XOR swizzle)
__device__ __forceinline__ uint32_t swz(int row, int chunk) {
    return (uint32_t)row * 256u + (uint32_t)((chunk ^ (row & 7)) * 16);
}

// ------ entity fp16 conversion + fused entity norms + g_Lkey init -----------
__global__ void k_split(const float* __restrict__ ent) {
    int tid = threadIdx.x;
    size_t i = ((size_t)blockIdx.x * 256 + tid) * 4;
    float4 v = *(const float4*)(ent + i);
    uint2 uh = {pack_half2(v.x, v.y), pack_half2(v.z, v.w)};
    *(uint2*)(g_ehi + i) = uh;
    float s = warp_sum(dot4(v, v));
    if ((tid & 31) == 0) {
        int gw = blockIdx.x * 8 + (tid >> 5);
        ((float*)g_esq)[gw] = s;
        unsigned init = fenc(-3e30f);
        int b = gw >> 11, n = gw & (N_ - 1);
        g_Lkey[0][b][n] = init;
        g_Lkey[1][b][n] = init;
    }
}

// ---------------- hop vectors + s0key init ----------------------------------
__global__ void k_hop(const float* __restrict__ rel, const float* __restrict__ W,
                      const float* __restrict__ hb) {
    int b = blockIdx.x, h = blockIdx.y, r = blockIdx.z, e = threadIdx.x;
    if (e == 0 && h == 0 && r == 0) g_s0key[b] = fenc(-3e30f);
    const float* w = W + (size_t)((r * 2 + h) * E_) * E_ + e;
    const float* rb = rel + b * E_;
    float s = hb[(r * 2 + h) * E_ + e];
#pragma unroll 8
    for (int i = 0; i < E_; i++) s += rb[i] * w[(size_t)i * E_];
    g_h[r][h][b][e] = s;
}

// -- per-fact biases + fused scores_0 + fused fp16 fact conversion; 2 facts/warp
__global__ void k_cbias(const float* __restrict__ rel, const float* __restrict__ arg1,
                        const float* __restrict__ arg2, const float* __restrict__ fr,
                        const float* __restrict__ fa1, const float* __restrict__ fa2,
                        const int* __restrict__ nbf) {
    int tid = threadIdx.x, lane = tid & 31, hl = lane & 15;
    int fi = ((blockIdx.x * 256 + tid) >> 5) * 2 + (lane >> 4);
    int b = fi >> 11, f = fi & (F_ - 1);
    size_t off = ((size_t)b * F_ + f) * E_ + hl * 8;
    const float4* PR = (const float4*)(fr + off);
    const float4* P1 = (const float4*)(fa1 + off);
    const float4* P2 = (const float4*)(fa2 + off);
    float4 vr0 = PR[0], vr1 = PR[1];
    float4 v10 = P1[0], v11 = P1[1];
    float4 v20 = P2[0], v21 = P2[1];
    uint4 c1 = {pack_half2(v10.x, v10.y), pack_half2(v10.z, v10.w),
                pack_half2(v11.x, v11.y), pack_half2(v11.z, v11.w)};
    uint4 c2 = {pack_half2(v20.x, v20.y), pack_half2(v20.z, v20.w),
                pack_half2(v21.x, v21.y), pack_half2(v21.z, v21.w)};
    *(uint4*)(g_f1hi + off) = c1;
    *(uint4*)(g_f2hi + off) = c2;
    const float4* Q;
#define LD2(dst0, dst1, base) Q = (const float4*)(base); float4 dst0 = Q[0], dst1 = Q[1];
    LD2(h00a, h00b, &g_h[0][0][b][hl * 8]);
    LD2(h10a, h10b, &g_h[1][0][b][hl * 8]);
    LD2(h01a, h01b, &g_h[0][1][b][hl * 8]);
    LD2(h11a, h11b, &g_h[1][1][b][hl * 8]);
    LD2(qra, qrb, rel + b * E_ + hl * 8);
    LD2(a1a, a1b, arg1 + b * E_ + hl * 8);
    LD2(a2a, a2b, arg2 + b * E_ + hl * 8);
#undef LD2
    float nsum = dot4(vr0, vr0) + dot4(vr1, vr1) + dot4(v10, v10) + dot4(v11, v11) +
                 dot4(v20, v20) + dot4(v21, v21);
    float a1s = dot4(a1a, a1a) + dot4(a1b, a1b);
    float a2s = dot4(a2a, a2a) + dot4(a2b, a2b);
    float p0 = nsum + dot4(h00a, h00a) + dot4(h00b, h00b) + a1s -
               2.f * (dot4(h00a, vr0) + dot4(h00b, vr1) + dot4(a1a, v10) + dot4(a1b, v11));
    float p1 = nsum + dot4(h10a, h10a) + dot4(h10b, h10b) + a1s -
               2.f * (dot4(h10a, vr0) + dot4(h10b, vr1) + dot4(a1a, v20) + dot4(a1b, v21));
    float q0 = nsum + dot4(h01a, h01a) + dot4(h01b, h01b) + a2s -
               2.f * (dot4(h01a, vr0) + dot4(h01b, vr1) + dot4(a2a, v20) + dot4(a2b, v21));
    float q1 = nsum + dot4(h11a, h11a) + dot4(h11b, h11b) + a2s -
               2.f * (dot4(h11a, vr0) + dot4(h11b, vr1) + dot4(a2a, v10) + dot4(a2b, v11));
    float s = nsum + dot4(qra, qra) + dot4(qrb, qrb) + a1s + a2s -
              2.f * (dot4(qra, vr0) + dot4(qrb, vr1) + dot4(a1a, v10) + dot4(a1b, v11) +
                     dot4(a2a, v20) + dot4(a2b, v21));
    p0 = hsum16(p0);
    p1 = hsum16(p1);
    q0 = hsum16(q0);
    q1 = hsum16(q1);
    s = hsum16(s);
    if (hl == 0) {
        bool valid = f < nbf[b];
        g_cbias[0][b][f] = valid ? -0.5f * p0 : -3e30f;
        g_cbias[1][b][f] = valid ? -0.5f * p1 : -3e30f;
        g_cb2[0][b][f] = valid ? -0.5f * q0 : -3e30f;
        g_cb2[1][b][f] = valid ? -0.5f * q1 : -3e30f;
        if (valid) atomicMax(&g_s0key[b], fenc(-0.5f * s));
    }
}

// ------- heavy max-plus GEMM via mma.sync (single-pass fp16) -----------------
// grid (nt=32, b=16, r*2+fhalf=4); 256 threads / 8 warps, CTA tile 64x128,
// warp tile 32x32, smem 80KB -> 2 CTAs/SM
#define OFF_AHI 0
#define OFF_B0 16384
#define SMEM_MG 81920

__global__ __launch_bounds__(256, 2) void k_maxgemm(const int* __restrict__ nbe) {
    extern __shared__ char smem[];
    uint32_t sb = smem_u32(smem);
    const int tid = threadIdx.x, lane = tid & 31, wid = tid >> 5;
    const int wm = (wid & 1) * 32, wn = (wid >> 1) * 32;
    const int nt = blockIdx.x, b = blockIdx.y;
    const int r = blockIdx.z >> 1, fh = blockIdx.z & 1;

    const __half* ehi = g_ehi + ((size_t)b * N_ + nt * 64) * E_;
    const __half* fhi = ((r == 0) ? g_f2hi : g_f1hi) + (size_t)b * F_ * E_;
    const float* cb = &g_cbias[r][b][0];

    // resident entity tile (64 rows), swizzled
#pragma unroll
    for (int it = 0; it < 2; ++it) {
        int i = tid + it * 256;
        int row = i >> 3, ch = (i & 7) * 2;
        uint32_t o = swz(row, ch);
        const uint4* src = (const uint4*)(ehi + (size_t)row * E_ + ch * 8);
        *(uint4*)(smem + OFF_AHI + o) = src[0];
        *(uint4*)(smem + OFF_AHI + (o ^ 16)) = src[1];
    }

    auto issueB = [&](int ft, int buf) {
        uint32_t base = sb + OFF_B0 + buf * 32768;
        const __half* sh = fhi + (size_t)ft * 128 * E_;
#pragma unroll
        for (int it = 0; it < 8; ++it) {
            int i = tid + it * 256;
            int row = i >> 4, ch = i & 15;
            cp16(base + swz(row, ch), sh + (size_t)row * E_ + ch * 8);
        }
    };
    issueB(fh * 8, 0);
    cpcommit();

    float rmax[4];
#pragma unroll
    for (int i = 0; i < 4; i++) rmax[i] = -3e30f;

    for (int t = 0; t < 8; ++t) {
        int ft = fh * 8 + t;
        // prefetch this tile's cbias into registers
        float creg[8];
#pragma unroll
        for (int j = 0; j < 4; j++) {
            int col = ft * 128 + wn + j * 8 + 2 * (lane & 3);
            creg[2 * j] = __ldg(cb + col);
            creg[2 * j + 1] = __ldg(cb + col + 1);
        }
        cpwait<0>();
        __syncthreads();  // buffer t&1 ready; all warps done with the other buffer
        if (t + 1 < 8) {
            issueB(ft + 1, (t + 1) & 1);
            cpcommit();
        }

        float acc[2][4][4];
#pragma unroll
        for (int i = 0; i < 2; i++)
#pragma unroll
            for (int j = 0; j < 4; j++)
#pragma unroll
                for (int q = 0; q < 4; q++) acc[i][j][q] = 0.f;

        uint32_t bbase = sb + OFF_B0 + (t & 1) * 32768;
#pragma unroll
        for (int ks = 0; ks < 8; ++ks) {
            int kc = ks * 2 + (lane >> 4);
            uint32_t ah[2][4];
#pragma unroll
            for (int i = 0; i < 2; i++) {
                int row = wm + i * 16 + (lane & 15);
                ldsm4(ah[i][0], ah[i][1], ah[i][2], ah[i][3], sb + OFF_AHI + swz(row, kc));
            }
            uint32_t bh[4][2];
#pragma unroll
            for (int p = 0; p < 2; p++) {
                int row = wn + p * 16 + (lane & 15);
                uint32_t r0, r1, r2, r3;
                ldsm4(r0, r1, r2, r3, bbase + swz(row, kc));
                bh[2 * p][0] = r0; bh[2 * p][1] = r2;
                bh[2 * p + 1][0] = r1; bh[2 * p + 1][1] = r3;
            }
#pragma unroll
            for (int i = 0; i < 2; i++)
#pragma unroll
                for (int j = 0; j < 4; j++) mma16816(acc[i][j], ah[i], bh[j]);
        }
        // epilogue: add cbias (registers), fold running row-max
#pragma unroll
        for (int j = 0; j < 4; j++) {
            float c0 = creg[2 * j], c1 = creg[2 * j + 1];
#pragma unroll
            for (int i = 0; i < 2; i++) {
                rmax[2 * i] = fmaxf(rmax[2 * i], fmaxf(acc[i][j][0] + c0, acc[i][j][1] + c1));
                rmax[2 * i + 1] = fmaxf(rmax[2 * i + 1],
                                        fmaxf(acc[i][j][2] + c0, acc[i][j][3] + c1));
            }
        }
    }

    // cross-thread row-max reduction (reuse smem)
    __syncthreads();
    float* Red = (float*)smem;
#pragma unroll
    for (int i = 0; i < 2; i++)
#pragma unroll
        for (int h = 0; h < 2; h++) {
            int row = wm + i * 16 + h * 8 + (lane >> 2);
            Red[row * 16 + (wid >> 1) * 4 + (lane & 3)] = rmax[2 * i + h];
        }
    __syncthreads();
    if (tid < 64) {
        float m = -3e30f;
#pragma unroll
        for (int t = 0; t < 16; t++) m = fmaxf(m, Red[tid * 16 + t]);
        int gn = nt * 64 + tid;
        float Lv = m - 0.5f * g_esq[b][gn];
        if (gn < nbe[b]) atomicMax(&g_Lkey[r][b][gn], fenc(Lv));
    }
}

// ---------------- top-K over N per (r,b): shuffle-based -----------------------
__global__ void k_topk() {
    int b = blockIdx.x, r = blockIdx.y, tid = threadIdx.x;
    int lane = tid & 31, wid = tid >> 5;
    float v[8];
#pragma unroll
    for (int j = 0; j < 8; j++) v[j] = fdec(g_Lkey[r][b][tid + 256 * j]);
    __shared__ float swv[8];
    __shared__ int swi[8];
    __shared__ int schosen;
    for (int kk = 0; kk < K_; kk++) {
        float bv = -3.4e38f;
        int bi = 0;
#pragma unroll
        for (int j = 0; j < 8; j++)
            if (v[j] > bv) { bv = v[j]; bi = tid + 256 * j; }
#pragma unroll
        for (int o = 16; o > 0; o >>= 1) {
            float ov = __shfl_xor_sync(0xffffffffu, bv, o);
            int oi = __shfl_xor_sync(0xffffffffu, bi, o);
            if (ov > bv || (ov == bv && oi < bi)) { bv = ov; bi = oi; }
        }
        if (lane == 0) { swv[wid] = bv; swi[wid] = bi; }
        __syncthreads();
        if (wid == 0) {
            float bv2 = (lane < 8) ? swv[lane] : -3.4e38f;
            int bi2 = (lane < 8) ? swi[lane] : 0;
#pragma unroll
            for (int o = 4; o > 0; o >>= 1) {
                float ov = __shfl_xor_sync(0xffffffffu, bv2, o);
                int oi = __shfl_xor_sync(0xffffffffu, bi2, o);
                if (ov > bv2 || (ov == bv2 && oi < bi2)) { bv2 = ov; bi2 = oi; }
            }
            if (lane == 0) {
                g_zidx[r][b][kk] = bi2;
                g_zlog[r][b][kk] = bv2;
                schosen = bi2;
            }
        }
        __syncthreads();
        int ch = schosen;
        if ((ch & 255) == tid) v[ch >> 8] = -3.4e38f;
        __syncthreads();
    }
}

// ---------------- hop-2 rescoring: max-plus over facts (split 8-way) ---------
__global__ void k_s2(const float* __restrict__ ent, const float* __restrict__ fa1,
                     const float* __restrict__ fa2) {
    int b = blockIdx.x, r = blockIdx.y, z = blockIdx.z, tid = threadIdx.x;
    int lane = tid & 31, wid = tid >> 5;
    __shared__ float zs[K_][E_];
    __shared__ float red[K_][257];
    for (int i = tid; i < K_ * E_; i += 256) {
        int k = i >> 7, e = i & 127;
        zs[k][e] = ent[((size_t)b * N_ + g_zidx[r][b][k]) * E_ + e];
    }
    __syncthreads();
    const float* fy = ((r == 0) ? fa1 : fa2) + (size_t)b * F_ * E_;
    int f = z * 256 + tid;
    float c = g_cb2[r][b][f];
    const float4* row = (const float4*)(fy + (size_t)f * E_);
    float d[K_];
#pragma unroll
    for (int k = 0; k < K_; k++) d[k] = 0.f;
#pragma unroll 4
    for (int e4 = 0; e4 < 32; e4++) {
        float4 v = row[e4];
#pragma unroll
        for (int k = 0; k < K_; k++) {
            float4 zz = ((const float4*)zs[k])[e4];
            d[k] += v.x * zz.x + v.y * zz.y + v.z * zz.z + v.w * zz.w;
        }
    }
#pragma unroll
    for (int k = 0; k < K_; k++) red[k][tid] = d[k] + c;
    __syncthreads();
    for (int k = wid; k < K_; k += 8) {
        float m = -3e30f;
        for (int j = lane; j < 256; j += 32) m = fmaxf(m, red[k][j]);
#pragma unroll
        for (int o = 16; o > 0; o >>= 1) m = fmaxf(m, __shfl_xor_sync(0xffffffffu, m, o));
        if (lane == 0) g_s2part[r][b][z][k] = m;
    }
}

// ---------------- final combine ----------------------------------------------
__global__ void k_final(float* __restrict__ out) {
    int b = threadIdx.x;
    if (b >= B_) return;
    float res = expf(fdec(g_s0key[b]));
#pragma unroll
    for (int r = 0; r < R_; r++)
#pragma unroll
        for (int k = 0; k < K_; k++) {
            float m = -3e30f;
            for (int z = 0; z < ZSPLIT; z++) m = fmaxf(m, g_s2part[r][b][z][k]);
            float s2 = m - 0.5f * g_esq[b][g_zidx[r][b][k]];
            res = fmaxf(res, expf(fminf(s2, g_zlog[r][b][k])));
        }
    out[b] = res;
}

// ---------------- launch -------------------------------------------------------
extern "C" void kernel_launch(void* const* d_in, const int* in_sizes, int n_in,
                              void* d_out, int out_size) {
    (void)in_sizes; (void)n_in; (void)out_size;
    const float* rel = (const float*)d_in[0];
    const float* arg1 = (const float*)d_in[1];
    const float* arg2 = (const float*)d_in[2];
    const float* fr = (const float*)d_in[3];
    const float* fa1 = (const float*)d_in[4];
    const float* fa2 = (const float*)d_in[5];
    const float* ent = (const float*)d_in[6];
    const float* W = (const float*)d_in[7];
    const float* hb = (const float*)d_in[8];
    const int* nbf = (const int*)d_in[9];
    const int* nbe = (const int*)d_in[10];
    float* out = (float*)d_out;

    cudaFuncSetAttribute(k_maxgemm, cudaFuncAttributeMaxDynamicSharedMemorySize, SMEM_MG);

    k_split<<<(B_ * N_ * E_) / 1024, 256>>>(ent);
    k_hop<<<dim3(B_, 2, R_), E_>>>(rel, W, hb);
    k_cbias<<<(B_ * F_) / 16, 256>>>(rel, arg1, arg2, fr, fa1, fa2, nbf);
    k_maxgemm<<<dim3(N_ / 64, B_, 2 * R_), 256, SMEM_MG>>>(nbe);
    k_topk<<<dim3(B_, R_), 256>>>();
    k_s2<<<dim3(B_, R_, ZSPLIT), 256>>>(ent, fa1, fa2);
    k_final<<<1, 32>>>(out);
}

// round 10
// speedup vs baseline: 5.9069x; 1.0852x over previous
#include <cuda_runtime.h>
#include <cuda_fp16.h>
#include <cstdint>

#define B_ 16
#define N_ 2048
#define F_ 2048
#define E_ 128
#define K_ 10
#define R_ 2
#define ZSPLIT 8

// ---------------- device scratch (static, no runtime allocation) ----------
__device__ float g_h[R_][2][B_][E_];        // hop vectors (h1,h2) per rule
__device__ float g_esq[B_][N_];             // entity squared norms
__device__ float g_cbias[R_][B_][F_];       // hop-1 fact bias
__device__ float g_cb2[R_][B_][F_];         // hop-2 fact bias
__device__ unsigned g_s0key[B_];            // scores_0 ordered-int atomic max
__device__ unsigned g_Lkey[R_][B_][N_];     // hop-1 log scores (ordered-uint)
__device__ int   g_zidx[R_][B_][K_];
__device__ float g_zlog[R_][B_][K_];
__device__ float g_s2part[R_][B_][ZSPLIT][K_];

// fp16 planes (round-to-nearest)
__device__ __half g_ehi[B_ * N_ * E_];
__device__ __half g_f1hi[B_ * F_ * E_];
__device__ __half g_f2hi[B_ * F_ * E_];

// ---------------- helpers ---------------------------------------------------
__device__ __forceinline__ float warp_sum(float v) {
#pragma unroll
    for (int o = 16; o > 0; o >>= 1) v += __shfl_xor_sync(0xffffffffu, v, o);
    return v;
}
__device__ __forceinline__ float hsum16(float v) {
#pragma unroll
    for (int o = 8; o > 0; o >>= 1) v += __shfl_xor_sync(0xffffffffu, v, o);
    return v;
}
__device__ __forceinline__ float dot4(float4 a, float4 b) {
    return a.x * b.x + a.y * b.y + a.z * b.z + a.w * b.w;
}
__device__ __forceinline__ unsigned fenc(float v) {
    unsigned u = __float_as_uint(v);
    return (u & 0x80000000u) ? ~u : (u | 0x80000000u);
}
__device__ __forceinline__ float fdec(unsigned k) {
    return (k & 0x80000000u) ? __uint_as_float(k ^ 0x80000000u) : __uint_as_float(~k);
}
__device__ __forceinline__ uint32_t smem_u32(const void* p) {
    uint32_t a;
    asm("{ .reg .u64 t; cvta.to.shared.u64 t, %1; cvt.u32.u64 %0, t; }" : "=r"(a) : "l"(p));
    return a;
}
__device__ __forceinline__ unsigned pack_half2(float a, float b) {
    __half2 h = __halves2half2(__float2half_rn(a), __float2half_rn(b));
    return *(unsigned*)&h;
}

// ---------------- portable tensor-core / async-copy PTX ----------------------
__device__ __forceinline__ void cp16(uint32_t s, const void* g) {
    asm volatile("cp.async.cg.shared.global [%0], [%1], 16;" :: "r"(s), "l"(g));
}
__device__ __forceinline__ void cpcommit() { asm volatile("cp.async.commit_group;"); }
template <int NN>
__device__ __forceinline__ void cpwait() {
    asm volatile("cp.async.wait_group %0;" :: "n"(NN));
}
__device__ __forceinline__ void ldsm4(uint32_t& r0, uint32_t& r1, uint32_t& r2, uint32_t& r3,
                                      uint32_t a) {
    asm volatile("ldmatrix.sync.aligned.m8n8.x4.shared.b16 {%0,%1,%2,%3}, [%4];"
                 : "=r"(r0), "=r"(r1), "=r"(r2), "=r"(r3) : "r"(a));
}
__device__ __forceinline__ void mma16816(float* c, const uint32_t* a, const uint32_t* b) {
    asm volatile(
        "mma.sync.aligned.m16n8k16.row.col.f32.f16.f16.f32 "
        "{%0,%1,%2,%3},{%4,%5,%6,%7},{%8,%9},{%0,%1,%2,%3};"
        : "+f"(c[0]), "+f"(c[1]), "+f"(c[2]), "+f"(c[3])
        : "r"(a[0]), "r"(a[1]), "r"(a[2]), "r"(a[3]), "r"(b[0]), "r"(b[1]));
}
// swizzled tile offset: rows x 128 fp16 (256B rows, 16-byte chunks, XOR swizzle)
__device__ __forceinline__ uint32_t swz(int row, int chunk) {
    return (uint32_t)row * 256u + (uint32_t)((chunk ^ (row & 7)) * 16);
}

// ------ entity fp16 conversion + fused entity norms + g_Lkey init -----------
__global__ void k_split(const float* __restrict__ ent) {
    int tid = threadIdx.x;
    size_t i = ((size_t)blockIdx.x * 256 + tid) * 4;
    float4 v = *(const float4*)(ent + i);
    uint2 uh = {pack_half2(v.x, v.y), pack_half2(v.z, v.w)};
    *(uint2*)(g_ehi + i) = uh;
    float s = warp_sum(dot4(v, v));
    if ((tid & 31) == 0) {
        int gw = blockIdx.x * 8 + (tid >> 5);
        ((float*)g_esq)[gw] = s;
        unsigned init = fenc(-3e30f);
        int b = gw >> 11, n = gw & (N_ - 1);
        g_Lkey[0][b][n] = init;
        g_Lkey[1][b][n] = init;
    }
}

// ---------------- hop vectors + s0key init ----------------------------------
__global__ void k_hop(const float* __restrict__ rel, const float* __restrict__ W,
                      const float* __restrict__ hb) {
    int b = blockIdx.x, h = blockIdx.y, r = blockIdx.z, e = threadIdx.x;
    if (e == 0 && h == 0 && r == 0) g_s0key[b] = fenc(-3e30f);
    const float* w = W + (size_t)((r * 2 + h) * E_) * E_ + e;
    const float* rb = rel + b * E_;
    float s = hb[(r * 2 + h) * E_ + e];
#pragma unroll 8
    for (int i = 0; i < E_; i++) s += rb[i] * w[(size_t)i * E_];
    g_h[r][h][b][e] = s;
}

// -- per-fact biases + fused scores_0 + fused fp16 fact conversion; 2 facts/warp
__global__ void k_cbias(const float* __restrict__ rel, const float* __restrict__ arg1,
                        const float* __restrict__ arg2, const float* __restrict__ fr,
                        const float* __restrict__ fa1, const float* __restrict__ fa2,
                        const int* __restrict__ nbf) {
    int tid = threadIdx.x, lane = tid & 31, hl = lane & 15;
    int fi = ((blockIdx.x * 256 + tid) >> 5) * 2 + (lane >> 4);
    int b = fi >> 11, f = fi & (F_ - 1);
    size_t off = ((size_t)b * F_ + f) * E_ + hl * 8;
    const float4* PR = (const float4*)(fr + off);
    const float4* P1 = (const float4*)(fa1 + off);
    const float4* P2 = (const float4*)(fa2 + off);
    float4 vr0 = PR[0], vr1 = PR[1];
    float4 v10 = P1[0], v11 = P1[1];
    float4 v20 = P2[0], v21 = P2[1];
    uint4 c1 = {pack_half2(v10.x, v10.y), pack_half2(v10.z, v10.w),
                pack_half2(v11.x, v11.y), pack_half2(v11.z, v11.w)};
    uint4 c2 = {pack_half2(v20.x, v20.y), pack_half2(v20.z, v20.w),
                pack_half2(v21.x, v21.y), pack_half2(v21.z, v21.w)};
    *(uint4*)(g_f1hi + off) = c1;
    *(uint4*)(g_f2hi + off) = c2;
    const float4* Q;
#define LD2(dst0, dst1, base) Q = (const float4*)(base); float4 dst0 = Q[0], dst1 = Q[1];
    LD2(h00a, h00b, &g_h[0][0][b][hl * 8]);
    LD2(h10a, h10b, &g_h[1][0][b][hl * 8]);
    LD2(h01a, h01b, &g_h[0][1][b][hl * 8]);
    LD2(h11a, h11b, &g_h[1][1][b][hl * 8]);
    LD2(qra, qrb, rel + b * E_ + hl * 8);
    LD2(a1a, a1b, arg1 + b * E_ + hl * 8);
    LD2(a2a, a2b, arg2 + b * E_ + hl * 8);
#undef LD2
    float nsum = dot4(vr0, vr0) + dot4(vr1, vr1) + dot4(v10, v10) + dot4(v11, v11) +
                 dot4(v20, v20) + dot4(v21, v21);
    float a1s = dot4(a1a, a1a) + dot4(a1b, a1b);
    float a2s = dot4(a2a, a2a) + dot4(a2b, a2b);
    float p0 = nsum + dot4(h00a, h00a) + dot4(h00b, h00b) + a1s -
               2.f * (dot4(h00a, vr0) + dot4(h00b, vr1) + dot4(a1a, v10) + dot4(a1b, v11));
    float p1 = nsum + dot4(h10a, h10a) + dot4(h10b, h10b) + a1s -
               2.f * (dot4(h10a, vr0) + dot4(h10b, vr1) + dot4(a1a, v20) + dot4(a1b, v21));
    float q0 = nsum + dot4(h01a, h01a) + dot4(h01b, h01b) + a2s -
               2.f * (dot4(h01a, vr0) + dot4(h01b, vr1) + dot4(a2a, v20) + dot4(a2b, v21));
    float q1 = nsum + dot4(h11a, h11a) + dot4(h11b, h11b) + a2s -
               2.f * (dot4(h11a, vr0) + dot4(h11b, vr1) + dot4(a2a, v10) + dot4(a2b, v11));
    float s = nsum + dot4(qra, qra) + dot4(qrb, qrb) + a1s + a2s -
              2.f * (dot4(qra, vr0) + dot4(qrb, vr1) + dot4(a1a, v10) + dot4(a1b, v11) +
                     dot4(a2a, v20) + dot4(a2b, v21));
    p0 = hsum16(p0);
    p1 = hsum16(p1);
    q0 = hsum16(q0);
    q1 = hsum16(q1);
    s = hsum16(s);
    if (hl == 0) {
        bool valid = f < nbf[b];
        g_cbias[0][b][f] = valid ? -0.5f * p0 : -3e30f;
        g_cbias[1][b][f] = valid ? -0.5f * p1 : -3e30f;
        g_cb2[0][b][f] = valid ? -0.5f * q0 : -3e30f;
        g_cb2[1][b][f] = valid ? -0.5f * q1 : -3e30f;
        if (valid) atomicMax(&g_s0key[b], fenc(-0.5f * s));
    }
}

// ------- heavy max-plus GEMM via mma.sync (single-pass fp16) -----------------
// grid (nt=16, b=16, r*4+fq=8); 256 threads / 8 warps, CTA tile 128x128,
// warp grid 4m x 2n (warp tile 32x64), smem 96KB -> 2 CTAs/SM, 4 fact tiles/CTA
#define OFF_AHI 0
#define OFF_B0 32768
#define SMEM_MG 98304

__global__ __launch_bounds__(256, 2) void k_maxgemm(const int* __restrict__ nbe) {
    extern __shared__ char smem[];
    uint32_t sb = smem_u32(smem);
    const int tid = threadIdx.x, lane = tid & 31, wid = tid >> 5;
    const int wm = (wid & 3) * 32, wn = (wid >> 2) * 64;
    const int nt = blockIdx.x, b = blockIdx.y;
    const int r = blockIdx.z >> 2, fq = blockIdx.z & 3;

    const __half* ehi = g_ehi + ((size_t)b * N_ + nt * 128) * E_;
    const __half* fhi = ((r == 0) ? g_f2hi : g_f1hi) + (size_t)b * F_ * E_;
    const float* cb = &g_cbias[r][b][0];

    // resident entity tile (128 rows), swizzled
#pragma unroll
    for (int it = 0; it < 8; ++it) {
        int i = tid + it * 256;
        int row = i >> 4, ch = i & 15;
        *(uint4*)(smem + OFF_AHI + swz(row, ch)) =
            *(const uint4*)(ehi + (size_t)row * E_ + ch * 8);
    }

    auto issueB = [&](int ft, int buf) {
        uint32_t base = sb + OFF_B0 + buf * 32768;
        const __half* sh = fhi + (size_t)ft * 128 * E_;
#pragma unroll
        for (int it = 0; it < 8; ++it) {
            int i = tid + it * 256;
            int row = i >> 4, ch = i & 15;
            cp16(base + swz(row, ch), sh + (size_t)row * E_ + ch * 8);
        }
    };
    issueB(fq * 4, 0);
    cpcommit();

    float rmax[4];
#pragma unroll
    for (int i = 0; i < 4; i++) rmax[i] = -3e30f;

    for (int t = 0; t < 4; ++t) {
        int ft = fq * 4 + t;
        cpwait<0>();
        __syncthreads();  // buffer t&1 ready; all warps done with the other buffer
        if (t + 1 < 4) {
            issueB(ft + 1, (t + 1) & 1);
            cpcommit();
        }

        float acc[2][8][4];
#pragma unroll
        for (int i = 0; i < 2; i++)
#pragma unroll
            for (int j = 0; j < 8; j++)
#pragma unroll
                for (int q = 0; q < 4; q++) acc[i][j][q] = 0.f;

        uint32_t bbase = sb + OFF_B0 + (t & 1) * 32768;
#pragma unroll
        for (int ks = 0; ks < 8; ++ks) {
            int kc = ks * 2 + (lane >> 4);
            uint32_t ah[2][4];
#pragma unroll
            for (int i = 0; i < 2; i++) {
                int row = wm + i * 16 + (lane & 15);
                ldsm4(ah[i][0], ah[i][1], ah[i][2], ah[i][3], sb + OFF_AHI + swz(row, kc));
            }
            uint32_t bh[8][2];
#pragma unroll
            for (int p = 0; p < 4; p++) {
                int row = wn + p * 16 + (lane & 15);
                uint32_t r0, r1, r2, r3;
                ldsm4(r0, r1, r2, r3, bbase + swz(row, kc));
                bh[2 * p][0] = r0; bh[2 * p][1] = r2;
                bh[2 * p + 1][0] = r1; bh[2 * p + 1][1] = r3;
            }
#pragma unroll
            for (int i = 0; i < 2; i++)
#pragma unroll
                for (int j = 0; j < 8; j++) mma16816(acc[i][j], ah[i], bh[j]);
        }
        // epilogue: add cbias, fold running row-max
#pragma unroll
        for (int j = 0; j < 8; j++) {
            int col = ft * 128 + wn + j * 8 + 2 * (lane & 3);
            float c0 = __ldg(cb + col), c1 = __ldg(cb + col + 1);
#pragma unroll
            for (int i = 0; i < 2; i++) {
                rmax[2 * i] = fmaxf(rmax[2 * i], fmaxf(acc[i][j][0] + c0, acc[i][j][1] + c1));
                rmax[2 * i + 1] = fmaxf(rmax[2 * i + 1],
                                        fmaxf(acc[i][j][2] + c0, acc[i][j][3] + c1));
            }
        }
    }

    // cross-thread row-max reduction (reuse smem): 8 partials per row
    __syncthreads();
    float* Red = (float*)smem;
#pragma unroll
    for (int i = 0; i < 2; i++)
#pragma unroll
        for (int h = 0; h < 2; h++) {
            int row = wm + i * 16 + h * 8 + (lane >> 2);
            Red[row * 9 + (wid >> 2) * 4 + (lane & 3)] = rmax[2 * i + h];
        }
    __syncthreads();
    if (tid < 128) {
        float m = -3e30f;
#pragma unroll
        for (int t = 0; t < 8; t++) m = fmaxf(m, Red[tid * 9 + t]);
        int gn = nt * 128 + tid;
        float Lv = m - 0.5f * g_esq[b][gn];
        if (gn < nbe[b]) atomicMax(&g_Lkey[r][b][gn], fenc(Lv));
    }
}

// ---------------- top-K over N per (r,b): shuffle-based -----------------------
__global__ void k_topk() {
    int b = blockIdx.x, r = blockIdx.y, tid = threadIdx.x;
    int lane = tid & 31, wid = tid >> 5;
    float v[8];
#pragma unroll
    for (int j = 0; j < 8; j++) v[j] = fdec(g_Lkey[r][b][tid + 256 * j]);
    __shared__ float swv[8];
    __shared__ int swi[8];
    __shared__ int schosen;
    for (int kk = 0; kk < K_; kk++) {
        float bv = -3.4e38f;
        int bi = 0;
#pragma unroll
        for (int j = 0; j < 8; j++)
            if (v[j] > bv) { bv = v[j]; bi = tid + 256 * j; }
#pragma unroll
        for (int o = 16; o > 0; o >>= 1) {
            float ov = __shfl_xor_sync(0xffffffffu, bv, o);
            int oi = __shfl_xor_sync(0xffffffffu, bi, o);
            if (ov > bv || (ov == bv && oi < bi)) { bv = ov; bi = oi; }
        }
        if (lane == 0) { swv[wid] = bv; swi[wid] = bi; }
        __syncthreads();
        if (wid == 0) {
            float bv2 = (lane < 8) ? swv[lane] : -3.4e38f;
            int bi2 = (lane < 8) ? swi[lane] : 0;
#pragma unroll
            for (int o = 4; o > 0; o >>= 1) {
                float ov = __shfl_xor_sync(0xffffffffu, bv2, o);
                int oi = __shfl_xor_sync(0xffffffffu, bi2, o);
                if (ov > bv2 || (ov == bv2 && oi < bi2)) { bv2 = ov; bi2 = oi; }
            }
            if (lane == 0) {
                g_zidx[r][b][kk] = bi2;
                g_zlog[r][b][kk] = bv2;
                schosen = bi2;
            }
        }
        __syncthreads();
        int ch = schosen;
        if ((ch & 255) == tid) v[ch >> 8] = -3.4e38f;
        __syncthreads();
    }
}

// ---------------- hop-2 rescoring: max-plus over facts (split 8-way) ---------
__global__ void k_s2(const float* __restrict__ ent, const float* __restrict__ fa1,
                     const float* __restrict__ fa2) {
    int b = blockIdx.x, r = blockIdx.y, z = blockIdx.z, tid = threadIdx.x;
    int lane = tid & 31, wid = tid >> 5;
    __shared__ float zs[K_][E_];
    __shared__ float red[K_][257];
    for (int i = tid; i < K_ * E_; i += 256) {
        int k = i >> 7, e = i & 127;
        zs[k][e] = ent[((size_t)b * N_ + g_zidx[r][b][k]) * E_ + e];
    }
    __syncthreads();
    const float* fy = ((r == 0) ? fa1 : fa2) + (size_t)b * F_ * E_;
    int f = z * 256 + tid;
    float c = g_cb2[r][b][f];
    const float4* row = (const float4*)(fy + (size_t)f * E_);
    float d[K_];
#pragma unroll
    for (int k = 0; k < K_; k++) d[k] = 0.f;
#pragma unroll 4
    for (int e4 = 0; e4 < 32; e4++) {
        float4 v = row[e4];
#pragma unroll
        for (int k = 0; k < K_; k++) {
            float4 zz = ((const float4*)zs[k])[e4];
            d[k] += v.x * zz.x + v.y * zz.y + v.z * zz.z + v.w * zz.w;
        }
    }
#pragma unroll
    for (int k = 0; k < K_; k++) red[k][tid] = d[k] + c;
    __syncthreads();
    for (int k = wid; k < K_; k += 8) {
        float m = -3e30f;
        for (int j = lane; j < 256; j += 32) m = fmaxf(m, red[k][j]);
#pragma unroll
        for (int o = 16; o > 0; o >>= 1) m = fmaxf(m, __shfl_xor_sync(0xffffffffu, m, o));
        if (lane == 0) g_s2part[r][b][z][k] = m;
    }
}

// ---------------- final combine ----------------------------------------------
__global__ void k_final(float* __restrict__ out) {
    int b = threadIdx.x;
    if (b >= B_) return;
    float res = expf(fdec(g_s0key[b]));
#pragma unroll
    for (int r = 0; r < R_; r++)
#pragma unroll
        for (int k = 0; k < K_; k++) {
            float m = -3e30f;
            for (int z = 0; z < ZSPLIT; z++) m = fmaxf(m, g_s2part[r][b][z][k]);
            float s2 = m - 0.5f * g_esq[b][g_zidx[r][b][k]];
            res = fmaxf(res, expf(fminf(s2, g_zlog[r][b][k])));
        }
    out[b] = res;
}

// ---------------- launch -------------------------------------------------------
extern "C" void kernel_launch(void* const* d_in, const int* in_sizes, int n_in,
                              void* d_out, int out_size) {
    (void)in_sizes; (void)n_in; (void)out_size;
    const float* rel = (const float*)d_in[0];
    const float* arg1 = (const float*)d_in[1];
    const float* arg2 = (const float*)d_in[2];
    const float* fr = (const float*)d_in[3];
    const float* fa1 = (const float*)d_in[4];
    const float* fa2 = (const float*)d_in[5];
    const float* ent = (const float*)d_in[6];
    const float* W = (const float*)d_in[7];
    const float* hb = (const float*)d_in[8];
    const int* nbf = (const int*)d_in[9];
    const int* nbe = (const int*)d_in[10];
    float* out = (float*)d_out;

    cudaFuncSetAttribute(k_maxgemm, cudaFuncAttributeMaxDynamicSharedMemorySize, SMEM_MG);

    k_split<<<(B_ * N_ * E_) / 1024, 256>>>(ent);
    k_hop<<<dim3(B_, 2, R_), E_>>>(rel, W, hb);
    k_cbias<<<(B_ * F_) / 16, 256>>>(rel, arg1, arg2, fr, fa1, fa2, nbf);
    k_maxgemm<<<dim3(N_ / 128, B_, 4 * R_), 256, SMEM_MG>>>(nbe);
    k_topk<<<dim3(B_, R_), 256>>>();
    k_s2<<<dim3(B_, R_, ZSPLIT), 256>>>(ent, fa1, fa2);
    k_final<<<1, 32>>>(out);
}

// round 11
// speedup vs baseline: 6.2798x; 1.0631x over previous
#include <cuda_runtime.h>
#include <cuda_fp16.h>
#include <cstdint>

#define B_ 16
#define N_ 2048
#define F_ 2048
#define E_ 128
#define K_ 10
#define R_ 2
#define ZSPLIT 8

// ---------------- device scratch (static, no runtime allocation) ----------
__device__ float g_h[R_][2][B_][E_];        // hop vectors (h1,h2) per rule
__device__ float g_esq[B_][N_];             // entity squared norms
__device__ float g_cbias[R_][B_][F_];       // hop-1 fact bias
__device__ float g_cb2[R_][B_][F_];         // hop-2 fact bias
__device__ unsigned g_s0key[B_];            // scores_0 ordered-int atomic max
__device__ unsigned g_Lkey[R_][B_][N_];     // hop-1 log scores (ordered-uint)
__device__ int   g_zidx[R_][B_][K_];
__device__ float g_zlog[R_][B_][K_];
__device__ float g_s2part[R_][B_][ZSPLIT][K_];

// fp16 planes (round-to-nearest)
__device__ __half g_ehi[B_ * N_ * E_];
__device__ __half g_f1hi[B_ * F_ * E_];
__device__ __half g_f2hi[B_ * F_ * E_];

// ---------------- helpers ---------------------------------------------------
__device__ __forceinline__ float warp_sum(float v) {
#pragma unroll
    for (int o = 16; o > 0; o >>= 1) v += __shfl_xor_sync(0xffffffffu, v, o);
    return v;
}
__device__ __forceinline__ float hsum16(float v) {
#pragma unroll
    for (int o = 8; o > 0; o >>= 1) v += __shfl_xor_sync(0xffffffffu, v, o);
    return v;
}
__device__ __forceinline__ float dot4(float4 a, float4 b) {
    return a.x * b.x + a.y * b.y + a.z * b.z + a.w * b.w;
}
__device__ __forceinline__ unsigned fenc(float v) {
    unsigned u = __float_as_uint(v);
    return (u & 0x80000000u) ? ~u : (u | 0x80000000u);
}
__device__ __forceinline__ float fdec(unsigned k) {
    return (k & 0x80000000u) ? __uint_as_float(k ^ 0x80000000u) : __uint_as_float(~k);
}
__device__ __forceinline__ uint32_t smem_u32(const void* p) {
    uint32_t a;
    asm("{ .reg .u64 t; cvta.to.shared.u64 t, %1; cvt.u32.u64 %0, t; }" : "=r"(a) : "l"(p));
    return a;
}
__device__ __forceinline__ unsigned pack_half2(float a, float b) {
    __half2 h = __halves2half2(__float2half_rn(a), __float2half_rn(b));
    return *(unsigned*)&h;
}

// ---------------- portable tensor-core / async-copy PTX ----------------------
__device__ __forceinline__ void cp16(uint32_t s, const void* g) {
    asm volatile("cp.async.cg.shared.global [%0], [%1], 16;" :: "r"(s), "l"(g));
}
__device__ __forceinline__ void cpcommit() { asm volatile("cp.async.commit_group;"); }
template <int NN>
__device__ __forceinline__ void cpwait() {
    asm volatile("cp.async.wait_group %0;" :: "n"(NN));
}
__device__ __forceinline__ void ldsm4(uint32_t& r0, uint32_t& r1, uint32_t& r2, uint32_t& r3,
                                      uint32_t a) {
    asm volatile("ldmatrix.sync.aligned.m8n8.x4.shared.b16 {%0,%1,%2,%3}, [%4];"
                 : "=r"(r0), "=r"(r1), "=r"(r2), "=r"(r3) : "r"(a));
}
__device__ __forceinline__ void mma16816(float* c, const uint32_t* a, const uint32_t* b) {
    asm volatile(
        "mma.sync.aligned.m16n8k16.row.col.f32.f16.f16.f32 "
        "{%0,%1,%2,%3},{%4,%5,%6,%7},{%8,%9},{%0,%1,%2,%3};"
        : "+f"(c[0]), "+f"(c[1]), "+f"(c[2]), "+f"(c[3])
        : "r"(a[0]), "r"(a[1]), "r"(a[2]), "r"(a[3]), "r"(b[0]), "r"(b[1]));
}
// swizzled tile offset: rows x 128 fp16 (256B rows, 16-byte chunks, XOR swizzle)
__device__ __forceinline__ uint32_t swz(int row, int chunk) {
    return (uint32_t)row * 256u + (uint32_t)((chunk ^ (row & 7)) * 16);
}

// ------ entity fp16 conversion + fused entity norms + g_Lkey init -----------
__global__ void k_split(const float* __restrict__ ent) {
    int tid = threadIdx.x;
    size_t i = ((size_t)blockIdx.x * 256 + tid) * 4;
    float4 v = *(const float4*)(ent + i);
    uint2 uh = {pack_half2(v.x, v.y), pack_half2(v.z, v.w)};
    *(uint2*)(g_ehi + i) = uh;
    float s = warp_sum(dot4(v, v));
    if ((tid & 31) == 0) {
        int gw = blockIdx.x * 8 + (tid >> 5);
        ((float*)g_esq)[gw] = s;
        unsigned init = fenc(-3e30f);
        int b = gw >> 11, n = gw & (N_ - 1);
        g_Lkey[0][b][n] = init;
        g_Lkey[1][b][n] = init;
    }
}

// ---------------- hop vectors + s0key init ----------------------------------
__global__ void k_hop(const float* __restrict__ rel, const float* __restrict__ W,
                      const float* __restrict__ hb) {
    int b = blockIdx.x, h = blockIdx.y, r = blockIdx.z, e = threadIdx.x;
    if (e == 0 && h == 0 && r == 0) g_s0key[b] = fenc(-3e30f);
    const float* w = W + (size_t)((r * 2 + h) * E_) * E_ + e;
    const float* rb = rel + b * E_;
    float s = hb[(r * 2 + h) * E_ + e];
#pragma unroll 8
    for (int i = 0; i < E_; i++) s += rb[i] * w[(size_t)i * E_];
    g_h[r][h][b][e] = s;
}

// -- per-fact biases + fused scores_0 + fused fp16 fact conversion -----------
// 256 blocks x 8 warps; each warp loops 16 facts (2 per iter), constants hoisted
__global__ void k_cbias(const float* __restrict__ rel, const float* __restrict__ arg1,
                        const float* __restrict__ arg2, const float* __restrict__ fr,
                        const float* __restrict__ fa1, const float* __restrict__ fa2,
                        const int* __restrict__ nbf) {
    int tid = threadIdx.x, lane = tid & 31, hl = lane & 15, sub = lane >> 4;
    int wg = blockIdx.x * 8 + (tid >> 5);  // 0..2047
    int b = wg >> 7;
    int fbase = (wg & 127) * 16;
    const float4* Q;
#define LD2(dst0, dst1, base) Q = (const float4*)(base); float4 dst0 = Q[0], dst1 = Q[1];
    LD2(h00a, h00b, &g_h[0][0][b][hl * 8]);
    LD2(h10a, h10b, &g_h[1][0][b][hl * 8]);
    LD2(h01a, h01b, &g_h[0][1][b][hl * 8]);
    LD2(h11a, h11b, &g_h[1][1][b][hl * 8]);
    LD2(qra, qrb, rel + b * E_ + hl * 8);
    LD2(a1a, a1b, arg1 + b * E_ + hl * 8);
    LD2(a2a, a2b, arg2 + b * E_ + hl * 8);
#undef LD2
    // per-lane partial self-dots (constant across facts)
    float h00s = dot4(h00a, h00a) + dot4(h00b, h00b);
    float h10s = dot4(h10a, h10a) + dot4(h10b, h10b);
    float h01s = dot4(h01a, h01a) + dot4(h01b, h01b);
    float h11s = dot4(h11a, h11a) + dot4(h11b, h11b);
    float qrs = dot4(qra, qra) + dot4(qrb, qrb);
    float a1s = dot4(a1a, a1a) + dot4(a1b, a1b);
    float a2s = dot4(a2a, a2a) + dot4(a2b, a2b);
    int nb = nbf[b];

    for (int it = 0; it < 8; ++it) {
        int f = fbase + it * 2 + sub;
        size_t off = ((size_t)b * F_ + f) * E_ + hl * 8;
        const float4* PR = (const float4*)(fr + off);
        const float4* P1 = (const float4*)(fa1 + off);
        const float4* P2 = (const float4*)(fa2 + off);
        float4 vr0 = PR[0], vr1 = PR[1];
        float4 v10 = P1[0], v11 = P1[1];
        float4 v20 = P2[0], v21 = P2[1];
        uint4 c1 = {pack_half2(v10.x, v10.y), pack_half2(v10.z, v10.w),
                    pack_half2(v11.x, v11.y), pack_half2(v11.z, v11.w)};
        uint4 c2 = {pack_half2(v20.x, v20.y), pack_half2(v20.z, v20.w),
                    pack_half2(v21.x, v21.y), pack_half2(v21.z, v21.w)};
        *(uint4*)(g_f1hi + off) = c1;
        *(uint4*)(g_f2hi + off) = c2;
        float nsum = dot4(vr0, vr0) + dot4(vr1, vr1) + dot4(v10, v10) + dot4(v11, v11) +
                     dot4(v20, v20) + dot4(v21, v21);
        float a1v1 = dot4(a1a, v10) + dot4(a1b, v11);
        float a2v1 = dot4(a2a, v10) + dot4(a2b, v11);
        float a1v2 = dot4(a1a, v20) + dot4(a1b, v21);
        float a2v2 = dot4(a2a, v20) + dot4(a2b, v21);
        float p0 = nsum + h00s + a1s - 2.f * (dot4(h00a, vr0) + dot4(h00b, vr1) + a1v1);
        float p1 = nsum + h10s + a1s - 2.f * (dot4(h10a, vr0) + dot4(h10b, vr1) + a1v2);
        float q0 = nsum + h01s + a2s - 2.f * (dot4(h01a, vr0) + dot4(h01b, vr1) + a2v2);
        float q1 = nsum + h11s + a2s - 2.f * (dot4(h11a, vr0) + dot4(h11b, vr1) + a2v1);
        float s = nsum + qrs + a1s + a2s -
                  2.f * (dot4(qra, vr0) + dot4(qrb, vr1) + a1v1 + a2v2);
        p0 = hsum16(p0);
        p1 = hsum16(p1);
        q0 = hsum16(q0);
        q1 = hsum16(q1);
        s = hsum16(s);
        if (hl == 0) {
            bool valid = f < nb;
            g_cbias[0][b][f] = valid ? -0.5f * p0 : -3e30f;
            g_cbias[1][b][f] = valid ? -0.5f * p1 : -3e30f;
            g_cb2[0][b][f] = valid ? -0.5f * q0 : -3e30f;
            g_cb2[1][b][f] = valid ? -0.5f * q1 : -3e30f;
            if (valid) atomicMax(&g_s0key[b], fenc(-0.5f * s));
        }
    }
}

// ------- heavy max-plus GEMM via mma.sync (single-pass fp16) -----------------
// grid (nt=16, b=16, r*4+fq=8); 256 threads / 8 warps, CTA tile 128x128,
// warp grid 4m x 2n (warp tile 32x64); A + cbias + B all via cp.async
#define OFF_AHI 0
#define OFF_B0 32768
#define OFF_CB 98304
#define SMEM_MG 99328

__global__ __launch_bounds__(256, 2) void k_maxgemm(const int* __restrict__ nbe) {
    extern __shared__ char smem[];
    uint32_t sb = smem_u32(smem);
    const int tid = threadIdx.x, lane = tid & 31, wid = tid >> 5;
    const int wm = (wid & 3) * 32, wn = (wid >> 2) * 64;
    const int nt = blockIdx.x, b = blockIdx.y;
    const int r = blockIdx.z >> 2, fq = blockIdx.z & 3;

    const __half* ehi = g_ehi + ((size_t)b * N_ + nt * 128) * E_;
    const __half* fhi = ((r == 0) ? g_f2hi : g_f1hi) + (size_t)b * F_ * E_;
    const float* cb = &g_cbias[r][b][0];

    // resident entity tile (128 rows) via cp.async, swizzled
#pragma unroll
    for (int it = 0; it < 8; ++it) {
        int i = tid + it * 256;
        int row = i >> 4, ch = i & 15;
        cp16(sb + OFF_AHI + swz(row, ch), ehi + (size_t)row * E_ + ch * 8);
    }
    cpcommit();

    auto issueB = [&](int ft, int buf) {
        uint32_t base = sb + OFF_B0 + buf * 32768;
        const __half* sh = fhi + (size_t)ft * 128 * E_;
#pragma unroll
        for (int it = 0; it < 8; ++it) {
            int i = tid + it * 256;
            int row = i >> 4, ch = i & 15;
            cp16(base + swz(row, ch), sh + (size_t)row * E_ + ch * 8);
        }
        if (tid < 32) cp16(sb + OFF_CB + buf * 512 + tid * 16, cb + ft * 128 + tid * 4);
    };
    issueB(fq * 4, 0);
    cpcommit();

    float rmax[4];
#pragma unroll
    for (int i = 0; i < 4; i++) rmax[i] = -3e30f;

    for (int t = 0; t < 4; ++t) {
        int ft = fq * 4 + t;
        cpwait<0>();
        __syncthreads();  // buffer t&1 ready; all warps done with the other buffer
        if (t + 1 < 4) {
            issueB(ft + 1, (t + 1) & 1);
            cpcommit();
        }

        float acc[2][8][4];
#pragma unroll
        for (int i = 0; i < 2; i++)
#pragma unroll
            for (int j = 0; j < 8; j++)
#pragma unroll
                for (int q = 0; q < 4; q++) acc[i][j][q] = 0.f;

        uint32_t bbase = sb + OFF_B0 + (t & 1) * 32768;
#pragma unroll
        for (int ks = 0; ks < 8; ++ks) {
            int kc = ks * 2 + (lane >> 4);
            uint32_t ah[2][4];
#pragma unroll
            for (int i = 0; i < 2; i++) {
                int row = wm + i * 16 + (lane & 15);
                ldsm4(ah[i][0], ah[i][1], ah[i][2], ah[i][3], sb + OFF_AHI + swz(row, kc));
            }
            uint32_t bh[8][2];
#pragma unroll
            for (int p = 0; p < 4; p++) {
                int row = wn + p * 16 + (lane & 15);
                uint32_t r0, r1, r2, r3;
                ldsm4(r0, r1, r2, r3, bbase + swz(row, kc));
                bh[2 * p][0] = r0; bh[2 * p][1] = r2;
                bh[2 * p + 1][0] = r1; bh[2 * p + 1][1] = r3;
            }
#pragma unroll
            for (int i = 0; i < 2; i++)
#pragma unroll
                for (int j = 0; j < 8; j++) mma16816(acc[i][j], ah[i], bh[j]);
        }
        // epilogue: add cbias (smem broadcast), fold running row-max
        const float* cbs = (const float*)(smem + OFF_CB + (t & 1) * 512);
#pragma unroll
        for (int j = 0; j < 8; j++) {
            float2 cc = *(const float2*)(cbs + wn + j * 8 + 2 * (lane & 3));
#pragma unroll
            for (int i = 0; i < 2; i++) {
                rmax[2 * i] = fmaxf(rmax[2 * i],
                                    fmaxf(acc[i][j][0] + cc.x, acc[i][j][1] + cc.y));
                rmax[2 * i + 1] = fmaxf(rmax[2 * i + 1],
                                        fmaxf(acc[i][j][2] + cc.x, acc[i][j][3] + cc.y));
            }
        }
    }

    // cross-thread row-max reduction (reuse smem): 8 partials per row
    __syncthreads();
    float* Red = (float*)smem;
#pragma unroll
    for (int i = 0; i < 2; i++)
#pragma unroll
        for (int h = 0; h < 2; h++) {
            int row = wm + i * 16 + h * 8 + (lane >> 2);
            Red[row * 9 + (wid >> 2) * 4 + (lane & 3)] = rmax[2 * i + h];
        }
    __syncthreads();
    if (tid < 128) {
        float m = -3e30f;
#pragma unroll
        for (int t = 0; t < 8; t++) m = fmaxf(m, Red[tid * 9 + t]);
        int gn = nt * 128 + tid;
        float Lv = m - 0.5f * g_esq[b][gn];
        if (gn < nbe[b]) atomicMax(&g_Lkey[r][b][gn], fenc(Lv));
    }
}

// ---------------- top-K over N per (r,b): shuffle-based -----------------------
__global__ void k_topk() {
    int b = blockIdx.x, r = blockIdx.y, tid = threadIdx.x;
    int lane = tid & 31, wid = tid >> 5;
    float v[8];
#pragma unroll
    for (int j = 0; j < 8; j++) v[j] = fdec(g_Lkey[r][b][tid + 256 * j]);
    __shared__ float swv[8];
    __shared__ int swi[8];
    __shared__ int schosen;
    for (int kk = 0; kk < K_; kk++) {
        float bv = -3.4e38f;
        int bi = 0;
#pragma unroll
        for (int j = 0; j < 8; j++)
            if (v[j] > bv) { bv = v[j]; bi = tid + 256 * j; }
#pragma unroll
        for (int o = 16; o > 0; o >>= 1) {
            float ov = __shfl_xor_sync(0xffffffffu, bv, o);
            int oi = __shfl_xor_sync(0xffffffffu, bi, o);
            if (ov > bv || (ov == bv && oi < bi)) { bv = ov; bi = oi; }
        }
        if (lane == 0) { swv[wid] = bv; swi[wid] = bi; }
        __syncthreads();
        if (wid == 0) {
            float bv2 = (lane < 8) ? swv[lane] : -3.4e38f;
            int bi2 = (lane < 8) ? swi[lane] : 0;
#pragma unroll
            for (int o = 4; o > 0; o >>= 1) {
                float ov = __shfl_xor_sync(0xffffffffu, bv2, o);
                int oi = __shfl_xor_sync(0xffffffffu, bi2, o);
                if (ov > bv2 || (ov == bv2 && oi < bi2)) { bv2 = ov; bi2 = oi; }
            }
            if (lane == 0) {
                g_zidx[r][b][kk] = bi2;
                g_zlog[r][b][kk] = bv2;
                schosen = bi2;
            }
        }
        __syncthreads();
        int ch = schosen;
        if ((ch & 255) == tid) v[ch >> 8] = -3.4e38f;
        __syncthreads();
    }
}

// ------- hop-2 rescoring: max-plus over facts (fp16 fact planes, 8-way) ------
__global__ void k_s2(const float* __restrict__ ent) {
    int b = blockIdx.x, r = blockIdx.y, z = blockIdx.z, tid = threadIdx.x;
    int lane = tid & 31, wid = tid >> 5;
    __shared__ float zs[K_][E_];
    __shared__ float red[K_][257];
    for (int i = tid; i < K_ * E_; i += 256) {
        int k = i >> 7, e = i & 127;
        zs[k][e] = ent[((size_t)b * N_ + g_zidx[r][b][k]) * E_ + e];
    }
    __syncthreads();
    const __half* fy = ((r == 0) ? g_f1hi : g_f2hi) + (size_t)b * F_ * E_;
    int f = z * 256 + tid;
    float c = g_cb2[r][b][f];
    const uint4* row = (const uint4*)(fy + (size_t)f * E_);
    float d[K_];
#pragma unroll
    for (int k = 0; k < K_; k++) d[k] = 0.f;
#pragma unroll 2
    for (int e8 = 0; e8 < 16; e8++) {
        uint4 u = row[e8];
        float2 w0 = __half22float2(*(__half2*)&u.x);
        float2 w1 = __half22float2(*(__half2*)&u.y);
        float2 w2 = __half22float2(*(__half2*)&u.z);
        float2 w3 = __half22float2(*(__half2*)&u.w);
#pragma unroll
        for (int k = 0; k < K_; k++) {
            float4 z0 = ((const float4*)zs[k])[e8 * 2];
            float4 z1 = ((const float4*)zs[k])[e8 * 2 + 1];
            d[k] += w0.x * z0.x + w0.y * z0.y + w1.x * z0.z + w1.y * z0.w +
                    w2.x * z1.x + w2.y * z1.y + w3.x * z1.z + w3.y * z1.w;
        }
    }
#pragma unroll
    for (int k = 0; k < K_; k++) red[k][tid] = d[k] + c;
    __syncthreads();
    for (int k = wid; k < K_; k += 8) {
        float m = -3e30f;
        for (int j = lane; j < 256; j += 32) m = fmaxf(m, red[k][j]);
#pragma unroll
        for (int o = 16; o > 0; o >>= 1) m = fmaxf(m, __shfl_xor_sync(0xffffffffu, m, o));
        if (lane == 0) g_s2part[r][b][z][k] = m;
    }
}

// ---------------- final combine ----------------------------------------------
__global__ void k_final(float* __restrict__ out) {
    int b = threadIdx.x;
    if (b >= B_) return;
    float res = expf(fdec(g_s0key[b]));
#pragma unroll
    for (int r = 0; r < R_; r++)
#pragma unroll
        for (int k = 0; k < K_; k++) {
            float m = -3e30f;
            for (int z = 0; z < ZSPLIT; z++) m = fmaxf(m, g_s2part[r][b][z][k]);
            float s2 = m - 0.5f * g_esq[b][g_zidx[r][b][k]];
            res = fmaxf(res, expf(fminf(s2, g_zlog[r][b][k])));
        }
    out[b] = res;
}

// ---------------- launch -------------------------------------------------------
extern "C" void kernel_launch(void* const* d_in, const int* in_sizes, int n_in,
                              void* d_out, int out_size) {
    (void)in_sizes; (void)n_in; (void)out_size;
    const float* rel = (const float*)d_in[0];
    const float* arg1 = (const float*)d_in[1];
    const float* arg2 = (const float*)d_in[2];
    const float* fr = (const float*)d_in[3];
    const float* fa1 = (const float*)d_in[4];
    const float* fa2 = (const float*)d_in[5];
    const float* ent = (const float*)d_in[6];
    const float* W = (const float*)d_in[7];
    const float* hb = (const float*)d_in[8];
    const int* nbf = (const int*)d_in[9];
    const int* nbe = (const int*)d_in[10];
    float* out = (float*)d_out;

    cudaFuncSetAttribute(k_maxgemm, cudaFuncAttributeMaxDynamicSharedMemorySize, SMEM_MG);

    k_split<<<(B_ * N_ * E_) / 1024, 256>>>(ent);
    k_hop<<<dim3(B_, 2, R_), E_>>>(rel, W, hb);
    k_cbias<<<256, 256>>>(rel, arg1, arg2, fr, fa1, fa2, nbf);
    k_maxgemm<<<dim3(N_ / 128, B_, 4 * R_), 256, SMEM_MG>>>(nbe);
    k_topk<<<dim3(B_, R_), 256>>>();
    k_s2<<<dim3(B_, R_, ZSPLIT), 256>>>(ent);
    k_final<<<1, 32>>>(out);
}

// round 13
// speedup vs baseline: 6.5245x; 1.0390x over previous
#include <cuda_runtime.h>
#include <cuda_fp16.h>
#include <cstdint>

#define B_ 16
#define N_ 2048
#define F_ 2048
#define E_ 128
#define K_ 10
#define R_ 2
#define ZSPLIT 8

// ---------------- device scratch (static, no runtime allocation) ----------
__device__ float g_h[R_][2][B_][E_];        // hop vectors (h1,h2) per rule
__device__ float g_esq[B_][N_];             // entity squared norms
__device__ float g_cbias[R_][B_][F_];       // hop-1 fact bias
__device__ float g_cb2[R_][B_][F_];         // hop-2 fact bias
__device__ unsigned g_s0key[B_];            // scores_0 ordered-int atomic max
__device__ unsigned g_Lkey[R_][B_][N_];     // hop-1 log scores (ordered-uint)
__device__ int   g_zidx[R_][B_][K_];
__device__ float g_zlog[R_][B_][K_];
__device__ float g_s2part[R_][B_][ZSPLIT][K_];

// fp16 planes (round-to-nearest)
__device__ __half g_ehi[B_ * N_ * E_];
__device__ __half g_f1hi[B_ * F_ * E_];
__device__ __half g_f2hi[B_ * F_ * E_];

// ---------------- helpers ---------------------------------------------------
__device__ __forceinline__ float warp_sum(float v) {
#pragma unroll
    for (int o = 16; o > 0; o >>= 1) v += __shfl_xor_sync(0xffffffffu, v, o);
    return v;
}
__device__ __forceinline__ float hsum16(float v) {
#pragma unroll
    for (int o = 8; o > 0; o >>= 1) v += __shfl_xor_sync(0xffffffffu, v, o);
    return v;
}
__device__ __forceinline__ float dot4(float4 a, float4 b) {
    return a.x * b.x + a.y * b.y + a.z * b.z + a.w * b.w;
}
__device__ __forceinline__ unsigned fenc(float v) {
    unsigned u = __float_as_uint(v);
    return (u & 0x80000000u) ? ~u : (u | 0x80000000u);
}
__device__ __forceinline__ float fdec(unsigned k) {
    return (k & 0x80000000u) ? __uint_as_float(k ^ 0x80000000u) : __uint_as_float(~k);
}
__device__ __forceinline__ uint32_t smem_u32(const void* p) {
    uint32_t a;
    asm("{ .reg .u64 t; cvta.to.shared.u64 t, %1; cvt.u32.u64 %0, t; }" : "=r"(a) : "l"(p));
    return a;
}
__device__ __forceinline__ unsigned pack_half2(float a, float b) {
    __half2 h = __halves2half2(__float2half_rn(a), __float2half_rn(b));
    return *(unsigned*)&h;
}

// ---------------- portable tensor-core / async-copy PTX ----------------------
__device__ __forceinline__ void cp16(uint32_t s, const void* g) {
    asm volatile("cp.async.cg.shared.global [%0], [%1], 16;" :: "r"(s), "l"(g));
}
__device__ __forceinline__ void cpcommit() { asm volatile("cp.async.commit_group;"); }
template <int NN>
__device__ __forceinline__ void cpwait() {
    asm volatile("cp.async.wait_group %0;" :: "n"(NN));
}
__device__ __forceinline__ void ldsm4(uint32_t& r0, uint32_t& r1, uint32_t& r2, uint32_t& r3,
                                      uint32_t a) {
    asm volatile("ldmatrix.sync.aligned.m8n8.x4.shared.b16 {%0,%1,%2,%3}, [%4];"
                 : "=r"(r0), "=r"(r1), "=r"(r2), "=r"(r3) : "r"(a));
}
__device__ __forceinline__ void mma16816(float* c, const uint32_t* a, const uint32_t* b) {
    asm volatile(
        "mma.sync.aligned.m16n8k16.row.col.f32.f16.f16.f32 "
        "{%0,%1,%2,%3},{%4,%5,%6,%7},{%8,%9},{%0,%1,%2,%3};"
        : "+f"(c[0]), "+f"(c[1]), "+f"(c[2]), "+f"(c[3])
        : "r"(a[0]), "r"(a[1]), "r"(a[2]), "r"(a[3]), "r"(b[0]), "r"(b[1]));
}
// swizzled tile offset: rows x 128 fp16 (256B rows, 16-byte chunks, XOR swizzle)
__device__ __forceinline__ uint32_t swz(int row, int chunk) {
    return (uint32_t)row * 256u + (uint32_t)((chunk ^ (row & 7)) * 16);
}

// ------ merged prep: entity fp16 + norms + Lkey init, and hop vectors --------
__global__ void k_prep(const float* __restrict__ ent, const float* __restrict__ rel,
                       const float* __restrict__ W, const float* __restrict__ hb) {
    int tid = threadIdx.x;
    if (blockIdx.x < 4096) {
        size_t i = ((size_t)blockIdx.x * 256 + tid) * 4;
        float4 v = *(const float4*)(ent + i);
        uint2 uh = {pack_half2(v.x, v.y), pack_half2(v.z, v.w)};
        *(uint2*)(g_ehi + i) = uh;
        float s = warp_sum(dot4(v, v));
        if ((tid & 31) == 0) {
            int gw = blockIdx.x * 8 + (tid >> 5);
            ((float*)g_esq)[gw] = s;
            unsigned init = fenc(-3e30f);
            int b = gw >> 11, n = gw & (N_ - 1);
            g_Lkey[0][b][n] = init;
            g_Lkey[1][b][n] = init;
        }
    } else {
        int idx = blockIdx.x - 4096;  // 0..63
        int b = idx & 15, h = (idx >> 4) & 1, r = idx >> 5;
        if (tid >= E_) return;
        int e = tid;
        if (e == 0 && h == 0 && r == 0) g_s0key[b] = fenc(-3e30f);
        const float* w = W + (size_t)((r * 2 + h) * E_) * E_ + e;
        const float* rb = rel + b * E_;
        float s = hb[(r * 2 + h) * E_ + e];
#pragma unroll 8
        for (int i = 0; i < E_; i++) s += rb[i] * w[(size_t)i * E_];
        g_h[r][h][b][e] = s;
    }
}

// -- per-fact biases + fused scores_0 + fused fp16 fact conversion -----------
__global__ void k_cbias(const float* __restrict__ rel, const float* __restrict__ arg1,
                        const float* __restrict__ arg2, const float* __restrict__ fr,
                        const float* __restrict__ fa1, const float* __restrict__ fa2,
                        const int* __restrict__ nbf) {
    int tid = threadIdx.x, lane = tid & 31, hl = lane & 15, sub = lane >> 4;
    int wg = blockIdx.x * 8 + (tid >> 5);  // 0..2047
    int b = wg >> 7;
    int fbase = (wg & 127) * 16;
    const float4* Q;
#define LD2(dst0, dst1, base) Q = (const float4*)(base); float4 dst0 = Q[0], dst1 = Q[1];
    LD2(h00a, h00b, &g_h[0][0][b][hl * 8]);
    LD2(h10a, h10b, &g_h[1][0][b][hl * 8]);
    LD2(h01a, h01b, &g_h[0][1][b][hl * 8]);
    LD2(h11a, h11b, &g_h[1][1][b][hl * 8]);
    LD2(qra, qrb, rel + b * E_ + hl * 8);
    LD2(a1a, a1b, arg1 + b * E_ + hl * 8);
    LD2(a2a, a2b, arg2 + b * E_ + hl * 8);
#undef LD2
    float h00s = dot4(h00a, h00a) + dot4(h00b, h00b);
    float h10s = dot4(h10a, h10a) + dot4(h10b, h10b);
    float h01s = dot4(h01a, h01a) + dot4(h01b, h01b);
    float h11s = dot4(h11a, h11a) + dot4(h11b, h11b);
    float qrs = dot4(qra, qra) + dot4(qrb, qrb);
    float a1s = dot4(a1a, a1a) + dot4(a1b, a1b);
    float a2s = dot4(a2a, a2a) + dot4(a2b, a2b);
    int nb = nbf[b];

    for (int it = 0; it < 8; ++it) {
        int f = fbase + it * 2 + sub;
        size_t off = ((size_t)b * F_ + f) * E_ + hl * 8;
        const float4* PR = (const float4*)(fr + off);
        const float4* P1 = (const float4*)(fa1 + off);
        const float4* P2 = (const float4*)(fa2 + off);
        float4 vr0 = PR[0], vr1 = PR[1];
        float4 v10 = P1[0], v11 = P1[1];
        float4 v20 = P2[0], v21 = P2[1];
        uint4 c1 = {pack_half2(v10.x, v10.y), pack_half2(v10.z, v10.w),
                    pack_half2(v11.x, v11.y), pack_half2(v11.z, v11.w)};
        uint4 c2 = {pack_half2(v20.x, v20.y), pack_half2(v20.z, v20.w),
                    pack_half2(v21.x, v21.y), pack_half2(v21.z, v21.w)};
        *(uint4*)(g_f1hi + off) = c1;
        *(uint4*)(g_f2hi + off) = c2;
        float nsum = dot4(vr0, vr0) + dot4(vr1, vr1) + dot4(v10, v10) + dot4(v11, v11) +
                     dot4(v20, v20) + dot4(v21, v21);
        float a1v1 = dot4(a1a, v10) + dot4(a1b, v11);
        float a2v1 = dot4(a2a, v10) + dot4(a2b, v11);
        float a1v2 = dot4(a1a, v20) + dot4(a1b, v21);
        float a2v2 = dot4(a2a, v20) + dot4(a2b, v21);
        float p0 = nsum + h00s + a1s - 2.f * (dot4(h00a, vr0) + dot4(h00b, vr1) + a1v1);
        float p1 = nsum + h10s + a1s - 2.f * (dot4(h10a, vr0) + dot4(h10b, vr1) + a1v2);
        float q0 = nsum + h01s + a2s - 2.f * (dot4(h01a, vr0) + dot4(h01b, vr1) + a2v2);
        float q1 = nsum + h11s + a2s - 2.f * (dot4(h11a, vr0) + dot4(h11b, vr1) + a2v1);
        float s = nsum + qrs + a1s + a2s -
                  2.f * (dot4(qra, vr0) + dot4(qrb, vr1) + a1v1 + a2v2);
        p0 = hsum16(p0);
        p1 = hsum16(p1);
        q0 = hsum16(q0);
        q1 = hsum16(q1);
        s = hsum16(s);
        if (hl == 0) {
            bool valid = f < nb;
            g_cbias[0][b][f] = valid ? -0.5f * p0 : -3e30f;
            g_cbias[1][b][f] = valid ? -0.5f * p1 : -3e30f;
            g_cb2[0][b][f] = valid ? -0.5f * q0 : -3e30f;
            g_cb2[1][b][f] = valid ? -0.5f * q1 : -3e30f;
            if (valid) atomicMax(&g_s0key[b], fenc(-0.5f * s));
        }
    }
}

// ------- heavy max-plus GEMM via mma.sync (single-pass fp16) -----------------
// grid (nt=16, b=16, r*4+fq=8); 256 threads / 8 warps, CTA tile 128x128,
// warp grid 4m x 2n (warp tile 32x64); A + cbias + B all via cp.async
#define OFF_AHI 0
#define OFF_B0 32768
#define OFF_CB 98304
#define SMEM_MG 99328

__global__ __launch_bounds__(256, 2) void k_maxgemm(const int* __restrict__ nbe) {
    extern __shared__ char smem[];
    uint32_t sb = smem_u32(smem);
    const int tid = threadIdx.x, lane = tid & 31, wid = tid >> 5;
    const int wm = (wid & 3) * 32, wn = (wid >> 2) * 64;
    const int nt = blockIdx.x, b = blockIdx.y;
    const int r = blockIdx.z >> 2, fq = blockIdx.z & 3;

    const __half* ehi = g_ehi + ((size_t)b * N_ + nt * 128) * E_;
    const __half* fhi = ((r == 0) ? g_f2hi : g_f1hi) + (size_t)b * F_ * E_;
    const float* cb = &g_cbias[r][b][0];

    // hoisted ldsm row bases + swizzle keys (invariant across k-steps/tiles)
    uint32_t aBase[2], bOff[4];
    int aX[2], bX[4];
#pragma unroll
    for (int i = 0; i < 2; i++) {
        int row = wm + i * 16 + (lane & 15);
        aBase[i] = sb + OFF_AHI + (uint32_t)row * 256u;
        aX[i] = row & 7;
    }
#pragma unroll
    for (int p = 0; p < 4; p++) {
        int row = wn + p * 16 + (lane & 15);
        bOff[p] = (uint32_t)row * 256u;
        bX[p] = row & 7;
    }

    // resident entity tile (128 rows) via cp.async, swizzled
#pragma unroll
    for (int it = 0; it < 8; ++it) {
        int i = tid + it * 256;
        int row = i >> 4, ch = i & 15;
        cp16(sb + OFF_AHI + swz(row, ch), ehi + (size_t)row * E_ + ch * 8);
    }
    cpcommit();

    auto issueB = [&](int ft, int buf) {
        uint32_t base = sb + OFF_B0 + buf * 32768;
        const __half* sh = fhi + (size_t)ft * 128 * E_;
#pragma unroll
        for (int it = 0; it < 8; ++it) {
            int i = tid + it * 256;
            int row = i >> 4, ch = i & 15;
            cp16(base + swz(row, ch), sh + (size_t)row * E_ + ch * 8);
        }
        if (tid < 32) cp16(sb + OFF_CB + buf * 512 + tid * 16, cb + ft * 128 + tid * 4);
    };
    issueB(fq * 4, 0);
    cpcommit();

    float rmax[4];
#pragma unroll
    for (int i = 0; i < 4; i++) rmax[i] = -3e30f;

    for (int t = 0; t < 4; ++t) {
        int ft = fq * 4 + t;
        cpwait<0>();
        __syncthreads();  // buffer t&1 ready; all warps done with the other buffer
        if (t + 1 < 4) {
            issueB(ft + 1, (t + 1) & 1);
            cpcommit();
        }

        float acc[2][8][4];
#pragma unroll
        for (int i = 0; i < 2; i++)
#pragma unroll
            for (int j = 0; j < 8; j++)
#pragma unroll
                for (int q = 0; q < 4; q++) acc[i][j][q] = 0.f;

        uint32_t bbase = sb + OFF_B0 + (t & 1) * 32768;
#pragma unroll
        for (int ks = 0; ks < 8; ++ks) {
            int kc = ks * 2 + (lane >> 4);
            uint32_t ah[2][4];
#pragma unroll
            for (int i = 0; i < 2; i++)
                ldsm4(ah[i][0], ah[i][1], ah[i][2], ah[i][3],
                      aBase[i] + (uint32_t)((kc ^ aX[i]) << 4));
            uint32_t bh[8][2];
#pragma unroll
            for (int p = 0; p < 4; p++) {
                uint32_t r0, r1, r2, r3;
                ldsm4(r0, r1, r2, r3, bbase + bOff[p] + (uint32_t)((kc ^ bX[p]) << 4));
                bh[2 * p][0] = r0; bh[2 * p][1] = r2;
                bh[2 * p + 1][0] = r1; bh[2 * p + 1][1] = r3;
            }
#pragma unroll
            for (int i = 0; i < 2; i++)
#pragma unroll
                for (int j = 0; j < 8; j++) mma16816(acc[i][j], ah[i], bh[j]);
        }
        // epilogue: add cbias (smem broadcast), fold running row-max
        const float* cbs = (const float*)(smem + OFF_CB + (t & 1) * 512);
#pragma unroll
        for (int j = 0; j < 8; j++) {
            float2 cc = *(const float2*)(cbs + wn + j * 8 + 2 * (lane & 3));
#pragma unroll
            for (int i = 0; i < 2; i++) {
                rmax[2 * i] = fmaxf(rmax[2 * i],
                                    fmaxf(acc[i][j][0] + cc.x, acc[i][j][1] + cc.y));
                rmax[2 * i + 1] = fmaxf(rmax[2 * i + 1],
                                        fmaxf(acc[i][j][2] + cc.x, acc[i][j][3] + cc.y));
            }
        }
    }

    // cross-thread row-max reduction (reuse smem): 8 partials per row
    __syncthreads();
    float* Red = (float*)smem;
#pragma unroll
    for (int i = 0; i < 2; i++)
#pragma unroll
        for (int h = 0; h < 2; h++) {
            int row = wm + i * 16 + h * 8 + (lane >> 2);
            Red[row * 9 + (wid >> 2) * 4 + (lane & 3)] = rmax[2 * i + h];
        }
    __syncthreads();
    if (tid < 128) {
        float m = -3e30f;
#pragma unroll
        for (int t = 0; t < 8; t++) m = fmaxf(m, Red[tid * 9 + t]);
        int gn = nt * 128 + tid;
        float Lv = m - 0.5f * g_esq[b][gn];
        if (gn < nbe[b]) atomicMax(&g_Lkey[r][b][gn], fenc(Lv));
    }
}

// ---- beam: per-(b,r,z) block — redundant top-K, then hop-2 partial max ------
__global__ void k_beam(const float* __restrict__ ent) {
    int b = blockIdx.x, r = blockIdx.y, z = blockIdx.z, tid = threadIdx.x;
    int lane = tid & 31, wid = tid >> 5;
    // 16B-aligned vector-accessed arrays FIRST (float4 casts require it)
    __shared__ __align__(16) float zs[K_][E_];
    __shared__ __align__(16) float red[K_][257];
    __shared__ float swv[8];
    __shared__ int swi[8];
    __shared__ int schosen;
    __shared__ float szlog[K_];
    __shared__ int szidx[K_];

    // ---- phase 1: top-K over N (identical in every z-block) ----
    float v[8];
#pragma unroll
    for (int j = 0; j < 8; j++) v[j] = fdec(g_Lkey[r][b][tid + 256 * j]);
    for (int kk = 0; kk < K_; kk++) {
        float bv = -3.4e38f;
        int bi = 0;
#pragma unroll
        for (int j = 0; j < 8; j++)
            if (v[j] > bv) { bv = v[j]; bi = tid + 256 * j; }
#pragma unroll
        for (int o = 16; o > 0; o >>= 1) {
            float ov = __shfl_xor_sync(0xffffffffu, bv, o);
            int oi = __shfl_xor_sync(0xffffffffu, bi, o);
            if (ov > bv || (ov == bv && oi < bi)) { bv = ov; bi = oi; }
        }
        if (lane == 0) { swv[wid] = bv; swi[wid] = bi; }
        __syncthreads();
        if (wid == 0) {
            float bv2 = (lane < 8) ? swv[lane] : -3.4e38f;
            int bi2 = (lane < 8) ? swi[lane] : 0;
#pragma unroll
            for (int o = 4; o > 0; o >>= 1) {
                float ov = __shfl_xor_sync(0xffffffffu, bv2, o);
                int oi = __shfl_xor_sync(0xffffffffu, bi2, o);
                if (ov > bv2 || (ov == bv2 && oi < bi2)) { bv2 = ov; bi2 = oi; }
            }
            if (lane == 0) {
                szlog[kk] = bv2;
                szidx[kk] = bi2;
                schosen = bi2;
            }
        }
        __syncthreads();
        int ch = schosen;
        if ((ch & 255) == tid) v[ch >> 8] = -3.4e38f;
        __syncthreads();
    }
    if (z == 0 && tid < K_) {  // publish once for k_final
        g_zidx[r][b][tid] = szidx[tid];
        g_zlog[r][b][tid] = szlog[tid];
    }

    // ---- phase 2: hop-2 partial max over this z-slice of facts ----
    for (int i = tid; i < K_ * E_; i += 256) {
        int k = i >> 7, e = i & 127;
        zs[k][e] = ent[((size_t)b * N_ + szidx[k]) * E_ + e];
    }
    __syncthreads();
    const __half* fy = ((r == 0) ? g_f1hi : g_f2hi) + (size_t)b * F_ * E_;
    int f = z * 256 + tid;
    float c = g_cb2[r][b][f];
    const uint4* row = (const uint4*)(fy + (size_t)f * E_);
    float d[K_];
#pragma unroll
    for (int k = 0; k < K_; k++) d[k] = 0.f;
#pragma unroll 2
    for (int e8 = 0; e8 < 16; e8++) {
        uint4 u = row[e8];
        float2 w0 = __half22float2(*(__half2*)&u.x);
        float2 w1 = __half22float2(*(__half2*)&u.y);
        float2 w2 = __half22float2(*(__half2*)&u.z);
        float2 w3 = __half22float2(*(__half2*)&u.w);
#pragma unroll
        for (int k = 0; k < K_; k++) {
            float4 z0 = ((const float4*)zs[k])[e8 * 2];
            float4 z1 = ((const float4*)zs[k])[e8 * 2 + 1];
            d[k] += w0.x * z0.x + w0.y * z0.y + w1.x * z0.z + w1.y * z0.w +
                    w2.x * z1.x + w2.y * z1.y + w3.x * z1.z + w3.y * z1.w;
        }
    }
#pragma unroll
    for (int k = 0; k < K_; k++) red[k][tid] = d[k] + c;
    __syncthreads();
    for (int k = wid; k < K_; k += 8) {
        float m = -3e30f;
        for (int j = lane; j < 256; j += 32) m = fmaxf(m, red[k][j]);
#pragma unroll
        for (int o = 16; o > 0; o >>= 1) m = fmaxf(m, __shfl_xor_sync(0xffffffffu, m, o));
        if (lane == 0) g_s2part[r][b][z][k] = m;
    }
}

// ---------------- final combine ----------------------------------------------
__global__ void k_final(float* __restrict__ out) {
    int b = threadIdx.x;
    if (b >= B_) return;
    float res = expf(fdec(g_s0key[b]));
#pragma unroll
    for (int r = 0; r < R_; r++)
#pragma unroll
        for (int k = 0; k < K_; k++) {
            float m = -3e30f;
            for (int z = 0; z < ZSPLIT; z++) m = fmaxf(m, g_s2part[r][b][z][k]);
            float s2 = m - 0.5f * g_esq[b][g_zidx[r][b][k]];
            res = fmaxf(res, expf(fminf(s2, g_zlog[r][b][k])));
        }
    out[b] = res;
}

// ---------------- launch -------------------------------------------------------
extern "C" void kernel_launch(void* const* d_in, const int* in_sizes, int n_in,
                              void* d_out, int out_size) {
    (void)in_sizes; (void)n_in; (void)out_size;
    const float* rel = (const float*)d_in[0];
    const float* arg1 = (const float*)d_in[1];
    const float* arg2 = (const float*)d_in[2];
    const float* fr = (const float*)d_in[3];
    const float* fa1 = (const float*)d_in[4];
    const float* fa2 = (const float*)d_in[5];
    const float* ent = (const float*)d_in[6];
    const float* W = (const float*)d_in[7];
    const float* hb = (const float*)d_in[8];
    const int* nbf = (const int*)d_in[9];
    const int* nbe = (const int*)d_in[10];
    float* out = (float*)d_out;

    cudaFuncSetAttribute(k_maxgemm, cudaFuncAttributeMaxDynamicSharedMemorySize, SMEM_MG);

    k_prep<<<4160, 256>>>(ent, rel, W, hb);
    k_cbias<<<256, 256>>>(rel, arg1, arg2, fr, fa1, fa2, nbf);
    k_maxgemm<<<dim3(N_ / 128, B_, 4 * R_), 256, SMEM_MG>>>(nbe);
    k_beam<<<dim3(B_, R_, ZSPLIT), 256>>>(ent);
    k_final<<<1, 32>>>(out);
}